// round 5
// baseline (speedup 1.0000x reference)
#include <cuda_runtime.h>
#include <math.h>

#define BB 2
#define CC 64
#define LL 32768      // 32*32*32 spatial = token count
#define DI 64
#define DS 8
#define CS 256        // scan chunk length
#define NCK 128       // number of chunks = LL/CS

// ---------------- scratch (static device globals; no allocation) -------------
__device__ float g_tmp1[BB*CC*LL];     // conv1 output
__device__ float g_mr[BB*CC*2];        // per (b,c) mean / rstd
__device__ float g_xz[(size_t)BB*LL*128]; // in_proj output, [b][l][128]
__device__ float g_xc[(size_t)BB*LL*DI];  // per-direction (reused)
__device__ float g_dt[(size_t)BB*LL*DI];
__device__ float g_Bm[(size_t)BB*LL*DS];
__device__ float g_Cm[(size_t)BB*LL*DS];
__device__ float g_P[BB*NCK*DI*DS];
__device__ float g_Q[BB*NCK*DI*DS];
__device__ float g_cin[BB*NCK*DI*DS];
__device__ float g_y[(size_t)BB*LL*DI];   // y_f*silu(z) + y_b*silu(z) at original l
__device__ float g_vol2[BB*CC*LL];        // LN output in volume layout (input of conv2)

// ---------------- conv3d (3x3x3, pad 1, 64->64) ------------------------------
// block = (b,h,w); 8 warps; warp w handles co = 8w..8w+7; lane = depth d.
// FIRST: reads `in` (harness input), writes g_tmp1.
// !FIRST: reads g_vol2 (device global, accessed FROM DEVICE CODE — passing a
//         __device__ array as a host-side kernel arg yields the host shadow
//         address and garbage reads; that was the round-3 bug), writes
//         outp = conv2 + relu(instance_norm(g_tmp1)).
template<bool FIRST>
__global__ __launch_bounds__(256) void conv3d_k(
    const float* __restrict__ in, const float* __restrict__ cw,
    const float* __restrict__ cb, float* __restrict__ outp)
{
    __shared__ float s_in[9][34];
    __shared__ float s_w[64][28];   // row padded to 28 floats (16B aligned)
    int bid = blockIdx.x;
    int b = bid >> 10;
    int hw = bid & 1023;
    int h = hw >> 5, w = hw & 31;
    int tid = threadIdx.x;
    int lane = tid & 31;
    int wid = tid >> 5;

    const float* src = FIRST ? in : (const float*)g_vol2;

    float acc[8];
#pragma unroll
    for (int i = 0; i < 8; i++) acc[i] = 0.f;

    for (int ci = 0; ci < 64; ci++) {
        for (int idx = tid; idx < 9*34; idx += 256) {
            int r = idx / 34, j = idx % 34;
            int ih = h + r/3 - 1, iw = w + (r%3) - 1;
            int id = j - 1;
            float v = 0.f;
            if ((unsigned)ih < 32u && (unsigned)iw < 32u && (unsigned)id < 32u)
                v = src[(((b*64 + ci)*32 + ih)*32 + iw)*32 + id];
            s_in[r][j] = v;
        }
        for (int idx = tid; idx < 64*27; idx += 256) {
            int co = idx / 27, k = idx % 27;
            s_w[co][k] = cw[(co*64 + ci)*27 + k];
        }
        __syncthreads();

        float a[27];
#pragma unroll
        for (int r = 0; r < 9; r++)
#pragma unroll
            for (int kd = 0; kd < 3; kd++)
                a[r*3 + kd] = s_in[r][lane + kd];

#pragma unroll
        for (int i = 0; i < 8; i++) {
            const float* wp = s_w[wid*8 + i];
            float s = 0.f;
#pragma unroll
            for (int k = 0; k < 27; k++) s += a[k] * wp[k];
            acc[i] += s;
        }
        __syncthreads();
    }

#pragma unroll
    for (int i = 0; i < 8; i++) {
        int co = wid*8 + i;
        float v = acc[i] + cb[co];
        int idx = (b*64 + co)*LL + h*1024 + w*32 + lane;
        if (FIRST) {
            g_tmp1[idx] = v;
        } else {
            float mean = g_mr[(b*64 + co)*2];
            float rstd = g_mr[(b*64 + co)*2 + 1];
            float sk = (g_tmp1[idx] - mean) * rstd;
            sk = sk > 0.f ? sk : 0.f;
            outp[idx] = v + sk;
        }
    }
}

// ---------------- instance-norm stats (deterministic) ------------------------
__global__ __launch_bounds__(256) void stats_k()
{
    int bc = blockIdx.x;  // 0..127
    const float* p = g_tmp1 + (size_t)bc * LL;
    float s = 0.f, sq = 0.f;
    for (int i = threadIdx.x; i < LL; i += 256) { float v = p[i]; s += v; sq += v*v; }
    __shared__ float sh0[256], sh1[256];
    sh0[threadIdx.x] = s; sh1[threadIdx.x] = sq;
    __syncthreads();
    for (int o = 128; o > 0; o >>= 1) {
        if (threadIdx.x < o) { sh0[threadIdx.x] += sh0[threadIdx.x+o]; sh1[threadIdx.x] += sh1[threadIdx.x+o]; }
        __syncthreads();
    }
    if (threadIdx.x == 0) {
        float mean = sh0[0] * (1.f/LL);
        float var  = sh1[0] * (1.f/LL) - mean*mean;
        g_mr[bc*2]   = mean;
        g_mr[bc*2+1] = rsqrtf(var + 1e-5f);
    }
}

// ---------------- in_proj: xz[b][l][j] = sum_c in[b][c][l] * W[j][c] ----------
__global__ __launch_bounds__(256) void inproj_k(const float* __restrict__ in,
                                                const float* __restrict__ ipw)
{
    __shared__ float s_w[128][66];
    __shared__ float s_x[32][64];
    int b = blockIdx.y;
    int l0 = blockIdx.x * 64;
    int tid = threadIdx.x;
    for (int idx = tid; idx < 128*64; idx += 256) s_w[idx >> 6][idx & 63] = ipw[idx];

    int lq = tid & 15;
    int jq = tid >> 4;
    float acc[4][8];
#pragma unroll
    for (int i = 0; i < 4; i++)
#pragma unroll
        for (int j = 0; j < 8; j++) acc[i][j] = 0.f;

    for (int ch = 0; ch < 2; ch++) {
        __syncthreads();
        for (int idx = tid; idx < 32*64; idx += 256) {
            int c = idx >> 6, ll = idx & 63;
            s_x[c][ll] = in[(size_t)(b*64 + ch*32 + c)*LL + l0 + ll];
        }
        __syncthreads();
        for (int c = 0; c < 32; c++) {
            float xv[4], wv[8];
#pragma unroll
            for (int i = 0; i < 4; i++) xv[i] = s_x[c][lq*4 + i];
#pragma unroll
            for (int j = 0; j < 8; j++) wv[j] = s_w[jq*8 + j][ch*32 + c];
#pragma unroll
            for (int i = 0; i < 4; i++)
#pragma unroll
                for (int j = 0; j < 8; j++) acc[i][j] += xv[i] * wv[j];
        }
    }
#pragma unroll
    for (int i = 0; i < 4; i++) {
        int l = l0 + lq*4 + i;
        float4 v0 = make_float4(acc[i][0], acc[i][1], acc[i][2], acc[i][3]);
        float4 v1 = make_float4(acc[i][4], acc[i][5], acc[i][6], acc[i][7]);
        float4* dst = (float4*)&g_xz[((size_t)b*LL + l)*128 + jq*8];
        dst[0] = v0; dst[1] = v1;
    }
}

// ---------------- per-direction prep: conv1d+silu, x_proj, dt_proj -----------
template<int DIR>
__global__ __launch_bounds__(256) void prep_k(
    const float* __restrict__ w1d_g, const float* __restrict__ b1d_g,
    const float* __restrict__ xpw_g, const float* __restrict__ dtw_g,
    const float* __restrict__ dtb_g)
{
    __shared__ float xs[67][64];
    __shared__ float xc_s[64][65];
    __shared__ float dbl_s[64][20];
    __shared__ float xpw[20][65];
    __shared__ float w1d[64][4];
    __shared__ float dtw[64][5];
    __shared__ float b1d[64], dtb[64];

    int b = blockIdx.y;
    int s0 = blockIdx.x * 64;
    int tid = threadIdx.x;

    for (int idx = tid; idx < 20*64; idx += 256) xpw[idx/64][idx%64] = xpw_g[idx];
    if (tid < 64) {
#pragma unroll
        for (int k = 0; k < 4; k++) { w1d[tid][k] = w1d_g[tid*4 + k]; dtw[tid][k] = dtw_g[tid*4 + k]; }
        b1d[tid] = b1d_g[tid];
        dtb[tid] = dtb_g[tid];
    }
    for (int idx = tid; idx < 67*64; idx += 256) {
        int sr = idx / 64, d = idx % 64;
        int s = s0 + sr - 3;
        float v = 0.f;
        if (s >= 0) {
            int l = (DIR == 0) ? s : (LL - 1 - s);
            v = g_xz[((size_t)b*LL + l)*128 + d];
        }
        xs[sr][d] = v;
    }
    __syncthreads();

    // causal depthwise conv1d (k=4) + silu
    for (int idx = tid; idx < 64*64; idx += 256) {
        int sl = idx >> 6, d = idx & 63;
        float v = b1d[d];
#pragma unroll
        for (int k = 0; k < 4; k++) v += w1d[d][k] * xs[sl + k][d];
        v = v / (1.f + __expf(-v));
        xc_s[sl][d] = v;
        g_xc[((size_t)b*LL + s0 + sl)*64 + d] = v;
    }
    __syncthreads();

    // dbl = xc @ x_proj_w.T  (20 outputs)
    for (int idx = tid; idx < 64*20; idx += 256) {
        int sl = idx / 20, j = idx % 20;
        float v = 0.f;
        for (int d = 0; d < 64; d++) v += xc_s[sl][d] * xpw[j][d];
        dbl_s[sl][j] = v;
        int s = s0 + sl;
        if (j >= 4 && j < 12)      g_Bm[((size_t)b*LL + s)*8 + (j-4)]  = v;
        else if (j >= 12)          g_Cm[((size_t)b*LL + s)*8 + (j-12)] = v;
    }
    __syncthreads();

    // dt = softplus(dt_r @ dt_proj_w.T + b)
    for (int idx = tid; idx < 64*64; idx += 256) {
        int sl = idx >> 6, dd = idx & 63;
        float t = dtb[dd];
#pragma unroll
        for (int r = 0; r < 4; r++) t += dbl_s[sl][r] * dtw[dd][r];
        float sp = (t > 20.f) ? t : log1pf(__expf(t));
        g_dt[((size_t)b*LL + s0 + sl)*64 + dd] = sp;
    }
}

// ---------------- scan pass A: per-chunk (P, Q) reduction --------------------
__global__ __launch_bounds__(512) void scanA_k(const float* __restrict__ alog)
{
    __shared__ float s_dt[32][64];
    __shared__ float s_xc[32][64];
    __shared__ float s_B[32][8];
    int b = blockIdx.y;
    int chunk = blockIdx.x;
    int tid = threadIdx.x;
    int d = tid >> 3, n = tid & 7;
    float a = -__expf(alog[d*8 + n]);
    float P = 1.f, Q = 0.f;
    int sbase = chunk * CS;
    for (int sub = 0; sub < CS/32; sub++) {
        __syncthreads();
        int st = sbase + sub*32;
        for (int idx = tid; idx < 32*64; idx += 512) {
            int sl = idx >> 6, dd = idx & 63;
            size_t g = ((size_t)b*LL + st + sl)*64 + dd;
            s_dt[sl][dd] = g_dt[g];
            s_xc[sl][dd] = g_xc[g];
        }
        if (tid < 256) {
            int sl = tid >> 3, nn = tid & 7;
            s_B[sl][nn] = g_Bm[((size_t)b*LL + st + sl)*8 + nn];
        }
        __syncthreads();
#pragma unroll 8
        for (int sl = 0; sl < 32; sl++) {
            float dtv = s_dt[sl][d];
            float ex = __expf(dtv * a);
            float u = dtv * s_xc[sl][d] * s_B[sl][n];
            P *= ex;
            Q = ex*Q + u;
        }
    }
    size_t o = (((size_t)b*NCK + chunk)*64 + d)*8 + n;
    g_P[o] = P; g_Q[o] = Q;
}

// ---------------- scan pass B: sequential carry across chunks ----------------
__global__ __launch_bounds__(512) void scanB_k()
{
    int idx = blockIdx.x*512 + threadIdx.x;  // 0..1023 = (b, d, n)
    int b = idx >> 9;
    int dn = idx & 511;
    float h = 0.f;
    for (int j = 0; j < NCK; j++) {
        size_t o = ((size_t)(b*NCK + j))*512 + dn;
        g_cin[o] = h;
        h = g_P[o]*h + g_Q[o];
    }
}

// ---------------- scan pass C: replay with carry, y epilogue -----------------
template<int DIR>
__global__ __launch_bounds__(512) void scanC_k(const float* __restrict__ alog,
                                               const float* __restrict__ Dsk)
{
    __shared__ float s_dt[32][64];
    __shared__ float s_xc[32][64];
    __shared__ float s_B[32][8];
    __shared__ float s_C[32][8];
    __shared__ float s_y[32][64];
    int b = blockIdx.y;
    int chunk = blockIdx.x;
    int tid = threadIdx.x;
    int d = tid >> 3, n = tid & 7;
    float a = -__expf(alog[d*8 + n]);
    float Dv = Dsk[d];
    float h = g_cin[(((size_t)b*NCK + chunk)*64 + d)*8 + n];
    int sbase = chunk * CS;

    for (int sub = 0; sub < CS/32; sub++) {
        int st = sbase + sub*32;
        __syncthreads();
        for (int idx = tid; idx < 32*64; idx += 512) {
            int sl = idx >> 6, dd = idx & 63;
            size_t g = ((size_t)b*LL + st + sl)*64 + dd;
            s_dt[sl][dd] = g_dt[g];
            s_xc[sl][dd] = g_xc[g];
        }
        if (tid < 256) {
            int sl = tid >> 3, nn = tid & 7;
            size_t g = ((size_t)b*LL + st + sl)*8 + nn;
            s_B[sl][nn] = g_Bm[g];
            s_C[sl][nn] = g_Cm[g];
        }
        __syncthreads();
        for (int sl = 0; sl < 32; sl++) {
            float dtv = s_dt[sl][d];
            float xcv = s_xc[sl][d];
            float ex = __expf(dtv * a);
            h = ex*h + dtv * xcv * s_B[sl][n];
            float part = h * s_C[sl][n];
            part += __shfl_xor_sync(0xffffffffu, part, 1);
            part += __shfl_xor_sync(0xffffffffu, part, 2);
            part += __shfl_xor_sync(0xffffffffu, part, 4);
            if (n == 0) s_y[sl][d] = part + xcv * Dv;
        }
        __syncthreads();
        // multiply silu(z) and store at ORIGINAL l
        for (int idx = tid; idx < 32*64; idx += 512) {
            int sl = idx >> 6, dd = idx & 63;
            int s = st + sl;
            int l = (DIR == 0) ? s : (LL - 1 - s);
            float z = g_xz[((size_t)b*LL + l)*128 + 64 + dd];
            float sil = z / (1.f + __expf(-z));
            float val = s_y[sl][dd] * sil;
            size_t o = ((size_t)b*LL + l)*64 + dd;
            if (DIR == 0) g_y[o] = val;
            else          g_y[o] += val;
        }
    }
}

// ---------------- out_proj (×0.5) + LayerNorm, write volume layout -----------
__global__ __launch_bounds__(256) void outln_k(const float* __restrict__ opw,
                                               const float* __restrict__ lng,
                                               const float* __restrict__ lnb)
{
    __shared__ float s_y[64][65];   // reused as r_s after GEMM
    __shared__ float s_w[64][65];
    __shared__ float mu_s[64], rs_s[64];
    int b = blockIdx.y;
    int l0 = blockIdx.x * 64;
    int tid = threadIdx.x;
    for (int idx = tid; idx < 64*64; idx += 256) s_w[idx >> 6][idx & 63] = opw[idx];
    for (int idx = tid; idx < 64*64; idx += 256) {
        int ll = idx >> 6, dd = idx & 63;
        s_y[ll][dd] = g_y[((size_t)b*LL + l0 + ll)*64 + dd];
    }
    __syncthreads();

    int lq = tid & 15, cq = tid >> 4;
    float acc[4][4];
#pragma unroll
    for (int i = 0; i < 4; i++)
#pragma unroll
        for (int j = 0; j < 4; j++) acc[i][j] = 0.f;
    for (int dd = 0; dd < 64; dd++) {
        float yv[4], wv[4];
#pragma unroll
        for (int i = 0; i < 4; i++) yv[i] = s_y[lq*4 + i][dd];
#pragma unroll
        for (int j = 0; j < 4; j++) wv[j] = s_w[cq*4 + j][dd];
#pragma unroll
        for (int i = 0; i < 4; i++)
#pragma unroll
            for (int j = 0; j < 4; j++) acc[i][j] += yv[i] * wv[j];
    }
    __syncthreads();
#pragma unroll
    for (int i = 0; i < 4; i++)
#pragma unroll
        for (int j = 0; j < 4; j++)
            s_y[lq*4 + i][cq*4 + j] = 0.5f * acc[i][j];
    __syncthreads();
    if (tid < 64) {
        float s = 0.f, sq = 0.f;
        for (int c = 0; c < 64; c++) { float v = s_y[tid][c]; s += v; sq += v*v; }
        float mu = s * (1.f/64.f);
        float var = sq * (1.f/64.f) - mu*mu;
        mu_s[tid] = mu; rs_s[tid] = rsqrtf(var + 1e-5f);
    }
    __syncthreads();
    for (int idx = tid; idx < 64*64; idx += 256) {
        int c = idx >> 6, ll = idx & 63;
        float v = (s_y[ll][c] - mu_s[ll]) * rs_s[ll] * lng[c] + lnb[c];
        g_vol2[(size_t)(b*64 + c)*LL + l0 + ll] = v;
    }
}

// ------------------------------- launcher ------------------------------------
extern "C" void kernel_launch(void* const* d_in, const int* in_sizes, int n_in,
                              void* d_out, int out_size)
{
    (void)in_sizes; (void)n_in; (void)out_size;
    const float* input     = (const float*)d_in[0];
    const float* conv_w    = (const float*)d_in[1];
    const float* conv_b    = (const float*)d_in[2];
    const float* in_proj_w = (const float*)d_in[3];
    const float* conv1d_w  = (const float*)d_in[4];
    const float* conv1d_b  = (const float*)d_in[5];
    const float* x_proj_w  = (const float*)d_in[6];
    const float* dt_proj_w = (const float*)d_in[7];
    const float* dt_proj_b = (const float*)d_in[8];
    const float* A_log     = (const float*)d_in[9];
    const float* A_b_log   = (const float*)d_in[10];
    const float* D_skip    = (const float*)d_in[11];
    const float* out_proj_w= (const float*)d_in[12];
    const float* ln_g      = (const float*)d_in[13];
    const float* ln_b      = (const float*)d_in[14];
    float* out = (float*)d_out;

    // conv #1 + instance-norm stats (skip branch deferred to final conv)
    conv3d_k<true><<<2048, 256>>>(input, conv_w, conv_b, nullptr);
    stats_k<<<128, 256>>>();

    // token projection
    inproj_k<<<dim3(512, 2), 256>>>(input, in_proj_w);

    // forward direction
    prep_k<0><<<dim3(512, 2), 256>>>(conv1d_w, conv1d_b, x_proj_w, dt_proj_w, dt_proj_b);
    scanA_k<<<dim3(NCK, 2), 512>>>(A_log);
    scanB_k<<<2, 512>>>();
    scanC_k<0><<<dim3(NCK, 2), 512>>>(A_log, D_skip);

    // backward direction (reuses the same scratch buffers)
    prep_k<1><<<dim3(512, 2), 256>>>(conv1d_w, conv1d_b, x_proj_w, dt_proj_w, dt_proj_b);
    scanA_k<<<dim3(NCK, 2), 512>>>(A_b_log);
    scanB_k<<<2, 512>>>();
    scanC_k<1><<<dim3(NCK, 2), 512>>>(A_b_log, D_skip);

    // out_proj + layernorm into volume layout
    outln_k<<<dim3(512, 2), 256>>>(out_proj_w, ln_g, ln_b);

    // conv #2 + residual skip; input g_vol2 is read from DEVICE code
    conv3d_k<false><<<2048, 256>>>(nullptr, conv_w, conv_b, out);
}

// round 6
// speedup vs baseline: 1.2018x; 1.2018x over previous
#include <cuda_runtime.h>
#include <math.h>

#define BB 2
#define CC 64
#define LL 32768      // 32*32*32 spatial = token count
#define DI 64
#define DS 8
#define CS 256        // scan chunk length
#define NCK 128       // number of chunks = LL/CS

// ---------------- scratch (static device globals; no allocation) -------------
__device__ float g_tmp1[BB*CC*LL];     // conv1 output
__device__ float g_mr[BB*CC*2];        // per (b,c) mean / rstd
__device__ float g_xz[(size_t)BB*LL*128]; // in_proj output, [b][l][128]
__device__ float g_xc[(size_t)BB*LL*DI];  // per-direction (reused)
__device__ float g_dt[(size_t)BB*LL*DI];
__device__ float g_Bm[(size_t)BB*LL*DS];
__device__ float g_Cm[(size_t)BB*LL*DS];
__device__ float g_P[BB*NCK*DI*DS];
__device__ float g_Q[BB*NCK*DI*DS];
__device__ float g_cin[BB*NCK*DI*DS];
__device__ float g_y[(size_t)BB*LL*DI];   // y_f*silu(z) + y_b*silu(z) at original l
__device__ float g_vol2[BB*CC*LL];        // LN output in volume layout (input of conv2)

// ---------------- conv3d (3x3x3, pad 1, 64->64) as register-tiled GEMM -------
// Block = (b, h, j) with j indexing a pair of w values. Output tile:
// M = 64 co  ×  N = 64 pos (pos = wl*32 + d, wl in {0,1}).
// K-loop: ci (64) × 27 taps. Per ci we stage transposed weights s_wT[k][co]
// and an im2col tile s_im[k][pos]; inner loop does 2×LDS.128 + 16 FFMA per tap
// per thread (FMA-pipe bound, no broadcast-LDS-per-FFMA).
template<bool FIRST>
__global__ __launch_bounds__(256) void conv3d_k(
    const float* __restrict__ in, const float* __restrict__ cw,
    const float* __restrict__ cb, float* __restrict__ outp)
{
    __shared__ float s_wT[27][68];   // [tap][co], row padded to 68 (16B-aligned rows)
    __shared__ float s_im[27][68];   // [tap][pos]
    int bid = blockIdx.x;            // 1024 = b(2) × h(32) × j(16)
    int b = bid >> 9;
    int h = (bid >> 4) & 31;
    int j = bid & 15;                // w = 2*j + wl
    int tid = threadIdx.x;
    int r = tid >> 4;                // co0 = 4r
    int c = tid & 15;                // pos0 = 4c

    const float* src = FIRST ? in : (const float*)g_vol2;
    const float* srcb = src + (size_t)b * 64 * LL;

    float acc[4][4];
#pragma unroll
    for (int i = 0; i < 4; i++)
#pragma unroll
        for (int q = 0; q < 4; q++) acc[i][q] = 0.f;

    for (int ci = 0; ci < 64; ci++) {
        // stage weights (transposed) for this ci
        const float* cwc = cw + ci * 27;
        for (int idx = tid; idx < 27*64; idx += 256) {
            int k = idx >> 6, co = idx & 63;
            s_wT[k][co] = cwc[co * 64 * 27 + k];
        }
        // stage im2col tile for this ci
        const float* srcc = srcb + (size_t)ci * LL;
        for (int idx = tid; idx < 27*64; idx += 256) {
            int k = idx >> 6, pos = idx & 63;
            int kh = k / 9;
            int kw = (k / 3) % 3;
            int kd = k - kh*9 - kw*3;
            int ih = h + kh - 1;
            int iw = j*2 + (pos >> 5) + kw - 1;
            int id = (pos & 31) + kd - 1;
            float v = 0.f;
            if ((unsigned)ih < 32u && (unsigned)iw < 32u && (unsigned)id < 32u)
                v = srcc[ih*1024 + iw*32 + id];
            s_im[k][pos] = v;
        }
        __syncthreads();

#pragma unroll
        for (int k = 0; k < 27; k++) {
            float4 wv = *(const float4*)&s_wT[k][r*4];
            float4 iv = *(const float4*)&s_im[k][c*4];
            acc[0][0] += wv.x*iv.x; acc[0][1] += wv.x*iv.y; acc[0][2] += wv.x*iv.z; acc[0][3] += wv.x*iv.w;
            acc[1][0] += wv.y*iv.x; acc[1][1] += wv.y*iv.y; acc[1][2] += wv.y*iv.z; acc[1][3] += wv.y*iv.w;
            acc[2][0] += wv.z*iv.x; acc[2][1] += wv.z*iv.y; acc[2][2] += wv.z*iv.z; acc[2][3] += wv.z*iv.w;
            acc[3][0] += wv.w*iv.x; acc[3][1] += wv.w*iv.y; acc[3][2] += wv.w*iv.z; acc[3][3] += wv.w*iv.w;
        }
        __syncthreads();
    }

    // epilogue: thread owns co 4r..4r+3  ×  pos 4c..4c+3 (contiguous in d)
    int pos0 = c * 4;
    int wl = pos0 >> 5;
    int d0 = pos0 & 31;
    int w = j*2 + wl;
#pragma unroll
    for (int i = 0; i < 4; i++) {
        int co = r*4 + i;
        float bias = cb[co];
        size_t idx = (size_t)(b*64 + co)*LL + h*1024 + w*32 + d0;
        float4 v = make_float4(acc[i][0]+bias, acc[i][1]+bias, acc[i][2]+bias, acc[i][3]+bias);
        if (FIRST) {
            *(float4*)&g_tmp1[idx] = v;
        } else {
            float mean = g_mr[(b*64 + co)*2];
            float rstd = g_mr[(b*64 + co)*2 + 1];
            float4 t = *(const float4*)&g_tmp1[idx];
            float s0 = (t.x - mean)*rstd; s0 = s0 > 0.f ? s0 : 0.f;
            float s1 = (t.y - mean)*rstd; s1 = s1 > 0.f ? s1 : 0.f;
            float s2 = (t.z - mean)*rstd; s2 = s2 > 0.f ? s2 : 0.f;
            float s3 = (t.w - mean)*rstd; s3 = s3 > 0.f ? s3 : 0.f;
            v.x += s0; v.y += s1; v.z += s2; v.w += s3;
            *(float4*)&outp[idx] = v;
        }
    }
}

// ---------------- instance-norm stats (deterministic) ------------------------
__global__ __launch_bounds__(256) void stats_k()
{
    int bc = blockIdx.x;  // 0..127
    const float* p = g_tmp1 + (size_t)bc * LL;
    float s = 0.f, sq = 0.f;
    for (int i = threadIdx.x; i < LL; i += 256) { float v = p[i]; s += v; sq += v*v; }
    __shared__ float sh0[256], sh1[256];
    sh0[threadIdx.x] = s; sh1[threadIdx.x] = sq;
    __syncthreads();
    for (int o = 128; o > 0; o >>= 1) {
        if (threadIdx.x < o) { sh0[threadIdx.x] += sh0[threadIdx.x+o]; sh1[threadIdx.x] += sh1[threadIdx.x+o]; }
        __syncthreads();
    }
    if (threadIdx.x == 0) {
        float mean = sh0[0] * (1.f/LL);
        float var  = sh1[0] * (1.f/LL) - mean*mean;
        g_mr[bc*2]   = mean;
        g_mr[bc*2+1] = rsqrtf(var + 1e-5f);
    }
}

// ---------------- in_proj: xz[b][l][j] = sum_c in[b][c][l] * W[j][c] ----------
__global__ __launch_bounds__(256) void inproj_k(const float* __restrict__ in,
                                                const float* __restrict__ ipw)
{
    __shared__ float s_w[128][66];
    __shared__ float s_x[32][64];
    int b = blockIdx.y;
    int l0 = blockIdx.x * 64;
    int tid = threadIdx.x;
    for (int idx = tid; idx < 128*64; idx += 256) s_w[idx >> 6][idx & 63] = ipw[idx];

    int lq = tid & 15;
    int jq = tid >> 4;
    float acc[4][8];
#pragma unroll
    for (int i = 0; i < 4; i++)
#pragma unroll
        for (int j = 0; j < 8; j++) acc[i][j] = 0.f;

    for (int ch = 0; ch < 2; ch++) {
        __syncthreads();
        for (int idx = tid; idx < 32*64; idx += 256) {
            int c = idx >> 6, ll = idx & 63;
            s_x[c][ll] = in[(size_t)(b*64 + ch*32 + c)*LL + l0 + ll];
        }
        __syncthreads();
        for (int c = 0; c < 32; c++) {
            float xv[4], wv[8];
#pragma unroll
            for (int i = 0; i < 4; i++) xv[i] = s_x[c][lq*4 + i];
#pragma unroll
            for (int j = 0; j < 8; j++) wv[j] = s_w[jq*8 + j][ch*32 + c];
#pragma unroll
            for (int i = 0; i < 4; i++)
#pragma unroll
                for (int j = 0; j < 8; j++) acc[i][j] += xv[i] * wv[j];
        }
    }
#pragma unroll
    for (int i = 0; i < 4; i++) {
        int l = l0 + lq*4 + i;
        float4 v0 = make_float4(acc[i][0], acc[i][1], acc[i][2], acc[i][3]);
        float4 v1 = make_float4(acc[i][4], acc[i][5], acc[i][6], acc[i][7]);
        float4* dst = (float4*)&g_xz[((size_t)b*LL + l)*128 + jq*8];
        dst[0] = v0; dst[1] = v1;
    }
}

// ---------------- per-direction prep: conv1d+silu, x_proj, dt_proj -----------
template<int DIR>
__global__ __launch_bounds__(256) void prep_k(
    const float* __restrict__ w1d_g, const float* __restrict__ b1d_g,
    const float* __restrict__ xpw_g, const float* __restrict__ dtw_g,
    const float* __restrict__ dtb_g)
{
    __shared__ float xs[67][64];
    __shared__ float xc_s[64][65];
    __shared__ float dbl_s[64][20];
    __shared__ float xpw[20][65];
    __shared__ float w1d[64][4];
    __shared__ float dtw[64][5];
    __shared__ float b1d[64], dtb[64];

    int b = blockIdx.y;
    int s0 = blockIdx.x * 64;
    int tid = threadIdx.x;

    for (int idx = tid; idx < 20*64; idx += 256) xpw[idx/64][idx%64] = xpw_g[idx];
    if (tid < 64) {
#pragma unroll
        for (int k = 0; k < 4; k++) { w1d[tid][k] = w1d_g[tid*4 + k]; dtw[tid][k] = dtw_g[tid*4 + k]; }
        b1d[tid] = b1d_g[tid];
        dtb[tid] = dtb_g[tid];
    }
    for (int idx = tid; idx < 67*64; idx += 256) {
        int sr = idx / 64, d = idx % 64;
        int s = s0 + sr - 3;
        float v = 0.f;
        if (s >= 0) {
            int l = (DIR == 0) ? s : (LL - 1 - s);
            v = g_xz[((size_t)b*LL + l)*128 + d];
        }
        xs[sr][d] = v;
    }
    __syncthreads();

    // causal depthwise conv1d (k=4) + silu
    for (int idx = tid; idx < 64*64; idx += 256) {
        int sl = idx >> 6, d = idx & 63;
        float v = b1d[d];
#pragma unroll
        for (int k = 0; k < 4; k++) v += w1d[d][k] * xs[sl + k][d];
        v = v / (1.f + __expf(-v));
        xc_s[sl][d] = v;
        g_xc[((size_t)b*LL + s0 + sl)*64 + d] = v;
    }
    __syncthreads();

    // dbl = xc @ x_proj_w.T  (20 outputs)
    for (int idx = tid; idx < 64*20; idx += 256) {
        int sl = idx / 20, j = idx % 20;
        float v = 0.f;
        for (int d = 0; d < 64; d++) v += xc_s[sl][d] * xpw[j][d];
        dbl_s[sl][j] = v;
        int s = s0 + sl;
        if (j >= 4 && j < 12)      g_Bm[((size_t)b*LL + s)*8 + (j-4)]  = v;
        else if (j >= 12)          g_Cm[((size_t)b*LL + s)*8 + (j-12)] = v;
    }
    __syncthreads();

    // dt = softplus(dt_r @ dt_proj_w.T + b)
    for (int idx = tid; idx < 64*64; idx += 256) {
        int sl = idx >> 6, dd = idx & 63;
        float t = dtb[dd];
#pragma unroll
        for (int r = 0; r < 4; r++) t += dbl_s[sl][r] * dtw[dd][r];
        float sp = (t > 20.f) ? t : log1pf(__expf(t));
        g_dt[((size_t)b*LL + s0 + sl)*64 + dd] = sp;
    }
}

// ---------------- scan pass A: per-chunk (P, Q) reduction --------------------
__global__ __launch_bounds__(512) void scanA_k(const float* __restrict__ alog)
{
    __shared__ float s_dt[32][64];
    __shared__ float s_xc[32][64];
    __shared__ float s_B[32][8];
    int b = blockIdx.y;
    int chunk = blockIdx.x;
    int tid = threadIdx.x;
    int d = tid >> 3, n = tid & 7;
    float a = -__expf(alog[d*8 + n]);
    float P = 1.f, Q = 0.f;
    int sbase = chunk * CS;
    for (int sub = 0; sub < CS/32; sub++) {
        __syncthreads();
        int st = sbase + sub*32;
        for (int idx = tid; idx < 32*64; idx += 512) {
            int sl = idx >> 6, dd = idx & 63;
            size_t g = ((size_t)b*LL + st + sl)*64 + dd;
            s_dt[sl][dd] = g_dt[g];
            s_xc[sl][dd] = g_xc[g];
        }
        if (tid < 256) {
            int sl = tid >> 3, nn = tid & 7;
            s_B[sl][nn] = g_Bm[((size_t)b*LL + st + sl)*8 + nn];
        }
        __syncthreads();
#pragma unroll 8
        for (int sl = 0; sl < 32; sl++) {
            float dtv = s_dt[sl][d];
            float ex = __expf(dtv * a);
            float u = dtv * s_xc[sl][d] * s_B[sl][n];
            P *= ex;
            Q = ex*Q + u;
        }
    }
    size_t o = (((size_t)b*NCK + chunk)*64 + d)*8 + n;
    g_P[o] = P; g_Q[o] = Q;
}

// ---------------- scan pass B: sequential carry across chunks ----------------
__global__ __launch_bounds__(512) void scanB_k()
{
    int idx = blockIdx.x*512 + threadIdx.x;  // 0..1023 = (b, d, n)
    int b = idx >> 9;
    int dn = idx & 511;
    float h = 0.f;
    for (int j = 0; j < NCK; j++) {
        size_t o = ((size_t)(b*NCK + j))*512 + dn;
        g_cin[o] = h;
        h = g_P[o]*h + g_Q[o];
    }
}

// ---------------- scan pass C: replay with carry, y epilogue -----------------
template<int DIR>
__global__ __launch_bounds__(512) void scanC_k(const float* __restrict__ alog,
                                               const float* __restrict__ Dsk)
{
    __shared__ float s_dt[32][64];
    __shared__ float s_xc[32][64];
    __shared__ float s_B[32][8];
    __shared__ float s_C[32][8];
    __shared__ float s_y[32][64];
    int b = blockIdx.y;
    int chunk = blockIdx.x;
    int tid = threadIdx.x;
    int d = tid >> 3, n = tid & 7;
    float a = -__expf(alog[d*8 + n]);
    float Dv = Dsk[d];
    float h = g_cin[(((size_t)b*NCK + chunk)*64 + d)*8 + n];
    int sbase = chunk * CS;

    for (int sub = 0; sub < CS/32; sub++) {
        int st = sbase + sub*32;
        __syncthreads();
        for (int idx = tid; idx < 32*64; idx += 512) {
            int sl = idx >> 6, dd = idx & 63;
            size_t g = ((size_t)b*LL + st + sl)*64 + dd;
            s_dt[sl][dd] = g_dt[g];
            s_xc[sl][dd] = g_xc[g];
        }
        if (tid < 256) {
            int sl = tid >> 3, nn = tid & 7;
            size_t g = ((size_t)b*LL + st + sl)*8 + nn;
            s_B[sl][nn] = g_Bm[g];
            s_C[sl][nn] = g_Cm[g];
        }
        __syncthreads();
        for (int sl = 0; sl < 32; sl++) {
            float dtv = s_dt[sl][d];
            float xcv = s_xc[sl][d];
            float ex = __expf(dtv * a);
            h = ex*h + dtv * xcv * s_B[sl][n];
            float part = h * s_C[sl][n];
            part += __shfl_xor_sync(0xffffffffu, part, 1);
            part += __shfl_xor_sync(0xffffffffu, part, 2);
            part += __shfl_xor_sync(0xffffffffu, part, 4);
            if (n == 0) s_y[sl][d] = part + xcv * Dv;
        }
        __syncthreads();
        // multiply silu(z) and store at ORIGINAL l
        for (int idx = tid; idx < 32*64; idx += 512) {
            int sl = idx >> 6, dd = idx & 63;
            int s = st + sl;
            int l = (DIR == 0) ? s : (LL - 1 - s);
            float z = g_xz[((size_t)b*LL + l)*128 + 64 + dd];
            float sil = z / (1.f + __expf(-z));
            float val = s_y[sl][dd] * sil;
            size_t o = ((size_t)b*LL + l)*64 + dd;
            if (DIR == 0) g_y[o] = val;
            else          g_y[o] += val;
        }
    }
}

// ---------------- out_proj (×0.5) + LayerNorm, write volume layout -----------
__global__ __launch_bounds__(256) void outln_k(const float* __restrict__ opw,
                                               const float* __restrict__ lng,
                                               const float* __restrict__ lnb)
{
    __shared__ float s_y[64][65];   // reused as r_s after GEMM
    __shared__ float s_w[64][65];
    __shared__ float mu_s[64], rs_s[64];
    int b = blockIdx.y;
    int l0 = blockIdx.x * 64;
    int tid = threadIdx.x;
    for (int idx = tid; idx < 64*64; idx += 256) s_w[idx >> 6][idx & 63] = opw[idx];
    for (int idx = tid; idx < 64*64; idx += 256) {
        int ll = idx >> 6, dd = idx & 63;
        s_y[ll][dd] = g_y[((size_t)b*LL + l0 + ll)*64 + dd];
    }
    __syncthreads();

    int lq = tid & 15, cq = tid >> 4;
    float acc[4][4];
#pragma unroll
    for (int i = 0; i < 4; i++)
#pragma unroll
        for (int j = 0; j < 4; j++) acc[i][j] = 0.f;
    for (int dd = 0; dd < 64; dd++) {
        float yv[4], wv[4];
#pragma unroll
        for (int i = 0; i < 4; i++) yv[i] = s_y[lq*4 + i][dd];
#pragma unroll
        for (int j = 0; j < 4; j++) wv[j] = s_w[cq*4 + j][dd];
#pragma unroll
        for (int i = 0; i < 4; i++)
#pragma unroll
            for (int j = 0; j < 4; j++) acc[i][j] += yv[i] * wv[j];
    }
    __syncthreads();
#pragma unroll
    for (int i = 0; i < 4; i++)
#pragma unroll
        for (int j = 0; j < 4; j++)
            s_y[lq*4 + i][cq*4 + j] = 0.5f * acc[i][j];
    __syncthreads();
    if (tid < 64) {
        float s = 0.f, sq = 0.f;
        for (int c = 0; c < 64; c++) { float v = s_y[tid][c]; s += v; sq += v*v; }
        float mu = s * (1.f/64.f);
        float var = sq * (1.f/64.f) - mu*mu;
        mu_s[tid] = mu; rs_s[tid] = rsqrtf(var + 1e-5f);
    }
    __syncthreads();
    for (int idx = tid; idx < 64*64; idx += 256) {
        int c = idx >> 6, ll = idx & 63;
        float v = (s_y[ll][c] - mu_s[ll]) * rs_s[ll] * lng[c] + lnb[c];
        g_vol2[(size_t)(b*64 + c)*LL + l0 + ll] = v;
    }
}

// ------------------------------- launcher ------------------------------------
extern "C" void kernel_launch(void* const* d_in, const int* in_sizes, int n_in,
                              void* d_out, int out_size)
{
    (void)in_sizes; (void)n_in; (void)out_size;
    const float* input     = (const float*)d_in[0];
    const float* conv_w    = (const float*)d_in[1];
    const float* conv_b    = (const float*)d_in[2];
    const float* in_proj_w = (const float*)d_in[3];
    const float* conv1d_w  = (const float*)d_in[4];
    const float* conv1d_b  = (const float*)d_in[5];
    const float* x_proj_w  = (const float*)d_in[6];
    const float* dt_proj_w = (const float*)d_in[7];
    const float* dt_proj_b = (const float*)d_in[8];
    const float* A_log     = (const float*)d_in[9];
    const float* A_b_log   = (const float*)d_in[10];
    const float* D_skip    = (const float*)d_in[11];
    const float* out_proj_w= (const float*)d_in[12];
    const float* ln_g      = (const float*)d_in[13];
    const float* ln_b      = (const float*)d_in[14];
    float* out = (float*)d_out;

    // conv #1 + instance-norm stats (skip branch deferred to final conv)
    conv3d_k<true><<<1024, 256>>>(input, conv_w, conv_b, nullptr);
    stats_k<<<128, 256>>>();

    // token projection
    inproj_k<<<dim3(512, 2), 256>>>(input, in_proj_w);

    // forward direction
    prep_k<0><<<dim3(512, 2), 256>>>(conv1d_w, conv1d_b, x_proj_w, dt_proj_w, dt_proj_b);
    scanA_k<<<dim3(NCK, 2), 512>>>(A_log);
    scanB_k<<<2, 512>>>();
    scanC_k<0><<<dim3(NCK, 2), 512>>>(A_log, D_skip);

    // backward direction (reuses the same scratch buffers)
    prep_k<1><<<dim3(512, 2), 256>>>(conv1d_w, conv1d_b, x_proj_w, dt_proj_w, dt_proj_b);
    scanA_k<<<dim3(NCK, 2), 512>>>(A_b_log);
    scanB_k<<<2, 512>>>();
    scanC_k<1><<<dim3(NCK, 2), 512>>>(A_b_log, D_skip);

    // out_proj + layernorm into volume layout
    outln_k<<<dim3(512, 2), 256>>>(out_proj_w, ln_g, ln_b);

    // conv #2 + residual skip; input g_vol2 is read from DEVICE code
    conv3d_k<false><<<1024, 256>>>(nullptr, conv_w, conv_b, out);
}

// round 7
// speedup vs baseline: 2.1318x; 1.7739x over previous
#include <cuda_runtime.h>
#include <math.h>

#define BB 2
#define CC 64
#define LL 32768      // 32*32*32 spatial = token count
#define DI 64
#define DS 8
#define CS 256        // scan chunk length
#define NCK 128       // number of chunks = LL/CS

// ---------------- scratch (static device globals; no allocation) -------------
__device__ float g_tmp1[BB*CC*LL];     // conv1 output
__device__ float g_mr[BB*CC*2];        // per (b,c) mean / rstd
__device__ float g_xz[(size_t)BB*LL*128]; // in_proj output, [b][l][128]
__device__ float g_xc[(size_t)BB*LL*DI];  // per-direction (reused)
__device__ float g_dt[(size_t)BB*LL*DI];
__device__ float g_Bm[(size_t)BB*LL*DS];
__device__ float g_Cm[(size_t)BB*LL*DS];
__device__ float g_P[BB*NCK*DI*DS];
__device__ float g_Q[BB*NCK*DI*DS];
__device__ float g_cin[BB*NCK*DI*DS];
__device__ float g_y[(size_t)BB*LL*DI];   // y_f*silu(z) + y_b*silu(z) at original l
__device__ float g_vol2[BB*CC*LL];        // LN output in volume layout (input of conv2)
__device__ float g_wT[64*27*64];          // conv weights transposed: [ci][k][co]

// ---------------- one-time weight transpose ----------------------------------
__global__ __launch_bounds__(256) void wtrans_k(const float* __restrict__ cw)
{
    int idx = blockIdx.x*256 + threadIdx.x;   // over 64*64*27 = 110592
    if (idx < 64*64*27) {
        int co  = idx / (64*27);
        int rem = idx % (64*27);
        int ci  = rem / 27;
        int k   = rem % 27;
        g_wT[(ci*27 + k)*64 + co] = cw[idx];
    }
}

// ---------------- conv3d (3x3x3, pad 1, 64->64) as register-tiled GEMM -------
// Block tile: 64 co × 128 pos (pos = wl*32 + d, 4 w-values). 128 threads,
// each owns an 8co × 8pos register tile. K-loop: ci (64) × 27 taps.
// Weights staged from pre-transposed g_wT (coalesced). Per tap per thread:
// 4× LDS.128 + 64 FFMA  →  crossbar need is half of FFMA need.
template<bool FIRST>
__global__ __launch_bounds__(128, 4) void conv3d_k(
    const float* __restrict__ in, const float* __restrict__ cb,
    float* __restrict__ outp)
{
    __shared__ float s_w[27*64];      // [k][co]
    __shared__ float s_im[27][128];   // [k][pos]
    int bid = blockIdx.x;             // 512 = b(2) × h(32) × j(8)
    int b = bid >> 8;
    int h = (bid >> 3) & 31;
    int j = bid & 7;                  // w = 4*j + wl
    int tid = threadIdx.x;
    int r = tid >> 4;                 // co group: co = 8r..8r+7
    int c = tid & 15;                 // pos group: pos = 8c..8c+7

    const float* src = FIRST ? in : (const float*)g_vol2;
    const float* srcb = src + (size_t)b * 64 * LL;

    int wl  = tid >> 5;               // staging pos mapping: pos = tid
    int dd  = tid & 31;
    int iwb = j*4 + wl - 1;
    int idb = dd - 1;
    int ih0 = h - 1;

    float acc[8][8];
#pragma unroll
    for (int m = 0; m < 8; m++)
#pragma unroll
        for (int n = 0; n < 8; n++) acc[m][n] = 0.f;

    for (int ci = 0; ci < 64; ci++) {
        // stage weights (flat, coalesced from pre-transposed buffer)
        const float* wsrc = g_wT + ci * (27*64);
#pragma unroll
        for (int i = 0; i < 13; i++) s_w[tid + i*128] = wsrc[tid + i*128];
        if (tid < 64) s_w[tid + 13*128] = wsrc[tid + 13*128];

        // stage im2col tile
        const float* srcc = srcb + (size_t)ci * LL;
#pragma unroll
        for (int k = 0; k < 27; k++) {
            const int kh = k/9, kw = (k/3)%3, kd = k%3;
            int ih = ih0 + kh, iw = iwb + kw, id = idb + kd;
            float v = 0.f;
            if ((unsigned)ih < 32u && (unsigned)iw < 32u && (unsigned)id < 32u)
                v = srcc[ih*1024 + iw*32 + id];
            s_im[k][tid] = v;
        }
        __syncthreads();

#pragma unroll 9
        for (int k = 0; k < 27; k++) {
            float4 w0 = *(const float4*)&s_w[k*64 + r*8];
            float4 w1 = *(const float4*)&s_w[k*64 + r*8 + 4];
            float4 i0 = *(const float4*)&s_im[k][c*8];
            float4 i1 = *(const float4*)&s_im[k][c*8 + 4];
            float wv[8] = {w0.x,w0.y,w0.z,w0.w, w1.x,w1.y,w1.z,w1.w};
            float iv[8] = {i0.x,i0.y,i0.z,i0.w, i1.x,i1.y,i1.z,i1.w};
#pragma unroll
            for (int m = 0; m < 8; m++)
#pragma unroll
                for (int n = 0; n < 8; n++) acc[m][n] += wv[m]*iv[n];
        }
        __syncthreads();
    }

    // epilogue: thread owns co 8r..8r+7 × pos 8c..8c+7 (contiguous in d)
    int pos0 = c * 8;
    int wlo  = pos0 >> 5;
    int d0   = pos0 & 31;
    int w    = j*4 + wlo;
#pragma unroll
    for (int m = 0; m < 8; m++) {
        int co = r*8 + m;
        float bias = cb[co];
        size_t idx = (size_t)(b*64 + co)*LL + h*1024 + w*32 + d0;
        float4 v0 = make_float4(acc[m][0]+bias, acc[m][1]+bias, acc[m][2]+bias, acc[m][3]+bias);
        float4 v1 = make_float4(acc[m][4]+bias, acc[m][5]+bias, acc[m][6]+bias, acc[m][7]+bias);
        if (FIRST) {
            *(float4*)&g_tmp1[idx]     = v0;
            *(float4*)&g_tmp1[idx + 4] = v1;
        } else {
            float mean = g_mr[(b*64 + co)*2];
            float rstd = g_mr[(b*64 + co)*2 + 1];
            float4 t0 = *(const float4*)&g_tmp1[idx];
            float4 t1 = *(const float4*)&g_tmp1[idx + 4];
            float s;
            s = (t0.x-mean)*rstd; v0.x += s > 0.f ? s : 0.f;
            s = (t0.y-mean)*rstd; v0.y += s > 0.f ? s : 0.f;
            s = (t0.z-mean)*rstd; v0.z += s > 0.f ? s : 0.f;
            s = (t0.w-mean)*rstd; v0.w += s > 0.f ? s : 0.f;
            s = (t1.x-mean)*rstd; v1.x += s > 0.f ? s : 0.f;
            s = (t1.y-mean)*rstd; v1.y += s > 0.f ? s : 0.f;
            s = (t1.z-mean)*rstd; v1.z += s > 0.f ? s : 0.f;
            s = (t1.w-mean)*rstd; v1.w += s > 0.f ? s : 0.f;
            *(float4*)&outp[idx]     = v0;
            *(float4*)&outp[idx + 4] = v1;
        }
    }
}

// ---------------- instance-norm stats (deterministic) ------------------------
__global__ __launch_bounds__(256) void stats_k()
{
    int bc = blockIdx.x;  // 0..127
    const float* p = g_tmp1 + (size_t)bc * LL;
    float s = 0.f, sq = 0.f;
    for (int i = threadIdx.x; i < LL; i += 256) { float v = p[i]; s += v; sq += v*v; }
    __shared__ float sh0[256], sh1[256];
    sh0[threadIdx.x] = s; sh1[threadIdx.x] = sq;
    __syncthreads();
    for (int o = 128; o > 0; o >>= 1) {
        if (threadIdx.x < o) { sh0[threadIdx.x] += sh0[threadIdx.x+o]; sh1[threadIdx.x] += sh1[threadIdx.x+o]; }
        __syncthreads();
    }
    if (threadIdx.x == 0) {
        float mean = sh0[0] * (1.f/LL);
        float var  = sh1[0] * (1.f/LL) - mean*mean;
        g_mr[bc*2]   = mean;
        g_mr[bc*2+1] = rsqrtf(var + 1e-5f);
    }
}

// ---------------- in_proj: xz[b][l][j] = sum_c in[b][c][l] * W[j][c] ----------
__global__ __launch_bounds__(256) void inproj_k(const float* __restrict__ in,
                                                const float* __restrict__ ipw)
{
    __shared__ float s_w[128][66];
    __shared__ float s_x[32][64];
    int b = blockIdx.y;
    int l0 = blockIdx.x * 64;
    int tid = threadIdx.x;
    for (int idx = tid; idx < 128*64; idx += 256) s_w[idx >> 6][idx & 63] = ipw[idx];

    int lq = tid & 15;
    int jq = tid >> 4;
    float acc[4][8];
#pragma unroll
    for (int i = 0; i < 4; i++)
#pragma unroll
        for (int j = 0; j < 8; j++) acc[i][j] = 0.f;

    for (int ch = 0; ch < 2; ch++) {
        __syncthreads();
        for (int idx = tid; idx < 32*64; idx += 256) {
            int c = idx >> 6, ll = idx & 63;
            s_x[c][ll] = in[(size_t)(b*64 + ch*32 + c)*LL + l0 + ll];
        }
        __syncthreads();
        for (int c = 0; c < 32; c++) {
            float xv[4], wv[8];
#pragma unroll
            for (int i = 0; i < 4; i++) xv[i] = s_x[c][lq*4 + i];
#pragma unroll
            for (int j = 0; j < 8; j++) wv[j] = s_w[jq*8 + j][ch*32 + c];
#pragma unroll
            for (int i = 0; i < 4; i++)
#pragma unroll
                for (int j = 0; j < 8; j++) acc[i][j] += xv[i] * wv[j];
        }
    }
#pragma unroll
    for (int i = 0; i < 4; i++) {
        int l = l0 + lq*4 + i;
        float4 v0 = make_float4(acc[i][0], acc[i][1], acc[i][2], acc[i][3]);
        float4 v1 = make_float4(acc[i][4], acc[i][5], acc[i][6], acc[i][7]);
        float4* dst = (float4*)&g_xz[((size_t)b*LL + l)*128 + jq*8];
        dst[0] = v0; dst[1] = v1;
    }
}

// ---------------- per-direction prep: conv1d+silu, x_proj, dt_proj -----------
template<int DIR>
__global__ __launch_bounds__(256) void prep_k(
    const float* __restrict__ w1d_g, const float* __restrict__ b1d_g,
    const float* __restrict__ xpw_g, const float* __restrict__ dtw_g,
    const float* __restrict__ dtb_g)
{
    __shared__ float xs[67][64];
    __shared__ float xc_s[64][65];
    __shared__ float dbl_s[64][20];
    __shared__ float xpw[20][65];
    __shared__ float w1d[64][4];
    __shared__ float dtw[64][5];
    __shared__ float b1d[64], dtb[64];

    int b = blockIdx.y;
    int s0 = blockIdx.x * 64;
    int tid = threadIdx.x;

    for (int idx = tid; idx < 20*64; idx += 256) xpw[idx/64][idx%64] = xpw_g[idx];
    if (tid < 64) {
#pragma unroll
        for (int k = 0; k < 4; k++) { w1d[tid][k] = w1d_g[tid*4 + k]; dtw[tid][k] = dtw_g[tid*4 + k]; }
        b1d[tid] = b1d_g[tid];
        dtb[tid] = dtb_g[tid];
    }
    for (int idx = tid; idx < 67*64; idx += 256) {
        int sr = idx / 64, d = idx % 64;
        int s = s0 + sr - 3;
        float v = 0.f;
        if (s >= 0) {
            int l = (DIR == 0) ? s : (LL - 1 - s);
            v = g_xz[((size_t)b*LL + l)*128 + d];
        }
        xs[sr][d] = v;
    }
    __syncthreads();

    // causal depthwise conv1d (k=4) + silu
    for (int idx = tid; idx < 64*64; idx += 256) {
        int sl = idx >> 6, d = idx & 63;
        float v = b1d[d];
#pragma unroll
        for (int k = 0; k < 4; k++) v += w1d[d][k] * xs[sl + k][d];
        v = v / (1.f + __expf(-v));
        xc_s[sl][d] = v;
        g_xc[((size_t)b*LL + s0 + sl)*64 + d] = v;
    }
    __syncthreads();

    // dbl = xc @ x_proj_w.T  (20 outputs)
    for (int idx = tid; idx < 64*20; idx += 256) {
        int sl = idx / 20, j = idx % 20;
        float v = 0.f;
        for (int d = 0; d < 64; d++) v += xc_s[sl][d] * xpw[j][d];
        dbl_s[sl][j] = v;
        int s = s0 + sl;
        if (j >= 4 && j < 12)      g_Bm[((size_t)b*LL + s)*8 + (j-4)]  = v;
        else if (j >= 12)          g_Cm[((size_t)b*LL + s)*8 + (j-12)] = v;
    }
    __syncthreads();

    // dt = softplus(dt_r @ dt_proj_w.T + b)
    for (int idx = tid; idx < 64*64; idx += 256) {
        int sl = idx >> 6, dd = idx & 63;
        float t = dtb[dd];
#pragma unroll
        for (int r = 0; r < 4; r++) t += dbl_s[sl][r] * dtw[dd][r];
        float sp = (t > 20.f) ? t : log1pf(__expf(t));
        g_dt[((size_t)b*LL + s0 + sl)*64 + dd] = sp;
    }
}

// ---------------- scan pass A: per-chunk (P, Q) reduction --------------------
__global__ __launch_bounds__(512) void scanA_k(const float* __restrict__ alog)
{
    __shared__ float s_dt[32][64];
    __shared__ float s_xc[32][64];
    __shared__ float s_B[32][8];
    int b = blockIdx.y;
    int chunk = blockIdx.x;
    int tid = threadIdx.x;
    int d = tid >> 3, n = tid & 7;
    float a = -__expf(alog[d*8 + n]);
    float P = 1.f, Q = 0.f;
    int sbase = chunk * CS;
    for (int sub = 0; sub < CS/32; sub++) {
        __syncthreads();
        int st = sbase + sub*32;
        for (int idx = tid; idx < 32*64; idx += 512) {
            int sl = idx >> 6, dd = idx & 63;
            size_t g = ((size_t)b*LL + st + sl)*64 + dd;
            s_dt[sl][dd] = g_dt[g];
            s_xc[sl][dd] = g_xc[g];
        }
        if (tid < 256) {
            int sl = tid >> 3, nn = tid & 7;
            s_B[sl][nn] = g_Bm[((size_t)b*LL + st + sl)*8 + nn];
        }
        __syncthreads();
#pragma unroll 8
        for (int sl = 0; sl < 32; sl++) {
            float dtv = s_dt[sl][d];
            float ex = __expf(dtv * a);
            float u = dtv * s_xc[sl][d] * s_B[sl][n];
            P *= ex;
            Q = ex*Q + u;
        }
    }
    size_t o = (((size_t)b*NCK + chunk)*64 + d)*8 + n;
    g_P[o] = P; g_Q[o] = Q;
}

// ---------------- scan pass B: sequential carry across chunks ----------------
__global__ __launch_bounds__(512) void scanB_k()
{
    int idx = blockIdx.x*512 + threadIdx.x;  // 0..1023 = (b, d, n)
    int b = idx >> 9;
    int dn = idx & 511;
    float h = 0.f;
    for (int j = 0; j < NCK; j++) {
        size_t o = ((size_t)(b*NCK + j))*512 + dn;
        g_cin[o] = h;
        h = g_P[o]*h + g_Q[o];
    }
}

// ---------------- scan pass C: replay with carry, y epilogue -----------------
template<int DIR>
__global__ __launch_bounds__(512) void scanC_k(const float* __restrict__ alog,
                                               const float* __restrict__ Dsk)
{
    __shared__ float s_dt[32][64];
    __shared__ float s_xc[32][64];
    __shared__ float s_B[32][8];
    __shared__ float s_C[32][8];
    __shared__ float s_y[32][64];
    int b = blockIdx.y;
    int chunk = blockIdx.x;
    int tid = threadIdx.x;
    int d = tid >> 3, n = tid & 7;
    float a = -__expf(alog[d*8 + n]);
    float Dv = Dsk[d];
    float h = g_cin[(((size_t)b*NCK + chunk)*64 + d)*8 + n];
    int sbase = chunk * CS;

    for (int sub = 0; sub < CS/32; sub++) {
        int st = sbase + sub*32;
        __syncthreads();
        for (int idx = tid; idx < 32*64; idx += 512) {
            int sl = idx >> 6, dd = idx & 63;
            size_t g = ((size_t)b*LL + st + sl)*64 + dd;
            s_dt[sl][dd] = g_dt[g];
            s_xc[sl][dd] = g_xc[g];
        }
        if (tid < 256) {
            int sl = tid >> 3, nn = tid & 7;
            size_t g = ((size_t)b*LL + st + sl)*8 + nn;
            s_B[sl][nn] = g_Bm[g];
            s_C[sl][nn] = g_Cm[g];
        }
        __syncthreads();
        for (int sl = 0; sl < 32; sl++) {
            float dtv = s_dt[sl][d];
            float xcv = s_xc[sl][d];
            float ex = __expf(dtv * a);
            h = ex*h + dtv * xcv * s_B[sl][n];
            float part = h * s_C[sl][n];
            part += __shfl_xor_sync(0xffffffffu, part, 1);
            part += __shfl_xor_sync(0xffffffffu, part, 2);
            part += __shfl_xor_sync(0xffffffffu, part, 4);
            if (n == 0) s_y[sl][d] = part + xcv * Dv;
        }
        __syncthreads();
        // multiply silu(z) and store at ORIGINAL l
        for (int idx = tid; idx < 32*64; idx += 512) {
            int sl = idx >> 6, dd = idx & 63;
            int s = st + sl;
            int l = (DIR == 0) ? s : (LL - 1 - s);
            float z = g_xz[((size_t)b*LL + l)*128 + 64 + dd];
            float sil = z / (1.f + __expf(-z));
            float val = s_y[sl][dd] * sil;
            size_t o = ((size_t)b*LL + l)*64 + dd;
            if (DIR == 0) g_y[o] = val;
            else          g_y[o] += val;
        }
    }
}

// ---------------- out_proj (×0.5) + LayerNorm, write volume layout -----------
__global__ __launch_bounds__(256) void outln_k(const float* __restrict__ opw,
                                               const float* __restrict__ lng,
                                               const float* __restrict__ lnb)
{
    __shared__ float s_y[64][65];   // reused as r_s after GEMM
    __shared__ float s_w[64][65];
    __shared__ float mu_s[64], rs_s[64];
    int b = blockIdx.y;
    int l0 = blockIdx.x * 64;
    int tid = threadIdx.x;
    for (int idx = tid; idx < 64*64; idx += 256) s_w[idx >> 6][idx & 63] = opw[idx];
    for (int idx = tid; idx < 64*64; idx += 256) {
        int ll = idx >> 6, dd = idx & 63;
        s_y[ll][dd] = g_y[((size_t)b*LL + l0 + ll)*64 + dd];
    }
    __syncthreads();

    int lq = tid & 15, cq = tid >> 4;
    float acc[4][4];
#pragma unroll
    for (int i = 0; i < 4; i++)
#pragma unroll
        for (int j = 0; j < 4; j++) acc[i][j] = 0.f;
    for (int dd = 0; dd < 64; dd++) {
        float yv[4], wv[4];
#pragma unroll
        for (int i = 0; i < 4; i++) yv[i] = s_y[lq*4 + i][dd];
#pragma unroll
        for (int j = 0; j < 4; j++) wv[j] = s_w[cq*4 + j][dd];
#pragma unroll
        for (int i = 0; i < 4; i++)
#pragma unroll
            for (int j = 0; j < 4; j++) acc[i][j] += yv[i] * wv[j];
    }
    __syncthreads();
#pragma unroll
    for (int i = 0; i < 4; i++)
#pragma unroll
        for (int j = 0; j < 4; j++)
            s_y[lq*4 + i][cq*4 + j] = 0.5f * acc[i][j];
    __syncthreads();
    if (tid < 64) {
        float s = 0.f, sq = 0.f;
        for (int c = 0; c < 64; c++) { float v = s_y[tid][c]; s += v; sq += v*v; }
        float mu = s * (1.f/64.f);
        float var = sq * (1.f/64.f) - mu*mu;
        mu_s[tid] = mu; rs_s[tid] = rsqrtf(var + 1e-5f);
    }
    __syncthreads();
    for (int idx = tid; idx < 64*64; idx += 256) {
        int c = idx >> 6, ll = idx & 63;
        float v = (s_y[ll][c] - mu_s[ll]) * rs_s[ll] * lng[c] + lnb[c];
        g_vol2[(size_t)(b*64 + c)*LL + l0 + ll] = v;
    }
}

// ------------------------------- launcher ------------------------------------
extern "C" void kernel_launch(void* const* d_in, const int* in_sizes, int n_in,
                              void* d_out, int out_size)
{
    (void)in_sizes; (void)n_in; (void)out_size;
    const float* input     = (const float*)d_in[0];
    const float* conv_w    = (const float*)d_in[1];
    const float* conv_b    = (const float*)d_in[2];
    const float* in_proj_w = (const float*)d_in[3];
    const float* conv1d_w  = (const float*)d_in[4];
    const float* conv1d_b  = (const float*)d_in[5];
    const float* x_proj_w  = (const float*)d_in[6];
    const float* dt_proj_w = (const float*)d_in[7];
    const float* dt_proj_b = (const float*)d_in[8];
    const float* A_log     = (const float*)d_in[9];
    const float* A_b_log   = (const float*)d_in[10];
    const float* D_skip    = (const float*)d_in[11];
    const float* out_proj_w= (const float*)d_in[12];
    const float* ln_g      = (const float*)d_in[13];
    const float* ln_b      = (const float*)d_in[14];
    float* out = (float*)d_out;

    // one-time weight transpose (shared by both convs)
    wtrans_k<<<432, 256>>>(conv_w);

    // conv #1 + instance-norm stats (skip branch deferred to final conv)
    conv3d_k<true><<<512, 128>>>(input, conv_b, nullptr);
    stats_k<<<128, 256>>>();

    // token projection
    inproj_k<<<dim3(512, 2), 256>>>(input, in_proj_w);

    // forward direction
    prep_k<0><<<dim3(512, 2), 256>>>(conv1d_w, conv1d_b, x_proj_w, dt_proj_w, dt_proj_b);
    scanA_k<<<dim3(NCK, 2), 512>>>(A_log);
    scanB_k<<<2, 512>>>();
    scanC_k<0><<<dim3(NCK, 2), 512>>>(A_log, D_skip);

    // backward direction (reuses the same scratch buffers)
    prep_k<1><<<dim3(512, 2), 256>>>(conv1d_w, conv1d_b, x_proj_w, dt_proj_w, dt_proj_b);
    scanA_k<<<dim3(NCK, 2), 512>>>(A_b_log);
    scanB_k<<<2, 512>>>();
    scanC_k<1><<<dim3(NCK, 2), 512>>>(A_b_log, D_skip);

    // out_proj + layernorm into volume layout
    outln_k<<<dim3(512, 2), 256>>>(out_proj_w, ln_g, ln_b);

    // conv #2 + residual skip; input g_vol2 is read from DEVICE code
    conv3d_k<false><<<512, 128>>>(nullptr, conv_b, out);
}

// round 9
// speedup vs baseline: 2.1623x; 1.0143x over previous
#include <cuda_runtime.h>
#include <math.h>
#include <stdint.h>

#define BB 2
#define CC 64
#define LL 32768      // 32*32*32 spatial = token count
#define DI 64
#define DS 8
#define CS 256        // scan chunk length
#define NCK 128       // number of chunks = LL/CS

// ---------------- scratch (static device globals; no allocation) -------------
__device__ float g_tmp1[BB*CC*LL];     // conv1 output
__device__ float g_mr[BB*CC*2];        // per (b,c) mean / rstd
__device__ float g_xz[(size_t)BB*LL*128]; // in_proj output, [b][l][128]
__device__ float g_xc[(size_t)BB*LL*DI];  // per-direction (reused)
__device__ float g_dt[(size_t)BB*LL*DI];
__device__ float g_Bm[(size_t)BB*LL*DS];
__device__ float g_Cm[(size_t)BB*LL*DS];
__device__ float g_P[BB*NCK*DI*DS];
__device__ float g_Q[BB*NCK*DI*DS];
__device__ float g_cin[BB*NCK*DI*DS];
__device__ float g_y[(size_t)BB*LL*DI];   // y_f*silu(z) + y_b*silu(z) at original l
__device__ float g_vol2[BB*CC*LL];        // LN output in volume layout (input of conv2)
__device__ float g_wBh[64*2048];   // weights [ci][k32][co64], tf32-rounded hi
__device__ float g_wBl[64*2048];   // f32 lo residual

// ---------------- one-time weight split: [co][ci][27] -> [ci][k32][co] -------
__global__ __launch_bounds__(256) void wsplit_k(const float* __restrict__ cw)
{
    int idx = blockIdx.x*256 + threadIdx.x;   // 64ci * 32k * 64co = 131072
    if (idx >= 64*32*64) return;
    int ci = idx >> 11;
    int k  = (idx >> 6) & 31;
    int co = idx & 63;
    float w = (k < 27) ? cw[(co*64 + ci)*27 + k] : 0.f;
    uint32_t hb; asm("cvt.rna.tf32.f32 %0, %1;" : "=r"(hb) : "f"(w));
    float hi = __uint_as_float(hb);
    g_wBh[idx] = hi;
    g_wBl[idx] = w - hi;
}

// ---------------- mma.sync m16n8k8 tf32 helper (sm_80+ baseline PTX) ---------
__device__ __forceinline__ void mma8(float* c, const uint32_t* a, const uint32_t* b)
{
    asm volatile("mma.sync.aligned.m16n8k8.row.col.f32.tf32.tf32.f32 "
        "{%0,%1,%2,%3}, {%4,%5,%6,%7}, {%8,%9}, {%0,%1,%2,%3};"
        : "+f"(c[0]), "+f"(c[1]), "+f"(c[2]), "+f"(c[3])
        : "r"(a[0]), "r"(a[1]), "r"(a[2]), "r"(a[3]), "r"(b[0]), "r"(b[1]));
}

// ---------------- conv3d (3x3x3, pad 1, 64->64) via split-tf32 mma.sync ------
// Block = (b, h, j): 128 pos (4 w × 32 d) × 64 co. 8 warps: warp (wm, wn)
// owns pos [wm*32, +32) × co [wn*32, +32) as 2 m-tiles × 4 n-tiles of m16n8k8.
// K = 64 ci × 32 taps (27 real). D = Ah·Bh + Al·Bh + Ah·Bl (tf32 split).
template<bool FIRST>
__global__ __launch_bounds__(256) void conv3d_m(
    const float* __restrict__ in, const float* __restrict__ cb,
    float* __restrict__ outp)
{
    __shared__ float sP[648];        // raw patch [3h][6w][36d-padded]
    __shared__ float sBh[32*72];     // [k][co] pad 72 -> conflict-free frag loads
    __shared__ float sBl[32*72];

    int tid  = threadIdx.x;
    int lane = tid & 31;
    int warp = tid >> 5;
    int wm = warp & 3;               // pos group (also wl, since pos = wl*32+d)
    int wn = warp >> 2;              // co group
    int bid = blockIdx.x;            // 512 = b(2) × h(32) × j(8)
    int b = bid >> 8;
    int h = (bid >> 3) & 31;
    int j = bid & 7;

    const float* src  = FIRST ? in : (const float*)g_vol2;
    const float* srcb = src + (size_t)b * 64 * LL;

    int r = lane & 3;                // threadID_in_group
    int q = lane >> 2;               // groupID

    // Per-thread patch offsets for the 8 k columns this lane touches
    // (4 ksteps × {+0,+4}); folds wl=wm. -1 marks zero-pad (k>=27).
    int koff[4][2];
#pragma unroll
    for (int ks = 0; ks < 4; ks++)
#pragma unroll
        for (int hf = 0; hf < 2; hf++) {
            int k = ks*8 + r + hf*4;
            if (k < 27) {
                int kh = k/9, kw = (k%9)/3, kd = k%3;
                koff[ks][hf] = (kh*6 + kw + wm)*36 + kd;
            } else koff[ks][hf] = -1;
        }

    float acc[2][4][4];
#pragma unroll
    for (int mt = 0; mt < 2; mt++)
#pragma unroll
        for (int nt = 0; nt < 4; nt++)
#pragma unroll
            for (int e = 0; e < 4; e++) acc[mt][nt][e] = 0.f;

    for (int ci = 0; ci < 64; ci++) {
        // stage raw patch [3][6][34->36]
        const float* sc = srcb + (size_t)ci * LL;
        for (int idx = tid; idx < 612; idx += 256) {
            int row = idx / 34, col = idx - row*34;
            int kh = row / 6, iww = row - kh*6;
            int ih = h + kh - 1;
            int iw = j*4 + iww - 1;
            int id = col - 1;
            float v = 0.f;
            if ((unsigned)ih < 32u && (unsigned)iw < 32u && (unsigned)id < 32u)
                v = sc[ih*1024 + iw*32 + id];
            sP[row*36 + col] = v;
        }
        // stage B tiles (flat LDG.128 -> padded STS.128)
        {
            const float4* bh4 = (const float4*)(g_wBh + ci*2048);
            const float4* bl4 = (const float4*)(g_wBl + ci*2048);
#pragma unroll
            for (int t = 0; t < 2; t++) {
                int i = tid + t*256;
                int k = i >> 4, co4 = (i & 15) << 2;
                *(float4*)&sBh[k*72 + co4] = bh4[i];
                *(float4*)&sBl[k*72 + co4] = bl4[i];
            }
        }
        __syncthreads();

#pragma unroll
        for (int ks = 0; ks < 4; ks++) {
            // A fragments (pos × k), hi/lo split
            uint32_t ah[2][4], al[2][4];
#pragma unroll
            for (int mt = 0; mt < 2; mt++) {
                int dA = mt*16 + q;
#pragma unroll
                for (int e = 0; e < 4; e++) {
                    int hf = e >> 1;               // a0,a1:+0 ; a2,a3:+4 in k
                    int dd = dA + ((e & 1) ? 8 : 0); // a1,a3: row+8
                    int off = koff[ks][hf];
                    float v = (off >= 0) ? sP[off + dd] : 0.f;
                    uint32_t hb; asm("cvt.rna.tf32.f32 %0, %1;" : "=r"(hb) : "f"(v));
                    ah[mt][e] = hb;
                    al[mt][e] = __float_as_uint(v - __uint_as_float(hb));
                }
            }
            // B fragments (k × co) — conflict-free (pad 72)
            uint32_t bhf[4][2], blf[4][2];
            int k0 = ks*8 + r;
#pragma unroll
            for (int nt = 0; nt < 4; nt++) {
                int co = wn*32 + nt*8 + q;
                bhf[nt][0] = __float_as_uint(sBh[k0*72 + co]);
                bhf[nt][1] = __float_as_uint(sBh[(k0+4)*72 + co]);
                blf[nt][0] = __float_as_uint(sBl[k0*72 + co]);
                blf[nt][1] = __float_as_uint(sBl[(k0+4)*72 + co]);
            }
#pragma unroll
            for (int mt = 0; mt < 2; mt++)
#pragma unroll
                for (int nt = 0; nt < 4; nt++) {
                    mma8(acc[mt][nt], ah[mt], bhf[nt]);
                    mma8(acc[mt][nt], al[mt], bhf[nt]);
                    mma8(acc[mt][nt], ah[mt], blf[nt]);
                }
        }
        __syncthreads();
    }

    // epilogue: c0:(q,2r) c1:(q,2r+1) c2:(q+8,2r) c3:(q+8,2r+1)
    int w = j*4 + wm;
#pragma unroll
    for (int mt = 0; mt < 2; mt++)
#pragma unroll
        for (int nt = 0; nt < 4; nt++)
#pragma unroll
            for (int e = 0; e < 4; e++) {
                int dd = mt*16 + q + ((e >= 2) ? 8 : 0);
                int co = wn*32 + nt*8 + 2*r + (e & 1);
                size_t gidx = (size_t)(b*64 + co)*LL + h*1024 + w*32 + dd;
                float v = acc[mt][nt][e] + cb[co];
                if (FIRST) {
                    g_tmp1[gidx] = v;
                } else {
                    float mean = g_mr[(b*64 + co)*2];
                    float rstd = g_mr[(b*64 + co)*2 + 1];
                    float s = (g_tmp1[gidx] - mean) * rstd;
                    outp[gidx] = v + (s > 0.f ? s : 0.f);
                }
            }
}

// ---------------- instance-norm stats (deterministic) ------------------------
__global__ __launch_bounds__(256) void stats_k()
{
    int bc = blockIdx.x;  // 0..127
    const float* p = g_tmp1 + (size_t)bc * LL;
    float s = 0.f, sq = 0.f;
    for (int i = threadIdx.x; i < LL; i += 256) { float v = p[i]; s += v; sq += v*v; }
    __shared__ float sh0[256], sh1[256];
    sh0[threadIdx.x] = s; sh1[threadIdx.x] = sq;
    __syncthreads();
    for (int o = 128; o > 0; o >>= 1) {
        if (threadIdx.x < o) { sh0[threadIdx.x] += sh0[threadIdx.x+o]; sh1[threadIdx.x] += sh1[threadIdx.x+o]; }
        __syncthreads();
    }
    if (threadIdx.x == 0) {
        float mean = sh0[0] * (1.f/LL);
        float var  = sh1[0] * (1.f/LL) - mean*mean;
        g_mr[bc*2]   = mean;
        g_mr[bc*2+1] = rsqrtf(var + 1e-5f);
    }
}

// ---------------- in_proj: xz[b][l][j] = sum_c in[b][c][l] * W[j][c] ----------
__global__ __launch_bounds__(256) void inproj_k(const float* __restrict__ in,
                                                const float* __restrict__ ipw)
{
    __shared__ float s_w[128][66];
    __shared__ float s_x[32][64];
    int b = blockIdx.y;
    int l0 = blockIdx.x * 64;
    int tid = threadIdx.x;
    for (int idx = tid; idx < 128*64; idx += 256) s_w[idx >> 6][idx & 63] = ipw[idx];

    int lq = tid & 15;
    int jq = tid >> 4;
    float acc[4][8];
#pragma unroll
    for (int i = 0; i < 4; i++)
#pragma unroll
        for (int j = 0; j < 8; j++) acc[i][j] = 0.f;

    for (int ch = 0; ch < 2; ch++) {
        __syncthreads();
        for (int idx = tid; idx < 32*64; idx += 256) {
            int c = idx >> 6, ll = idx & 63;
            s_x[c][ll] = in[(size_t)(b*64 + ch*32 + c)*LL + l0 + ll];
        }
        __syncthreads();
        for (int c = 0; c < 32; c++) {
            float xv[4], wv[8];
#pragma unroll
            for (int i = 0; i < 4; i++) xv[i] = s_x[c][lq*4 + i];
#pragma unroll
            for (int j = 0; j < 8; j++) wv[j] = s_w[jq*8 + j][ch*32 + c];
#pragma unroll
            for (int i = 0; i < 4; i++)
#pragma unroll
                for (int j = 0; j < 8; j++) acc[i][j] += xv[i] * wv[j];
        }
    }
#pragma unroll
    for (int i = 0; i < 4; i++) {
        int l = l0 + lq*4 + i;
        float4 v0 = make_float4(acc[i][0], acc[i][1], acc[i][2], acc[i][3]);
        float4 v1 = make_float4(acc[i][4], acc[i][5], acc[i][6], acc[i][7]);
        float4* dst = (float4*)&g_xz[((size_t)b*LL + l)*128 + jq*8];
        dst[0] = v0; dst[1] = v1;
    }
}

// ---------------- per-direction prep: conv1d+silu, x_proj, dt_proj -----------
template<int DIR>
__global__ __launch_bounds__(256) void prep_k(
    const float* __restrict__ w1d_g, const float* __restrict__ b1d_g,
    const float* __restrict__ xpw_g, const float* __restrict__ dtw_g,
    const float* __restrict__ dtb_g)
{
    __shared__ float xs[67][64];
    __shared__ float xc_s[64][65];
    __shared__ float dbl_s[64][20];
    __shared__ float xpw[20][65];
    __shared__ float w1d[64][4];
    __shared__ float dtw[64][5];
    __shared__ float b1d[64], dtb[64];

    int b = blockIdx.y;
    int s0 = blockIdx.x * 64;
    int tid = threadIdx.x;

    for (int idx = tid; idx < 20*64; idx += 256) xpw[idx/64][idx%64] = xpw_g[idx];
    if (tid < 64) {
#pragma unroll
        for (int k = 0; k < 4; k++) { w1d[tid][k] = w1d_g[tid*4 + k]; dtw[tid][k] = dtw_g[tid*4 + k]; }
        b1d[tid] = b1d_g[tid];
        dtb[tid] = dtb_g[tid];
    }
    for (int idx = tid; idx < 67*64; idx += 256) {
        int sr = idx / 64, d = idx % 64;
        int s = s0 + sr - 3;
        float v = 0.f;
        if (s >= 0) {
            int l = (DIR == 0) ? s : (LL - 1 - s);
            v = g_xz[((size_t)b*LL + l)*128 + d];
        }
        xs[sr][d] = v;
    }
    __syncthreads();

    // causal depthwise conv1d (k=4) + silu
    for (int idx = tid; idx < 64*64; idx += 256) {
        int sl = idx >> 6, d = idx & 63;
        float v = b1d[d];
#pragma unroll
        for (int k = 0; k < 4; k++) v += w1d[d][k] * xs[sl + k][d];
        v = v / (1.f + __expf(-v));
        xc_s[sl][d] = v;
        g_xc[((size_t)b*LL + s0 + sl)*64 + d] = v;
    }
    __syncthreads();

    // dbl = xc @ x_proj_w.T  (20 outputs)
    for (int idx = tid; idx < 64*20; idx += 256) {
        int sl = idx / 20, j = idx % 20;
        float v = 0.f;
        for (int d = 0; d < 64; d++) v += xc_s[sl][d] * xpw[j][d];
        dbl_s[sl][j] = v;
        int s = s0 + sl;
        if (j >= 4 && j < 12)      g_Bm[((size_t)b*LL + s)*8 + (j-4)]  = v;
        else if (j >= 12)          g_Cm[((size_t)b*LL + s)*8 + (j-12)] = v;
    }
    __syncthreads();

    // dt = softplus(dt_r @ dt_proj_w.T + b)
    for (int idx = tid; idx < 64*64; idx += 256) {
        int sl = idx >> 6, dd = idx & 63;
        float t = dtb[dd];
#pragma unroll
        for (int r = 0; r < 4; r++) t += dbl_s[sl][r] * dtw[dd][r];
        float sp = (t > 20.f) ? t : log1pf(__expf(t));
        g_dt[((size_t)b*LL + s0 + sl)*64 + dd] = sp;
    }
}

// ---------------- scan pass A: per-chunk (P, Q) reduction --------------------
__global__ __launch_bounds__(512) void scanA_k(const float* __restrict__ alog)
{
    __shared__ float s_dt[32][64];
    __shared__ float s_xc[32][64];
    __shared__ float s_B[32][8];
    int b = blockIdx.y;
    int chunk = blockIdx.x;
    int tid = threadIdx.x;
    int d = tid >> 3, n = tid & 7;
    float a = -__expf(alog[d*8 + n]);
    float P = 1.f, Q = 0.f;
    int sbase = chunk * CS;
    for (int sub = 0; sub < CS/32; sub++) {
        __syncthreads();
        int st = sbase + sub*32;
        for (int idx = tid; idx < 32*64; idx += 512) {
            int sl = idx >> 6, dd = idx & 63;
            size_t g = ((size_t)b*LL + st + sl)*64 + dd;
            s_dt[sl][dd] = g_dt[g];
            s_xc[sl][dd] = g_xc[g];
        }
        if (tid < 256) {
            int sl = tid >> 3, nn = tid & 7;
            s_B[sl][nn] = g_Bm[((size_t)b*LL + st + sl)*8 + nn];
        }
        __syncthreads();
#pragma unroll 8
        for (int sl = 0; sl < 32; sl++) {
            float dtv = s_dt[sl][d];
            float ex = __expf(dtv * a);
            float u = dtv * s_xc[sl][d] * s_B[sl][n];
            P *= ex;
            Q = ex*Q + u;
        }
    }
    size_t o = (((size_t)b*NCK + chunk)*64 + d)*8 + n;
    g_P[o] = P; g_Q[o] = Q;
}

// ---------------- scan pass B: sequential carry across chunks ----------------
__global__ __launch_bounds__(512) void scanB_k()
{
    int idx = blockIdx.x*512 + threadIdx.x;  // 0..1023 = (b, d, n)
    int b = idx >> 9;
    int dn = idx & 511;
    float h = 0.f;
    for (int j = 0; j < NCK; j++) {
        size_t o = ((size_t)(b*NCK + j))*512 + dn;
        g_cin[o] = h;
        h = g_P[o]*h + g_Q[o];
    }
}

// ---------------- scan pass C: replay with carry, y epilogue -----------------
template<int DIR>
__global__ __launch_bounds__(512) void scanC_k(const float* __restrict__ alog,
                                               const float* __restrict__ Dsk)
{
    __shared__ float s_dt[32][64];
    __shared__ float s_xc[32][64];
    __shared__ float s_B[32][8];
    __shared__ float s_C[32][8];
    __shared__ float s_y[32][64];
    int b = blockIdx.y;
    int chunk = blockIdx.x;
    int tid = threadIdx.x;
    int d = tid >> 3, n = tid & 7;
    float a = -__expf(alog[d*8 + n]);
    float Dv = Dsk[d];
    float h = g_cin[(((size_t)b*NCK + chunk)*64 + d)*8 + n];
    int sbase = chunk * CS;

    for (int sub = 0; sub < CS/32; sub++) {
        int st = sbase + sub*32;
        __syncthreads();
        for (int idx = tid; idx < 32*64; idx += 512) {
            int sl = idx >> 6, dd = idx & 63;
            size_t g = ((size_t)b*LL + st + sl)*64 + dd;
            s_dt[sl][dd] = g_dt[g];
            s_xc[sl][dd] = g_xc[g];
        }
        if (tid < 256) {
            int sl = tid >> 3, nn = tid & 7;
            size_t g = ((size_t)b*LL + st + sl)*8 + nn;
            s_B[sl][nn] = g_Bm[g];
            s_C[sl][nn] = g_Cm[g];
        }
        __syncthreads();
        for (int sl = 0; sl < 32; sl++) {
            float dtv = s_dt[sl][d];
            float xcv = s_xc[sl][d];
            float ex = __expf(dtv * a);
            h = ex*h + dtv * xcv * s_B[sl][n];
            float part = h * s_C[sl][n];
            part += __shfl_xor_sync(0xffffffffu, part, 1);
            part += __shfl_xor_sync(0xffffffffu, part, 2);
            part += __shfl_xor_sync(0xffffffffu, part, 4);
            if (n == 0) s_y[sl][d] = part + xcv * Dv;
        }
        __syncthreads();
        // multiply silu(z) and store at ORIGINAL l
        for (int idx = tid; idx < 32*64; idx += 512) {
            int sl = idx >> 6, dd = idx & 63;
            int s = st + sl;
            int l = (DIR == 0) ? s : (LL - 1 - s);
            float z = g_xz[((size_t)b*LL + l)*128 + 64 + dd];
            float sil = z / (1.f + __expf(-z));
            float val = s_y[sl][dd] * sil;
            size_t o = ((size_t)b*LL + l)*64 + dd;
            if (DIR == 0) g_y[o] = val;
            else          g_y[o] += val;
        }
    }
}

// ---------------- out_proj (×0.5) + LayerNorm, write volume layout -----------
__global__ __launch_bounds__(256) void outln_k(const float* __restrict__ opw,
                                               const float* __restrict__ lng,
                                               const float* __restrict__ lnb)
{
    __shared__ float s_y[64][65];   // reused as r_s after GEMM
    __shared__ float s_w[64][65];
    __shared__ float mu_s[64], rs_s[64];
    int b = blockIdx.y;
    int l0 = blockIdx.x * 64;
    int tid = threadIdx.x;
    for (int idx = tid; idx < 64*64; idx += 256) s_w[idx >> 6][idx & 63] = opw[idx];
    for (int idx = tid; idx < 64*64; idx += 256) {
        int ll = idx >> 6, dd = idx & 63;
        s_y[ll][dd] = g_y[((size_t)b*LL + l0 + ll)*64 + dd];
    }
    __syncthreads();

    int lq = tid & 15, cq = tid >> 4;
    float acc[4][4];
#pragma unroll
    for (int i = 0; i < 4; i++)
#pragma unroll
        for (int j = 0; j < 4; j++) acc[i][j] = 0.f;
    for (int dd = 0; dd < 64; dd++) {
        float yv[4], wv[4];
#pragma unroll
        for (int i = 0; i < 4; i++) yv[i] = s_y[lq*4 + i][dd];
#pragma unroll
        for (int j = 0; j < 4; j++) wv[j] = s_w[cq*4 + j][dd];
#pragma unroll
        for (int i = 0; i < 4; i++)
#pragma unroll
            for (int j = 0; j < 4; j++) acc[i][j] += yv[i] * wv[j];
    }
    __syncthreads();
#pragma unroll
    for (int i = 0; i < 4; i++)
#pragma unroll
        for (int j = 0; j < 4; j++)
            s_y[lq*4 + i][cq*4 + j] = 0.5f * acc[i][j];
    __syncthreads();
    if (tid < 64) {
        float s = 0.f, sq = 0.f;
        for (int c = 0; c < 64; c++) { float v = s_y[tid][c]; s += v; sq += v*v; }
        float mu = s * (1.f/64.f);
        float var = sq * (1.f/64.f) - mu*mu;
        mu_s[tid] = mu; rs_s[tid] = rsqrtf(var + 1e-5f);
    }
    __syncthreads();
    for (int idx = tid; idx < 64*64; idx += 256) {
        int c = idx >> 6, ll = idx & 63;
        float v = (s_y[ll][c] - mu_s[ll]) * rs_s[ll] * lng[c] + lnb[c];
        g_vol2[(size_t)(b*64 + c)*LL + l0 + ll] = v;
    }
}

// ------------------------------- launcher ------------------------------------
extern "C" void kernel_launch(void* const* d_in, const int* in_sizes, int n_in,
                              void* d_out, int out_size)
{
    (void)in_sizes; (void)n_in; (void)out_size;
    const float* input     = (const float*)d_in[0];
    const float* conv_w    = (const float*)d_in[1];
    const float* conv_b    = (const float*)d_in[2];
    const float* in_proj_w = (const float*)d_in[3];
    const float* conv1d_w  = (const float*)d_in[4];
    const float* conv1d_b  = (const float*)d_in[5];
    const float* x_proj_w  = (const float*)d_in[6];
    const float* dt_proj_w = (const float*)d_in[7];
    const float* dt_proj_b = (const float*)d_in[8];
    const float* A_log     = (const float*)d_in[9];
    const float* A_b_log   = (const float*)d_in[10];
    const float* D_skip    = (const float*)d_in[11];
    const float* out_proj_w= (const float*)d_in[12];
    const float* ln_g      = (const float*)d_in[13];
    const float* ln_b      = (const float*)d_in[14];
    float* out = (float*)d_out;

    // one-time weight split (shared by both convs)
    wsplit_k<<<512, 256>>>(conv_w);

    // conv #1 + instance-norm stats (skip branch deferred to final conv)
    conv3d_m<true><<<512, 256>>>(input, conv_b, nullptr);
    stats_k<<<128, 256>>>();

    // token projection
    inproj_k<<<dim3(512, 2), 256>>>(input, in_proj_w);

    // forward direction
    prep_k<0><<<dim3(512, 2), 256>>>(conv1d_w, conv1d_b, x_proj_w, dt_proj_w, dt_proj_b);
    scanA_k<<<dim3(NCK, 2), 512>>>(A_log);
    scanB_k<<<2, 512>>>();
    scanC_k<0><<<dim3(NCK, 2), 512>>>(A_log, D_skip);

    // backward direction (reuses the same scratch buffers)
    prep_k<1><<<dim3(512, 2), 256>>>(conv1d_w, conv1d_b, x_proj_w, dt_proj_w, dt_proj_b);
    scanA_k<<<dim3(NCK, 2), 512>>>(A_b_log);
    scanB_k<<<2, 512>>>();
    scanC_k<1><<<dim3(NCK, 2), 512>>>(A_b_log, D_skip);

    // out_proj + layernorm into volume layout
    outln_k<<<dim3(512, 2), 256>>>(out_proj_w, ln_g, ln_b);

    // conv #2 + residual skip; input g_vol2 is read from DEVICE code
    conv3d_m<false><<<512, 256>>>(nullptr, conv_b, out);
}

// round 11
// speedup vs baseline: 2.3180x; 1.0720x over previous
#include <cuda_runtime.h>
#include <math.h>
#include <stdint.h>

#define BB 2
#define CC 64
#define LL 32768      // 32*32*32 spatial = token count
#define DI 64
#define DS 8
#define CS 256        // scan chunk length
#define NCK 128       // number of chunks = LL/CS

// ---------------- scratch (static device globals; no allocation) -------------
__device__ float g_tmp1[BB*CC*LL];     // conv1 output
__device__ float g_mr[BB*CC*2];        // per (b,c) mean / rstd
__device__ float g_xz[(size_t)BB*LL*128]; // in_proj output, [b][l][128]
__device__ float g_xc[(size_t)BB*LL*DI];  // per-direction (reused)
__device__ float g_dt[(size_t)BB*LL*DI];
__device__ float g_Bm[(size_t)BB*LL*DS];
__device__ float g_Cm[(size_t)BB*LL*DS];
__device__ float g_P[BB*NCK*DI*DS];
__device__ float g_Q[BB*NCK*DI*DS];
__device__ float g_cin[BB*NCK*DI*DS];
__device__ float g_y[(size_t)BB*LL*DI];   // y_f*silu(z) + y_b*silu(z) at original l
__device__ float g_vol2[BB*CC*LL];        // LN output in volume layout (input of conv2)
__device__ float g_wBh[64*2048];   // weights [ci][k32][co64], tf32-rounded hi
__device__ float g_wBl[64*2048];   // f32 lo residual

// ---------------- one-time weight split: [co][ci][27] -> [ci][k32][co] -------
__global__ __launch_bounds__(256) void wsplit_k(const float* __restrict__ cw)
{
    int idx = blockIdx.x*256 + threadIdx.x;   // 64ci * 32k * 64co = 131072
    if (idx >= 64*32*64) return;
    int ci = idx >> 11;
    int k  = (idx >> 6) & 31;
    int co = idx & 63;
    float w = (k < 27) ? cw[(co*64 + ci)*27 + k] : 0.f;
    uint32_t hb; asm("cvt.rna.tf32.f32 %0, %1;" : "=r"(hb) : "f"(w));
    float hi = __uint_as_float(hb);
    g_wBh[idx] = hi;
    g_wBl[idx] = w - hi;
}

// ---------------- mma.sync m16n8k8 tf32 helper (sm_80+ baseline PTX) ---------
__device__ __forceinline__ void mma8(float* c, const uint32_t* a, const uint32_t* b)
{
    asm volatile("mma.sync.aligned.m16n8k8.row.col.f32.tf32.tf32.f32 "
        "{%0,%1,%2,%3}, {%4,%5,%6,%7}, {%8,%9}, {%0,%1,%2,%3};"
        : "+f"(c[0]), "+f"(c[1]), "+f"(c[2]), "+f"(c[3])
        : "r"(a[0]), "r"(a[1]), "r"(a[2]), "r"(a[3]), "r"(b[0]), "r"(b[1]));
}

// ---------------- cp.async helpers (sm_80+ baseline PTX) ---------------------
__device__ __forceinline__ uint32_t s2u32(const void* p) {
    uint32_t a;
    asm("{ .reg .u64 t; cvta.to.shared.u64 t, %1; cvt.u32.u64 %0, t; }" : "=r"(a) : "l"(p));
    return a;
}
__device__ __forceinline__ void cpa4(uint32_t dst, const float* src, int srcsz) {
    asm volatile("cp.async.ca.shared.global [%0], [%1], 4, %2;"
        :: "r"(dst), "l"(src), "r"(srcsz) : "memory");
}
__device__ __forceinline__ void cpa16(uint32_t dst, const float4* src) {
    asm volatile("cp.async.cg.shared.global [%0], [%1], 16;"
        :: "r"(dst), "l"(src) : "memory");
}
#define CP_COMMIT() asm volatile("cp.async.commit_group;" ::: "memory")
#define CP_WAIT1()  asm volatile("cp.async.wait_group 1;" ::: "memory")
#define CP_WAIT0()  asm volatile("cp.async.wait_group 0;" ::: "memory")

// ---------------- conv3d (3x3x3, pad 1, 64->64) via split-tf32 mma.sync ------
// Block = (b, h, j): 128 pos (4 w × 32 d) × 64 co. 8 warps: warp (wm, wn)
// owns pos [wm*32, +32) × co [wn*32, +32) as 2 m-tiles × 4 n-tiles of m16n8k8.
// K = 64 ci × 32 taps (27 real). D = Ah·Bh + Al·Bh + Ah·Bl (tf32 split).
// Staging is cp.async double-buffered: prefetch ci+1 while computing ci.
// NOTE: patch SMEM layout is 36-stride rows ([3h*6w][36]); the cp.async
// destinations MUST use row*36+col (round-10 bug was flat 34-stride dsts).
template<bool FIRST>
__global__ __launch_bounds__(256) void conv3d_m(
    const float* __restrict__ in, const float* __restrict__ cb,
    float* __restrict__ outp)
{
    __shared__ __align__(16) float sP[2][648];       // raw patch [3h*6w][36]
    __shared__ __align__(16) float sBh[2][32*72];    // [k][co] pad 72
    __shared__ __align__(16) float sBl[2][32*72];

    int tid  = threadIdx.x;
    int lane = tid & 31;
    int warp = tid >> 5;
    int wm = warp & 3;               // pos group (also wl, since pos = wl*32+d)
    int wn = warp >> 2;              // co group
    int bid = blockIdx.x;            // 512 = b(2) × h(32) × j(8)
    int b = bid >> 8;
    int h = (bid >> 3) & 31;
    int j = bid & 7;

    const float* src  = FIRST ? in : (const float*)g_vol2;
    const float* srcb = src + (size_t)b * 64 * LL;

    int r = lane & 3;                // threadID_in_group
    int q = lane >> 2;               // groupID

    // ---- precomputed per-thread staging descriptors ----
    // patch: 612 logical elements (18 rows × 34 cols), stored at row*36+col.
    int   pOff[3]; int pSz[3]; uint32_t pDst0[3], pDst1[3];
    int nP = (tid < 100) ? 3 : 2;
#pragma unroll
    for (int e = 0; e < 3; e++) {
        int idx = tid + e*256;
        if (idx < 612) {
            int row = idx / 34, col = idx - row*34;
            int kh = row / 6, iww = row - kh*6;
            int ih = h + kh - 1;
            int iw = j*4 + iww - 1;
            int id = col - 1;
            bool ok = (unsigned)ih < 32u && (unsigned)iw < 32u && (unsigned)id < 32u;
            pOff[e] = ok ? (ih*1024 + iw*32 + id) : 0;
            pSz[e]  = ok ? 4 : 0;
            pDst0[e] = s2u32(&sP[0][row*36 + col]);   // 36-stride (matches koff)
            pDst1[e] = s2u32(&sP[1][row*36 + col]);
        }
    }
    // B: 512 16B-chunks per (h|l); thread handles c = tid, tid+256
    uint32_t bDst0[2][2], bDst1[2][2];   // [t][h/l]
    int bSrcOff[2];
#pragma unroll
    for (int t = 0; t < 2; t++) {
        int c = tid + t*256;
        int k = c >> 4, cc = c & 15;
        bSrcOff[t] = c*4;                              // float offset in dense 2048
        bDst0[t][0] = s2u32(&sBh[0][k*72 + cc*4]);
        bDst1[t][0] = s2u32(&sBh[1][k*72 + cc*4]);
        bDst0[t][1] = s2u32(&sBl[0][k*72 + cc*4]);
        bDst1[t][1] = s2u32(&sBl[1][k*72 + cc*4]);
    }

    // Per-thread patch offsets for the 8 k columns this lane touches
    int koff[4][2];
#pragma unroll
    for (int ks = 0; ks < 4; ks++)
#pragma unroll
        for (int hf = 0; hf < 2; hf++) {
            int k = ks*8 + r + hf*4;
            if (k < 27) {
                int kh = k/9, kw = (k%9)/3, kd = k%3;
                koff[ks][hf] = (kh*6 + kw + wm)*36 + kd;
            } else koff[ks][hf] = -1;
        }

    float acc[2][4][4];
#pragma unroll
    for (int mt = 0; mt < 2; mt++)
#pragma unroll
        for (int nt = 0; nt < 4; nt++)
#pragma unroll
            for (int e = 0; e < 4; e++) acc[mt][nt][e] = 0.f;

    // ---- prefetch ci = 0 into buffer 0 ----
    {
        const float* sc = srcb;                       // ci = 0
        for (int e = 0; e < nP; e++) cpa4(pDst0[e], sc + pOff[e], pSz[e]);
#pragma unroll
        for (int t = 0; t < 2; t++) {
            cpa16(bDst0[t][0], (const float4*)(g_wBh + bSrcOff[t]));
            cpa16(bDst0[t][1], (const float4*)(g_wBl + bSrcOff[t]));
        }
        CP_COMMIT();
    }

    for (int ci = 0; ci < 64; ci++) {
        int cur = ci & 1;
        if (ci < 63) {
            // prefetch ci+1 into the other buffer
            const float* sc = srcb + (size_t)(ci+1) * LL;
            int bo = (ci+1) * 2048;
            if (cur == 0) {
                for (int e = 0; e < nP; e++) cpa4(pDst1[e], sc + pOff[e], pSz[e]);
#pragma unroll
                for (int t = 0; t < 2; t++) {
                    cpa16(bDst1[t][0], (const float4*)(g_wBh + bo + bSrcOff[t]));
                    cpa16(bDst1[t][1], (const float4*)(g_wBl + bo + bSrcOff[t]));
                }
            } else {
                for (int e = 0; e < nP; e++) cpa4(pDst0[e], sc + pOff[e], pSz[e]);
#pragma unroll
                for (int t = 0; t < 2; t++) {
                    cpa16(bDst0[t][0], (const float4*)(g_wBh + bo + bSrcOff[t]));
                    cpa16(bDst0[t][1], (const float4*)(g_wBl + bo + bSrcOff[t]));
                }
            }
            CP_COMMIT();
            CP_WAIT1();           // current buffer's group complete
        } else {
            CP_WAIT0();
        }
        __syncthreads();          // all threads' copies visible

        const float* sPc  = sP[cur];
        const float* sBhc = sBh[cur];
        const float* sBlc = sBl[cur];

#pragma unroll
        for (int ks = 0; ks < 4; ks++) {
            // A fragments (pos × k), hi/lo split
            uint32_t ah[2][4], al[2][4];
#pragma unroll
            for (int mt = 0; mt < 2; mt++) {
                int dA = mt*16 + q;
#pragma unroll
                for (int e = 0; e < 4; e++) {
                    int hf = e >> 1;
                    int dd = dA + ((e & 1) ? 8 : 0);
                    int off = koff[ks][hf];
                    float v = (off >= 0) ? sPc[off + dd] : 0.f;
                    uint32_t hb; asm("cvt.rna.tf32.f32 %0, %1;" : "=r"(hb) : "f"(v));
                    ah[mt][e] = hb;
                    al[mt][e] = __float_as_uint(v - __uint_as_float(hb));
                }
            }
            // B fragments (k × co) — conflict-free (pad 72)
            uint32_t bhf[4][2], blf[4][2];
            int k0 = ks*8 + r;
#pragma unroll
            for (int nt = 0; nt < 4; nt++) {
                int co = wn*32 + nt*8 + q;
                bhf[nt][0] = __float_as_uint(sBhc[k0*72 + co]);
                bhf[nt][1] = __float_as_uint(sBhc[(k0+4)*72 + co]);
                blf[nt][0] = __float_as_uint(sBlc[k0*72 + co]);
                blf[nt][1] = __float_as_uint(sBlc[(k0+4)*72 + co]);
            }
#pragma unroll
            for (int mt = 0; mt < 2; mt++)
#pragma unroll
                for (int nt = 0; nt < 4; nt++) {
                    mma8(acc[mt][nt], ah[mt], bhf[nt]);
                    mma8(acc[mt][nt], al[mt], bhf[nt]);
                    mma8(acc[mt][nt], ah[mt], blf[nt]);
                }
        }
        __syncthreads();          // done reading cur before it is overwritten
    }

    // epilogue: c0:(q,2r) c1:(q,2r+1) c2:(q+8,2r) c3:(q+8,2r+1)
    int w = j*4 + wm;
#pragma unroll
    for (int mt = 0; mt < 2; mt++)
#pragma unroll
        for (int nt = 0; nt < 4; nt++)
#pragma unroll
            for (int e = 0; e < 4; e++) {
                int dd = mt*16 + q + ((e >= 2) ? 8 : 0);
                int co = wn*32 + nt*8 + 2*r + (e & 1);
                size_t gidx = (size_t)(b*64 + co)*LL + h*1024 + w*32 + dd;
                float v = acc[mt][nt][e] + cb[co];
                if (FIRST) {
                    g_tmp1[gidx] = v;
                } else {
                    float mean = g_mr[(b*64 + co)*2];
                    float rstd = g_mr[(b*64 + co)*2 + 1];
                    float s = (g_tmp1[gidx] - mean) * rstd;
                    outp[gidx] = v + (s > 0.f ? s : 0.f);
                }
            }
}

// ---------------- instance-norm stats (deterministic) ------------------------
__global__ __launch_bounds__(256) void stats_k()
{
    int bc = blockIdx.x;  // 0..127
    const float* p = g_tmp1 + (size_t)bc * LL;
    float s = 0.f, sq = 0.f;
    for (int i = threadIdx.x; i < LL; i += 256) { float v = p[i]; s += v; sq += v*v; }
    __shared__ float sh0[256], sh1[256];
    sh0[threadIdx.x] = s; sh1[threadIdx.x] = sq;
    __syncthreads();
    for (int o = 128; o > 0; o >>= 1) {
        if (threadIdx.x < o) { sh0[threadIdx.x] += sh0[threadIdx.x+o]; sh1[threadIdx.x] += sh1[threadIdx.x+o]; }
        __syncthreads();
    }
    if (threadIdx.x == 0) {
        float mean = sh0[0] * (1.f/LL);
        float var  = sh1[0] * (1.f/LL) - mean*mean;
        g_mr[bc*2]   = mean;
        g_mr[bc*2+1] = rsqrtf(var + 1e-5f);
    }
}

// ---------------- in_proj: xz[b][l][j] = sum_c in[b][c][l] * W[j][c] ----------
__global__ __launch_bounds__(256) void inproj_k(const float* __restrict__ in,
                                                const float* __restrict__ ipw)
{
    __shared__ float s_w[128][66];
    __shared__ float s_x[32][64];
    int b = blockIdx.y;
    int l0 = blockIdx.x * 64;
    int tid = threadIdx.x;
    for (int idx = tid; idx < 128*64; idx += 256) s_w[idx >> 6][idx & 63] = ipw[idx];

    int lq = tid & 15;
    int jq = tid >> 4;
    float acc[4][8];
#pragma unroll
    for (int i = 0; i < 4; i++)
#pragma unroll
        for (int j = 0; j < 8; j++) acc[i][j] = 0.f;

    for (int ch = 0; ch < 2; ch++) {
        __syncthreads();
        for (int idx = tid; idx < 32*64; idx += 256) {
            int c = idx >> 6, ll = idx & 63;
            s_x[c][ll] = in[(size_t)(b*64 + ch*32 + c)*LL + l0 + ll];
        }
        __syncthreads();
        for (int c = 0; c < 32; c++) {
            float xv[4], wv[8];
#pragma unroll
            for (int i = 0; i < 4; i++) xv[i] = s_x[c][lq*4 + i];
#pragma unroll
            for (int j = 0; j < 8; j++) wv[j] = s_w[jq*8 + j][ch*32 + c];
#pragma unroll
            for (int i = 0; i < 4; i++)
#pragma unroll
                for (int j = 0; j < 8; j++) acc[i][j] += xv[i] * wv[j];
        }
    }
#pragma unroll
    for (int i = 0; i < 4; i++) {
        int l = l0 + lq*4 + i;
        float4 v0 = make_float4(acc[i][0], acc[i][1], acc[i][2], acc[i][3]);
        float4 v1 = make_float4(acc[i][4], acc[i][5], acc[i][6], acc[i][7]);
        float4* dst = (float4*)&g_xz[((size_t)b*LL + l)*128 + jq*8];
        dst[0] = v0; dst[1] = v1;
    }
}

// ---------------- per-direction prep: conv1d+silu, x_proj, dt_proj -----------
template<int DIR>
__global__ __launch_bounds__(256) void prep_k(
    const float* __restrict__ w1d_g, const float* __restrict__ b1d_g,
    const float* __restrict__ xpw_g, const float* __restrict__ dtw_g,
    const float* __restrict__ dtb_g)
{
    __shared__ float xs[67][64];
    __shared__ float xc_s[64][65];
    __shared__ float dbl_s[64][20];
    __shared__ float xpw[20][65];
    __shared__ float w1d[64][4];
    __shared__ float dtw[64][5];
    __shared__ float b1d[64], dtb[64];

    int b = blockIdx.y;
    int s0 = blockIdx.x * 64;
    int tid = threadIdx.x;

    for (int idx = tid; idx < 20*64; idx += 256) xpw[idx/64][idx%64] = xpw_g[idx];
    if (tid < 64) {
#pragma unroll
        for (int k = 0; k < 4; k++) { w1d[tid][k] = w1d_g[tid*4 + k]; dtw[tid][k] = dtw_g[tid*4 + k]; }
        b1d[tid] = b1d_g[tid];
        dtb[tid] = dtb_g[tid];
    }
    for (int idx = tid; idx < 67*64; idx += 256) {
        int sr = idx / 64, d = idx % 64;
        int s = s0 + sr - 3;
        float v = 0.f;
        if (s >= 0) {
            int l = (DIR == 0) ? s : (LL - 1 - s);
            v = g_xz[((size_t)b*LL + l)*128 + d];
        }
        xs[sr][d] = v;
    }
    __syncthreads();

    // causal depthwise conv1d (k=4) + silu
    for (int idx = tid; idx < 64*64; idx += 256) {
        int sl = idx >> 6, d = idx & 63;
        float v = b1d[d];
#pragma unroll
        for (int k = 0; k < 4; k++) v += w1d[d][k] * xs[sl + k][d];
        v = v / (1.f + __expf(-v));
        xc_s[sl][d] = v;
        g_xc[((size_t)b*LL + s0 + sl)*64 + d] = v;
    }
    __syncthreads();

    // dbl = xc @ x_proj_w.T  (20 outputs)
    for (int idx = tid; idx < 64*20; idx += 256) {
        int sl = idx / 20, j = idx % 20;
        float v = 0.f;
        for (int d = 0; d < 64; d++) v += xc_s[sl][d] * xpw[j][d];
        dbl_s[sl][j] = v;
        int s = s0 + sl;
        if (j >= 4 && j < 12)      g_Bm[((size_t)b*LL + s)*8 + (j-4)]  = v;
        else if (j >= 12)          g_Cm[((size_t)b*LL + s)*8 + (j-12)] = v;
    }
    __syncthreads();

    // dt = softplus(dt_r @ dt_proj_w.T + b)
    for (int idx = tid; idx < 64*64; idx += 256) {
        int sl = idx >> 6, dd = idx & 63;
        float t = dtb[dd];
#pragma unroll
        for (int r = 0; r < 4; r++) t += dbl_s[sl][r] * dtw[dd][r];
        float sp = (t > 20.f) ? t : log1pf(__expf(t));
        g_dt[((size_t)b*LL + s0 + sl)*64 + dd] = sp;
    }
}

// ---------------- scan pass A: per-chunk (P, Q) reduction --------------------
__global__ __launch_bounds__(512) void scanA_k(const float* __restrict__ alog)
{
    __shared__ float s_dt[32][64];
    __shared__ float s_xc[32][64];
    __shared__ float s_B[32][8];
    int b = blockIdx.y;
    int chunk = blockIdx.x;
    int tid = threadIdx.x;
    int d = tid >> 3, n = tid & 7;
    float a = -__expf(alog[d*8 + n]);
    float P = 1.f, Q = 0.f;
    int sbase = chunk * CS;
    for (int sub = 0; sub < CS/32; sub++) {
        __syncthreads();
        int st = sbase + sub*32;
        for (int idx = tid; idx < 32*64; idx += 512) {
            int sl = idx >> 6, dd = idx & 63;
            size_t g = ((size_t)b*LL + st + sl)*64 + dd;
            s_dt[sl][dd] = g_dt[g];
            s_xc[sl][dd] = g_xc[g];
        }
        if (tid < 256) {
            int sl = tid >> 3, nn = tid & 7;
            s_B[sl][nn] = g_Bm[((size_t)b*LL + st + sl)*8 + nn];
        }
        __syncthreads();
#pragma unroll 8
        for (int sl = 0; sl < 32; sl++) {
            float dtv = s_dt[sl][d];
            float ex = __expf(dtv * a);
            float u = dtv * s_xc[sl][d] * s_B[sl][n];
            P *= ex;
            Q = ex*Q + u;
        }
    }
    size_t o = (((size_t)b*NCK + chunk)*64 + d)*8 + n;
    g_P[o] = P; g_Q[o] = Q;
}

// ---------------- scan pass B: sequential carry across chunks ----------------
__global__ __launch_bounds__(512) void scanB_k()
{
    int idx = blockIdx.x*512 + threadIdx.x;  // 0..1023 = (b, d, n)
    int b = idx >> 9;
    int dn = idx & 511;
    float h = 0.f;
    for (int j = 0; j < NCK; j++) {
        size_t o = ((size_t)(b*NCK + j))*512 + dn;
        g_cin[o] = h;
        h = g_P[o]*h + g_Q[o];
    }
}

// ---------------- scan pass C: replay with carry, y epilogue -----------------
template<int DIR>
__global__ __launch_bounds__(512) void scanC_k(const float* __restrict__ alog,
                                               const float* __restrict__ Dsk)
{
    __shared__ float s_dt[32][64];
    __shared__ float s_xc[32][64];
    __shared__ float s_B[32][8];
    __shared__ float s_C[32][8];
    __shared__ float s_y[32][64];
    int b = blockIdx.y;
    int chunk = blockIdx.x;
    int tid = threadIdx.x;
    int d = tid >> 3, n = tid & 7;
    float a = -__expf(alog[d*8 + n]);
    float Dv = Dsk[d];
    float h = g_cin[(((size_t)b*NCK + chunk)*64 + d)*8 + n];
    int sbase = chunk * CS;

    for (int sub = 0; sub < CS/32; sub++) {
        int st = sbase + sub*32;
        __syncthreads();
        for (int idx = tid; idx < 32*64; idx += 512) {
            int sl = idx >> 6, dd = idx & 63;
            size_t g = ((size_t)b*LL + st + sl)*64 + dd;
            s_dt[sl][dd] = g_dt[g];
            s_xc[sl][dd] = g_xc[g];
        }
        if (tid < 256) {
            int sl = tid >> 3, nn = tid & 7;
            size_t g = ((size_t)b*LL + st + sl)*8 + nn;
            s_B[sl][nn] = g_Bm[g];
            s_C[sl][nn] = g_Cm[g];
        }
        __syncthreads();
        for (int sl = 0; sl < 32; sl++) {
            float dtv = s_dt[sl][d];
            float xcv = s_xc[sl][d];
            float ex = __expf(dtv * a);
            h = ex*h + dtv * xcv * s_B[sl][n];
            float part = h * s_C[sl][n];
            part += __shfl_xor_sync(0xffffffffu, part, 1);
            part += __shfl_xor_sync(0xffffffffu, part, 2);
            part += __shfl_xor_sync(0xffffffffu, part, 4);
            if (n == 0) s_y[sl][d] = part + xcv * Dv;
        }
        __syncthreads();
        // multiply silu(z) and store at ORIGINAL l
        for (int idx = tid; idx < 32*64; idx += 512) {
            int sl = idx >> 6, dd = idx & 63;
            int s = st + sl;
            int l = (DIR == 0) ? s : (LL - 1 - s);
            float z = g_xz[((size_t)b*LL + l)*128 + 64 + dd];
            float sil = z / (1.f + __expf(-z));
            float val = s_y[sl][dd] * sil;
            size_t o = ((size_t)b*LL + l)*64 + dd;
            if (DIR == 0) g_y[o] = val;
            else          g_y[o] += val;
        }
    }
}

// ---------------- out_proj (×0.5) + LayerNorm, write volume layout -----------
__global__ __launch_bounds__(256) void outln_k(const float* __restrict__ opw,
                                               const float* __restrict__ lng,
                                               const float* __restrict__ lnb)
{
    __shared__ float s_y[64][65];   // reused as r_s after GEMM
    __shared__ float s_w[64][65];
    __shared__ float mu_s[64], rs_s[64];
    int b = blockIdx.y;
    int l0 = blockIdx.x * 64;
    int tid = threadIdx.x;
    for (int idx = tid; idx < 64*64; idx += 256) s_w[idx >> 6][idx & 63] = opw[idx];
    for (int idx = tid; idx < 64*64; idx += 256) {
        int ll = idx >> 6, dd = idx & 63;
        s_y[ll][dd] = g_y[((size_t)b*LL + l0 + ll)*64 + dd];
    }
    __syncthreads();

    int lq = tid & 15, cq = tid >> 4;
    float acc[4][4];
#pragma unroll
    for (int i = 0; i < 4; i++)
#pragma unroll
        for (int j = 0; j < 4; j++) acc[i][j] = 0.f;
    for (int dd = 0; dd < 64; dd++) {
        float yv[4], wv[4];
#pragma unroll
        for (int i = 0; i < 4; i++) yv[i] = s_y[lq*4 + i][dd];
#pragma unroll
        for (int j = 0; j < 4; j++) wv[j] = s_w[cq*4 + j][dd];
#pragma unroll
        for (int i = 0; i < 4; i++)
#pragma unroll
            for (int j = 0; j < 4; j++) acc[i][j] += yv[i] * wv[j];
    }
    __syncthreads();
#pragma unroll
    for (int i = 0; i < 4; i++)
#pragma unroll
        for (int j = 0; j < 4; j++)
            s_y[lq*4 + i][cq*4 + j] = 0.5f * acc[i][j];
    __syncthreads();
    if (tid < 64) {
        float s = 0.f, sq = 0.f;
        for (int c = 0; c < 64; c++) { float v = s_y[tid][c]; s += v; sq += v*v; }
        float mu = s * (1.f/64.f);
        float var = sq * (1.f/64.f) - mu*mu;
        mu_s[tid] = mu; rs_s[tid] = rsqrtf(var + 1e-5f);
    }
    __syncthreads();
    for (int idx = tid; idx < 64*64; idx += 256) {
        int c = idx >> 6, ll = idx & 63;
        float v = (s_y[ll][c] - mu_s[ll]) * rs_s[ll] * lng[c] + lnb[c];
        g_vol2[(size_t)(b*64 + c)*LL + l0 + ll] = v;
    }
}

// ------------------------------- launcher ------------------------------------
extern "C" void kernel_launch(void* const* d_in, const int* in_sizes, int n_in,
                              void* d_out, int out_size)
{
    (void)in_sizes; (void)n_in; (void)out_size;
    const float* input     = (const float*)d_in[0];
    const float* conv_w    = (const float*)d_in[1];
    const float* conv_b    = (const float*)d_in[2];
    const float* in_proj_w = (const float*)d_in[3];
    const float* conv1d_w  = (const float*)d_in[4];
    const float* conv1d_b  = (const float*)d_in[5];
    const float* x_proj_w  = (const float*)d_in[6];
    const float* dt_proj_w = (const float*)d_in[7];
    const float* dt_proj_b = (const float*)d_in[8];
    const float* A_log     = (const float*)d_in[9];
    const float* A_b_log   = (const float*)d_in[10];
    const float* D_skip    = (const float*)d_in[11];
    const float* out_proj_w= (const float*)d_in[12];
    const float* ln_g      = (const float*)d_in[13];
    const float* ln_b      = (const float*)d_in[14];
    float* out = (float*)d_out;

    // one-time weight split (shared by both convs)
    wsplit_k<<<512, 256>>>(conv_w);

    // token projection + fwd prep first (independent of conv), so that conv #1
    // lands in the ncu-profiled launch slot.
    inproj_k<<<dim3(512, 2), 256>>>(input, in_proj_w);
    prep_k<0><<<dim3(512, 2), 256>>>(conv1d_w, conv1d_b, x_proj_w, dt_proj_w, dt_proj_b);

    // conv #1 + instance-norm stats (skip branch deferred to final conv)
    conv3d_m<true><<<512, 256>>>(input, conv_b, nullptr);
    stats_k<<<128, 256>>>();

    // forward direction scans
    scanA_k<<<dim3(NCK, 2), 512>>>(A_log);
    scanB_k<<<2, 512>>>();
    scanC_k<0><<<dim3(NCK, 2), 512>>>(A_log, D_skip);

    // backward direction (reuses the same scratch buffers)
    prep_k<1><<<dim3(512, 2), 256>>>(conv1d_w, conv1d_b, x_proj_w, dt_proj_w, dt_proj_b);
    scanA_k<<<dim3(NCK, 2), 512>>>(A_b_log);
    scanB_k<<<2, 512>>>();
    scanC_k<1><<<dim3(NCK, 2), 512>>>(A_b_log, D_skip);

    // out_proj + layernorm into volume layout
    outln_k<<<dim3(512, 2), 256>>>(out_proj_w, ln_g, ln_b);

    // conv #2 + residual skip; input g_vol2 is read from DEVICE code
    conv3d_m<false><<<512, 256>>>(nullptr, conv_b, out);
}

// round 12
// speedup vs baseline: 2.7534x; 1.1879x over previous
#include <cuda_runtime.h>
#include <math.h>
#include <stdint.h>

#define BB 2
#define CC 64
#define LL 32768      // 32*32*32 spatial = token count
#define DI 64
#define DS 8
#define CS 256        // scan chunk length
#define NCK 128       // number of chunks = LL/CS

// ---------------- scratch (static device globals; no allocation) -------------
__device__ float g_tmp1[BB*CC*LL];     // conv1 output
__device__ float g_mr[BB*CC*2];        // per (b,c) mean / rstd
__device__ float g_xz[(size_t)BB*LL*128]; // in_proj output, [b][l][128]
__device__ float g_xc[(size_t)BB*LL*DI];  // per-direction (reused)
__device__ float g_dt[(size_t)BB*LL*DI];
__device__ float g_Bm[(size_t)BB*LL*DS];
__device__ float g_Cm[(size_t)BB*LL*DS];
__device__ float g_P[BB*NCK*DI*DS];
__device__ float g_Q[BB*NCK*DI*DS];
__device__ float g_cin[BB*NCK*DI*DS];
__device__ float g_y[(size_t)BB*LL*DI];   // y_f*silu(z) + y_b*silu(z) at original l
__device__ float g_vol2[BB*CC*LL];        // LN output in volume layout (input of conv2)
__device__ float g_wBh[64*2048];   // weights [ci][k32][co64], tf32-rounded hi
__device__ float g_wBl[64*2048];   // f32 lo residual

// ---------------- one-time weight split: [co][ci][27] -> [ci][k32][co] -------
__global__ __launch_bounds__(256) void wsplit_k(const float* __restrict__ cw)
{
    int idx = blockIdx.x*256 + threadIdx.x;   // 64ci * 32k * 64co = 131072
    if (idx >= 64*32*64) return;
    int ci = idx >> 11;
    int k  = (idx >> 6) & 31;
    int co = idx & 63;
    float w = (k < 27) ? cw[(co*64 + ci)*27 + k] : 0.f;
    uint32_t hb; asm("cvt.rna.tf32.f32 %0, %1;" : "=r"(hb) : "f"(w));
    float hi = __uint_as_float(hb);
    g_wBh[idx] = hi;
    g_wBl[idx] = w - hi;
}

// ---------------- mma.sync m16n8k8 tf32 helper (sm_80+ baseline PTX) ---------
__device__ __forceinline__ void mma8(float* c, const uint32_t* a, const uint32_t* b)
{
    asm volatile("mma.sync.aligned.m16n8k8.row.col.f32.tf32.tf32.f32 "
        "{%0,%1,%2,%3}, {%4,%5,%6,%7}, {%8,%9}, {%0,%1,%2,%3};"
        : "+f"(c[0]), "+f"(c[1]), "+f"(c[2]), "+f"(c[3])
        : "r"(a[0]), "r"(a[1]), "r"(a[2]), "r"(a[3]), "r"(b[0]), "r"(b[1]));
}

// ---------------- cp.async helpers (sm_80+ baseline PTX) ---------------------
__device__ __forceinline__ uint32_t s2u32(const void* p) {
    uint32_t a;
    asm("{ .reg .u64 t; cvta.to.shared.u64 t, %1; cvt.u32.u64 %0, t; }" : "=r"(a) : "l"(p));
    return a;
}
__device__ __forceinline__ void cpa4(uint32_t dst, const float* src, int srcsz) {
    asm volatile("cp.async.ca.shared.global [%0], [%1], 4, %2;"
        :: "r"(dst), "l"(src), "r"(srcsz) : "memory");
}
__device__ __forceinline__ void cpa16(uint32_t dst, const float4* src) {
    asm volatile("cp.async.cg.shared.global [%0], [%1], 16;"
        :: "r"(dst), "l"(src) : "memory");
}
#define CP_COMMIT() asm volatile("cp.async.commit_group;" ::: "memory")
#define CP_WAIT1()  asm volatile("cp.async.wait_group 1;" ::: "memory")
#define CP_WAIT0()  asm volatile("cp.async.wait_group 0;" ::: "memory")

// ---------------- conv3d (3x3x3, pad 1, 64->64) via split-tf32 mma.sync ------
// Block = (b, h, j): 128 pos (4 w × 32 d) × 64 co. 8 warps: warp (wm, wn)
// owns pos [wm*32, +32) × co [wn*32, +32) as 2 m-tiles × 4 n-tiles of m16n8k8.
// K = 64 ci × 32 taps (27 real). 2-term split: D = Ah·Bh + Ah·Bl — A single
// tf32 (error ~2^-12 rel, ~1e-4 on output), B exactly split offline.
// Staging is cp.async double-buffered: prefetch ci+1 while computing ci.
// Patch SMEM layout is 36-stride rows; cp.async dsts MUST use row*36+col.
template<bool FIRST>
__global__ __launch_bounds__(256, 3) void conv3d_m(
    const float* __restrict__ in, const float* __restrict__ cb,
    float* __restrict__ outp)
{
    __shared__ __align__(16) float sP[2][648];       // raw patch [3h*6w][36]
    __shared__ __align__(16) float sBh[2][32*72];    // [k][co] pad 72
    __shared__ __align__(16) float sBl[2][32*72];

    int tid  = threadIdx.x;
    int lane = tid & 31;
    int warp = tid >> 5;
    int wm = warp & 3;               // pos group (also wl, since pos = wl*32+d)
    int wn = warp >> 2;              // co group
    int bid = blockIdx.x;            // 512 = b(2) × h(32) × j(8)
    int b = bid >> 8;
    int h = (bid >> 3) & 31;
    int j = bid & 7;

    const float* src  = FIRST ? in : (const float*)g_vol2;
    const float* srcb = src + (size_t)b * 64 * LL;

    int r = lane & 3;                // threadID_in_group
    int q = lane >> 2;               // groupID

    // ---- precomputed per-thread staging descriptors ----
    // patch: 612 logical elements (18 rows × 34 cols), stored at row*36+col.
    int   pOff[3]; int pSz[3]; uint32_t pDst0[3], pDst1[3];
    int nP = (tid < 100) ? 3 : 2;
#pragma unroll
    for (int e = 0; e < 3; e++) {
        int idx = tid + e*256;
        if (idx < 612) {
            int row = idx / 34, col = idx - row*34;
            int kh = row / 6, iww = row - kh*6;
            int ih = h + kh - 1;
            int iw = j*4 + iww - 1;
            int id = col - 1;
            bool ok = (unsigned)ih < 32u && (unsigned)iw < 32u && (unsigned)id < 32u;
            pOff[e] = ok ? (ih*1024 + iw*32 + id) : 0;
            pSz[e]  = ok ? 4 : 0;
            pDst0[e] = s2u32(&sP[0][row*36 + col]);   // 36-stride (matches koff)
            pDst1[e] = s2u32(&sP[1][row*36 + col]);
        }
    }
    // B: 512 16B-chunks per (h|l); thread handles c = tid, tid+256
    uint32_t bDst0[2][2], bDst1[2][2];   // [t][h/l]
    int bSrcOff[2];
#pragma unroll
    for (int t = 0; t < 2; t++) {
        int c = tid + t*256;
        int k = c >> 4, cc = c & 15;
        bSrcOff[t] = c*4;                              // float offset in dense 2048
        bDst0[t][0] = s2u32(&sBh[0][k*72 + cc*4]);
        bDst1[t][0] = s2u32(&sBh[1][k*72 + cc*4]);
        bDst0[t][1] = s2u32(&sBl[0][k*72 + cc*4]);
        bDst1[t][1] = s2u32(&sBl[1][k*72 + cc*4]);
    }

    // Per-thread patch offsets for the 8 k columns this lane touches
    int koff[4][2];
#pragma unroll
    for (int ks = 0; ks < 4; ks++)
#pragma unroll
        for (int hf = 0; hf < 2; hf++) {
            int k = ks*8 + r + hf*4;
            if (k < 27) {
                int kh = k/9, kw = (k%9)/3, kd = k%3;
                koff[ks][hf] = (kh*6 + kw + wm)*36 + kd;
            } else koff[ks][hf] = -1;
        }

    float acc[2][4][4];
#pragma unroll
    for (int mt = 0; mt < 2; mt++)
#pragma unroll
        for (int nt = 0; nt < 4; nt++)
#pragma unroll
            for (int e = 0; e < 4; e++) acc[mt][nt][e] = 0.f;

    // ---- prefetch ci = 0 into buffer 0 ----
    {
        const float* sc = srcb;                       // ci = 0
        for (int e = 0; e < nP; e++) cpa4(pDst0[e], sc + pOff[e], pSz[e]);
#pragma unroll
        for (int t = 0; t < 2; t++) {
            cpa16(bDst0[t][0], (const float4*)(g_wBh + bSrcOff[t]));
            cpa16(bDst0[t][1], (const float4*)(g_wBl + bSrcOff[t]));
        }
        CP_COMMIT();
    }

    for (int ci = 0; ci < 64; ci++) {
        int cur = ci & 1;
        if (ci < 63) {
            // prefetch ci+1 into the other buffer
            const float* sc = srcb + (size_t)(ci+1) * LL;
            int bo = (ci+1) * 2048;
            if (cur == 0) {
                for (int e = 0; e < nP; e++) cpa4(pDst1[e], sc + pOff[e], pSz[e]);
#pragma unroll
                for (int t = 0; t < 2; t++) {
                    cpa16(bDst1[t][0], (const float4*)(g_wBh + bo + bSrcOff[t]));
                    cpa16(bDst1[t][1], (const float4*)(g_wBl + bo + bSrcOff[t]));
                }
            } else {
                for (int e = 0; e < nP; e++) cpa4(pDst0[e], sc + pOff[e], pSz[e]);
#pragma unroll
                for (int t = 0; t < 2; t++) {
                    cpa16(bDst0[t][0], (const float4*)(g_wBh + bo + bSrcOff[t]));
                    cpa16(bDst0[t][1], (const float4*)(g_wBl + bo + bSrcOff[t]));
                }
            }
            CP_COMMIT();
            CP_WAIT1();           // current buffer's group complete
        } else {
            CP_WAIT0();
        }
        __syncthreads();          // all threads' copies visible

        const float* sPc  = sP[cur];
        const float* sBhc = sBh[cur];
        const float* sBlc = sBl[cur];

#pragma unroll
        for (int ks = 0; ks < 4; ks++) {
            // A fragments (pos × k), single tf32
            uint32_t ah[2][4];
#pragma unroll
            for (int mt = 0; mt < 2; mt++) {
                int dA = mt*16 + q;
#pragma unroll
                for (int e = 0; e < 4; e++) {
                    int hf = e >> 1;
                    int dd = dA + ((e & 1) ? 8 : 0);
                    int off = koff[ks][hf];
                    float v = (off >= 0) ? sPc[off + dd] : 0.f;
                    uint32_t hb; asm("cvt.rna.tf32.f32 %0, %1;" : "=r"(hb) : "f"(v));
                    ah[mt][e] = hb;
                }
            }
            // B fragments (k × co) — conflict-free (pad 72)
            uint32_t bhf[4][2], blf[4][2];
            int k0 = ks*8 + r;
#pragma unroll
            for (int nt = 0; nt < 4; nt++) {
                int co = wn*32 + nt*8 + q;
                bhf[nt][0] = __float_as_uint(sBhc[k0*72 + co]);
                bhf[nt][1] = __float_as_uint(sBhc[(k0+4)*72 + co]);
                blf[nt][0] = __float_as_uint(sBlc[k0*72 + co]);
                blf[nt][1] = __float_as_uint(sBlc[(k0+4)*72 + co]);
            }
#pragma unroll
            for (int mt = 0; mt < 2; mt++)
#pragma unroll
                for (int nt = 0; nt < 4; nt++) {
                    mma8(acc[mt][nt], ah[mt], bhf[nt]);
                    mma8(acc[mt][nt], ah[mt], blf[nt]);
                }
        }
        __syncthreads();          // done reading cur before it is overwritten
    }

    // epilogue: c0:(q,2r) c1:(q,2r+1) c2:(q+8,2r) c3:(q+8,2r+1)
    int w = j*4 + wm;
#pragma unroll
    for (int mt = 0; mt < 2; mt++)
#pragma unroll
        for (int nt = 0; nt < 4; nt++)
#pragma unroll
            for (int e = 0; e < 4; e++) {
                int dd = mt*16 + q + ((e >= 2) ? 8 : 0);
                int co = wn*32 + nt*8 + 2*r + (e & 1);
                size_t gidx = (size_t)(b*64 + co)*LL + h*1024 + w*32 + dd;
                float v = acc[mt][nt][e] + cb[co];
                if (FIRST) {
                    g_tmp1[gidx] = v;
                } else {
                    float mean = g_mr[(b*64 + co)*2];
                    float rstd = g_mr[(b*64 + co)*2 + 1];
                    float s = (g_tmp1[gidx] - mean) * rstd;
                    outp[gidx] = v + (s > 0.f ? s : 0.f);
                }
            }
}

// ---------------- instance-norm stats (deterministic) ------------------------
__global__ __launch_bounds__(256) void stats_k()
{
    int bc = blockIdx.x;  // 0..127
    const float* p = g_tmp1 + (size_t)bc * LL;
    float s = 0.f, sq = 0.f;
    for (int i = threadIdx.x; i < LL; i += 256) { float v = p[i]; s += v; sq += v*v; }
    __shared__ float sh0[256], sh1[256];
    sh0[threadIdx.x] = s; sh1[threadIdx.x] = sq;
    __syncthreads();
    for (int o = 128; o > 0; o >>= 1) {
        if (threadIdx.x < o) { sh0[threadIdx.x] += sh0[threadIdx.x+o]; sh1[threadIdx.x] += sh1[threadIdx.x+o]; }
        __syncthreads();
    }
    if (threadIdx.x == 0) {
        float mean = sh0[0] * (1.f/LL);
        float var  = sh1[0] * (1.f/LL) - mean*mean;
        g_mr[bc*2]   = mean;
        g_mr[bc*2+1] = rsqrtf(var + 1e-5f);
    }
}

// ---------------- in_proj: xz[b][l][j] = sum_c in[b][c][l] * W[j][c] ----------
__global__ __launch_bounds__(256) void inproj_k(const float* __restrict__ in,
                                                const float* __restrict__ ipw)
{
    __shared__ float s_w[128][66];
    __shared__ float s_x[32][64];
    int b = blockIdx.y;
    int l0 = blockIdx.x * 64;
    int tid = threadIdx.x;
    for (int idx = tid; idx < 128*64; idx += 256) s_w[idx >> 6][idx & 63] = ipw[idx];

    int lq = tid & 15;
    int jq = tid >> 4;
    float acc[4][8];
#pragma unroll
    for (int i = 0; i < 4; i++)
#pragma unroll
        for (int j = 0; j < 8; j++) acc[i][j] = 0.f;

    for (int ch = 0; ch < 2; ch++) {
        __syncthreads();
        for (int idx = tid; idx < 32*64; idx += 256) {
            int c = idx >> 6, ll = idx & 63;
            s_x[c][ll] = in[(size_t)(b*64 + ch*32 + c)*LL + l0 + ll];
        }
        __syncthreads();
        for (int c = 0; c < 32; c++) {
            float xv[4], wv[8];
#pragma unroll
            for (int i = 0; i < 4; i++) xv[i] = s_x[c][lq*4 + i];
#pragma unroll
            for (int j = 0; j < 8; j++) wv[j] = s_w[jq*8 + j][ch*32 + c];
#pragma unroll
            for (int i = 0; i < 4; i++)
#pragma unroll
                for (int j = 0; j < 8; j++) acc[i][j] += xv[i] * wv[j];
        }
    }
#pragma unroll
    for (int i = 0; i < 4; i++) {
        int l = l0 + lq*4 + i;
        float4 v0 = make_float4(acc[i][0], acc[i][1], acc[i][2], acc[i][3]);
        float4 v1 = make_float4(acc[i][4], acc[i][5], acc[i][6], acc[i][7]);
        float4* dst = (float4*)&g_xz[((size_t)b*LL + l)*128 + jq*8];
        dst[0] = v0; dst[1] = v1;
    }
}

// ---------------- per-direction prep: conv1d+silu, x_proj, dt_proj -----------
template<int DIR>
__global__ __launch_bounds__(256) void prep_k(
    const float* __restrict__ w1d_g, const float* __restrict__ b1d_g,
    const float* __restrict__ xpw_g, const float* __restrict__ dtw_g,
    const float* __restrict__ dtb_g)
{
    __shared__ float xs[67][64];
    __shared__ float xc_s[64][65];
    __shared__ float dbl_s[64][20];
    __shared__ float xpw[20][65];
    __shared__ float w1d[64][4];
    __shared__ float dtw[64][5];
    __shared__ float b1d[64], dtb[64];

    int b = blockIdx.y;
    int s0 = blockIdx.x * 64;
    int tid = threadIdx.x;

    for (int idx = tid; idx < 20*64; idx += 256) xpw[idx/64][idx%64] = xpw_g[idx];
    if (tid < 64) {
#pragma unroll
        for (int k = 0; k < 4; k++) { w1d[tid][k] = w1d_g[tid*4 + k]; dtw[tid][k] = dtw_g[tid*4 + k]; }
        b1d[tid] = b1d_g[tid];
        dtb[tid] = dtb_g[tid];
    }
    for (int idx = tid; idx < 67*64; idx += 256) {
        int sr = idx / 64, d = idx % 64;
        int s = s0 + sr - 3;
        float v = 0.f;
        if (s >= 0) {
            int l = (DIR == 0) ? s : (LL - 1 - s);
            v = g_xz[((size_t)b*LL + l)*128 + d];
        }
        xs[sr][d] = v;
    }
    __syncthreads();

    // causal depthwise conv1d (k=4) + silu
    for (int idx = tid; idx < 64*64; idx += 256) {
        int sl = idx >> 6, d = idx & 63;
        float v = b1d[d];
#pragma unroll
        for (int k = 0; k < 4; k++) v += w1d[d][k] * xs[sl + k][d];
        v = v / (1.f + __expf(-v));
        xc_s[sl][d] = v;
        g_xc[((size_t)b*LL + s0 + sl)*64 + d] = v;
    }
    __syncthreads();

    // dbl = xc @ x_proj_w.T  (20 outputs)
    for (int idx = tid; idx < 64*20; idx += 256) {
        int sl = idx / 20, j = idx % 20;
        float v = 0.f;
        for (int d = 0; d < 64; d++) v += xc_s[sl][d] * xpw[j][d];
        dbl_s[sl][j] = v;
        int s = s0 + sl;
        if (j >= 4 && j < 12)      g_Bm[((size_t)b*LL + s)*8 + (j-4)]  = v;
        else if (j >= 12)          g_Cm[((size_t)b*LL + s)*8 + (j-12)] = v;
    }
    __syncthreads();

    // dt = softplus(dt_r @ dt_proj_w.T + b)
    for (int idx = tid; idx < 64*64; idx += 256) {
        int sl = idx >> 6, dd = idx & 63;
        float t = dtb[dd];
#pragma unroll
        for (int r = 0; r < 4; r++) t += dbl_s[sl][r] * dtw[dd][r];
        float sp = (t > 20.f) ? t : log1pf(__expf(t));
        g_dt[((size_t)b*LL + s0 + sl)*64 + dd] = sp;
    }
}

// ---------------- scan pass A: per-chunk (P, Q) reduction --------------------
__global__ __launch_bounds__(512) void scanA_k(const float* __restrict__ alog)
{
    __shared__ float s_dt[32][64];
    __shared__ float s_xc[32][64];
    __shared__ float s_B[32][8];
    int b = blockIdx.y;
    int chunk = blockIdx.x;
    int tid = threadIdx.x;
    int d = tid >> 3, n = tid & 7;
    float a = -__expf(alog[d*8 + n]);
    float P = 1.f, Q = 0.f;
    int sbase = chunk * CS;
    for (int sub = 0; sub < CS/32; sub++) {
        __syncthreads();
        int st = sbase + sub*32;
        for (int idx = tid; idx < 32*64; idx += 512) {
            int sl = idx >> 6, dd = idx & 63;
            size_t g = ((size_t)b*LL + st + sl)*64 + dd;
            s_dt[sl][dd] = g_dt[g];
            s_xc[sl][dd] = g_xc[g];
        }
        if (tid < 256) {
            int sl = tid >> 3, nn = tid & 7;
            s_B[sl][nn] = g_Bm[((size_t)b*LL + st + sl)*8 + nn];
        }
        __syncthreads();
#pragma unroll 8
        for (int sl = 0; sl < 32; sl++) {
            float dtv = s_dt[sl][d];
            float ex = __expf(dtv * a);
            float u = dtv * s_xc[sl][d] * s_B[sl][n];
            P *= ex;
            Q = ex*Q + u;
        }
    }
    size_t o = (((size_t)b*NCK + chunk)*64 + d)*8 + n;
    g_P[o] = P; g_Q[o] = Q;
}

// ---------------- scan pass B: sequential carry across chunks ----------------
__global__ __launch_bounds__(512) void scanB_k()
{
    int idx = blockIdx.x*512 + threadIdx.x;  // 0..1023 = (b, d, n)
    int b = idx >> 9;
    int dn = idx & 511;
    float h = 0.f;
    for (int j = 0; j < NCK; j++) {
        size_t o = ((size_t)(b*NCK + j))*512 + dn;
        g_cin[o] = h;
        h = g_P[o]*h + g_Q[o];
    }
}

// ---------------- scan pass C: replay with carry, y epilogue -----------------
template<int DIR>
__global__ __launch_bounds__(512) void scanC_k(const float* __restrict__ alog,
                                               const float* __restrict__ Dsk)
{
    __shared__ float s_dt[32][64];
    __shared__ float s_xc[32][64];
    __shared__ float s_B[32][8];
    __shared__ float s_C[32][8];
    __shared__ float s_y[32][64];
    int b = blockIdx.y;
    int chunk = blockIdx.x;
    int tid = threadIdx.x;
    int d = tid >> 3, n = tid & 7;
    float a = -__expf(alog[d*8 + n]);
    float Dv = Dsk[d];
    float h = g_cin[(((size_t)b*NCK + chunk)*64 + d)*8 + n];
    int sbase = chunk * CS;

    for (int sub = 0; sub < CS/32; sub++) {
        int st = sbase + sub*32;
        __syncthreads();
        for (int idx = tid; idx < 32*64; idx += 512) {
            int sl = idx >> 6, dd = idx & 63;
            size_t g = ((size_t)b*LL + st + sl)*64 + dd;
            s_dt[sl][dd] = g_dt[g];
            s_xc[sl][dd] = g_xc[g];
        }
        if (tid < 256) {
            int sl = tid >> 3, nn = tid & 7;
            size_t g = ((size_t)b*LL + st + sl)*8 + nn;
            s_B[sl][nn] = g_Bm[g];
            s_C[sl][nn] = g_Cm[g];
        }
        __syncthreads();
        for (int sl = 0; sl < 32; sl++) {
            float dtv = s_dt[sl][d];
            float xcv = s_xc[sl][d];
            float ex = __expf(dtv * a);
            h = ex*h + dtv * xcv * s_B[sl][n];
            float part = h * s_C[sl][n];
            part += __shfl_xor_sync(0xffffffffu, part, 1);
            part += __shfl_xor_sync(0xffffffffu, part, 2);
            part += __shfl_xor_sync(0xffffffffu, part, 4);
            if (n == 0) s_y[sl][d] = part + xcv * Dv;
        }
        __syncthreads();
        // multiply silu(z) and store at ORIGINAL l
        for (int idx = tid; idx < 32*64; idx += 512) {
            int sl = idx >> 6, dd = idx & 63;
            int s = st + sl;
            int l = (DIR == 0) ? s : (LL - 1 - s);
            float z = g_xz[((size_t)b*LL + l)*128 + 64 + dd];
            float sil = z / (1.f + __expf(-z));
            float val = s_y[sl][dd] * sil;
            size_t o = ((size_t)b*LL + l)*64 + dd;
            if (DIR == 0) g_y[o] = val;
            else          g_y[o] += val;
        }
    }
}

// ---------------- out_proj (×0.5) + LayerNorm, write volume layout -----------
__global__ __launch_bounds__(256) void outln_k(const float* __restrict__ opw,
                                               const float* __restrict__ lng,
                                               const float* __restrict__ lnb)
{
    __shared__ float s_y[64][65];   // reused as r_s after GEMM
    __shared__ float s_w[64][65];
    __shared__ float mu_s[64], rs_s[64];
    int b = blockIdx.y;
    int l0 = blockIdx.x * 64;
    int tid = threadIdx.x;
    for (int idx = tid; idx < 64*64; idx += 256) s_w[idx >> 6][idx & 63] = opw[idx];
    for (int idx = tid; idx < 64*64; idx += 256) {
        int ll = idx >> 6, dd = idx & 63;
        s_y[ll][dd] = g_y[((size_t)b*LL + l0 + ll)*64 + dd];
    }
    __syncthreads();

    int lq = tid & 15, cq = tid >> 4;
    float acc[4][4];
#pragma unroll
    for (int i = 0; i < 4; i++)
#pragma unroll
        for (int j = 0; j < 4; j++) acc[i][j] = 0.f;
    for (int dd = 0; dd < 64; dd++) {
        float yv[4], wv[4];
#pragma unroll
        for (int i = 0; i < 4; i++) yv[i] = s_y[lq*4 + i][dd];
#pragma unroll
        for (int j = 0; j < 4; j++) wv[j] = s_w[cq*4 + j][dd];
#pragma unroll
        for (int i = 0; i < 4; i++)
#pragma unroll
            for (int j = 0; j < 4; j++) acc[i][j] += yv[i] * wv[j];
    }
    __syncthreads();
#pragma unroll
    for (int i = 0; i < 4; i++)
#pragma unroll
        for (int j = 0; j < 4; j++)
            s_y[lq*4 + i][cq*4 + j] = 0.5f * acc[i][j];
    __syncthreads();
    if (tid < 64) {
        float s = 0.f, sq = 0.f;
        for (int c = 0; c < 64; c++) { float v = s_y[tid][c]; s += v; sq += v*v; }
        float mu = s * (1.f/64.f);
        float var = sq * (1.f/64.f) - mu*mu;
        mu_s[tid] = mu; rs_s[tid] = rsqrtf(var + 1e-5f);
    }
    __syncthreads();
    for (int idx = tid; idx < 64*64; idx += 256) {
        int c = idx >> 6, ll = idx & 63;
        float v = (s_y[ll][c] - mu_s[ll]) * rs_s[ll] * lng[c] + lnb[c];
        g_vol2[(size_t)(b*64 + c)*LL + l0 + ll] = v;
    }
}

// ------------------------------- launcher ------------------------------------
extern "C" void kernel_launch(void* const* d_in, const int* in_sizes, int n_in,
                              void* d_out, int out_size)
{
    (void)in_sizes; (void)n_in; (void)out_size;
    const float* input     = (const float*)d_in[0];
    const float* conv_w    = (const float*)d_in[1];
    const float* conv_b    = (const float*)d_in[2];
    const float* in_proj_w = (const float*)d_in[3];
    const float* conv1d_w  = (const float*)d_in[4];
    const float* conv1d_b  = (const float*)d_in[5];
    const float* x_proj_w  = (const float*)d_in[6];
    const float* dt_proj_w = (const float*)d_in[7];
    const float* dt_proj_b = (const float*)d_in[8];
    const float* A_log     = (const float*)d_in[9];
    const float* A_b_log   = (const float*)d_in[10];
    const float* D_skip    = (const float*)d_in[11];
    const float* out_proj_w= (const float*)d_in[12];
    const float* ln_g      = (const float*)d_in[13];
    const float* ln_b      = (const float*)d_in[14];
    float* out = (float*)d_out;

    // one-time weight split (shared by both convs)
    wsplit_k<<<512, 256>>>(conv_w);

    // token projection + fwd prep first (independent of conv), so that conv #1
    // lands in the ncu-profiled launch slot.
    inproj_k<<<dim3(512, 2), 256>>>(input, in_proj_w);
    prep_k<0><<<dim3(512, 2), 256>>>(conv1d_w, conv1d_b, x_proj_w, dt_proj_w, dt_proj_b);

    // conv #1 + instance-norm stats (skip branch deferred to final conv)
    conv3d_m<true><<<512, 256>>>(input, conv_b, nullptr);
    stats_k<<<128, 256>>>();

    // forward direction scans
    scanA_k<<<dim3(NCK, 2), 512>>>(A_log);
    scanB_k<<<2, 512>>>();
    scanC_k<0><<<dim3(NCK, 2), 512>>>(A_log, D_skip);

    // backward direction (reuses the same scratch buffers)
    prep_k<1><<<dim3(512, 2), 256>>>(conv1d_w, conv1d_b, x_proj_w, dt_proj_w, dt_proj_b);
    scanA_k<<<dim3(NCK, 2), 512>>>(A_b_log);
    scanB_k<<<2, 512>>>();
    scanC_k<1><<<dim3(NCK, 2), 512>>>(A_b_log, D_skip);

    // out_proj + layernorm into volume layout
    outln_k<<<dim3(512, 2), 256>>>(out_proj_w, ln_g, ln_b);

    // conv #2 + residual skip; input g_vol2 is read from DEVICE code
    conv3d_m<false><<<512, 256>>>(nullptr, conv_b, out);
}

// round 13
// speedup vs baseline: 3.6196x; 1.3146x over previous
#include <cuda_runtime.h>
#include <math.h>
#include <stdint.h>

#define BB 2
#define CC 64
#define LL 32768      // 32*32*32 spatial = token count
#define DI 64
#define DS 8
#define CS 256        // scan chunk length
#define NCK 128       // number of chunks = LL/CS

// per-direction buffer strides
#define XZSTR ((size_t)BB*LL*128)
#define XCSTR ((size_t)BB*LL*DI)      // g_xc/g_dt/g_y per-dir stride
#define BMSTR ((size_t)BB*LL*DS)
#define PQSTR ((size_t)BB*NCK*DI*DS)  // = BB*NCK*512

// ---------------- scratch (static device globals; no allocation) -------------
__device__ float g_tmp1[BB*CC*LL];     // conv1 output
__device__ float g_mr[BB*CC*2];        // per (b,c) mean / rstd
__device__ float g_xz[XZSTR];          // in_proj output, [b][l][128]
__device__ float g_xc[2*XCSTR];        // [dir][b][l][d]
__device__ float g_dt[2*XCSTR];
__device__ float g_Bm[2*BMSTR];
__device__ float g_Cm[2*BMSTR];
__device__ float g_P[2*PQSTR];
__device__ float g_Q[2*PQSTR];
__device__ float g_cin[2*PQSTR];
__device__ float g_y[2*XCSTR];         // [dir][b][l][d] at ORIGINAL l
__device__ float g_vol2[BB*CC*LL];     // LN output in volume layout (input of conv2)
__device__ float g_wBh[64*2048];       // weights [ci][k32][co64], tf32-rna

// ---------------- one-time weight prep: [co][ci][27] -> [ci][k32][co] --------
__global__ __launch_bounds__(256) void wsplit_k(const float* __restrict__ cw)
{
    int idx = blockIdx.x*256 + threadIdx.x;   // 64ci * 32k * 64co = 131072
    if (idx >= 64*32*64) return;
    int ci = idx >> 11;
    int k  = (idx >> 6) & 31;
    int co = idx & 63;
    float w = (k < 27) ? cw[(co*64 + ci)*27 + k] : 0.f;
    uint32_t hb; asm("cvt.rna.tf32.f32 %0, %1;" : "=r"(hb) : "f"(w));
    g_wBh[idx] = __uint_as_float(hb);
}

// ---------------- mma.sync m16n8k8 tf32 helper (sm_80+ baseline PTX) ---------
__device__ __forceinline__ void mma8(float* c, const uint32_t* a, const uint32_t* b)
{
    asm volatile("mma.sync.aligned.m16n8k8.row.col.f32.tf32.tf32.f32 "
        "{%0,%1,%2,%3}, {%4,%5,%6,%7}, {%8,%9}, {%0,%1,%2,%3};"
        : "+f"(c[0]), "+f"(c[1]), "+f"(c[2]), "+f"(c[3])
        : "r"(a[0]), "r"(a[1]), "r"(a[2]), "r"(a[3]), "r"(b[0]), "r"(b[1]));
}

// ---------------- cp.async helpers (sm_80+ baseline PTX) ---------------------
__device__ __forceinline__ uint32_t s2u32(const void* p) {
    uint32_t a;
    asm("{ .reg .u64 t; cvta.to.shared.u64 t, %1; cvt.u32.u64 %0, t; }" : "=r"(a) : "l"(p));
    return a;
}
__device__ __forceinline__ void cpa4(uint32_t dst, const float* src, int srcsz) {
    asm volatile("cp.async.ca.shared.global [%0], [%1], 4, %2;"
        :: "r"(dst), "l"(src), "r"(srcsz) : "memory");
}
__device__ __forceinline__ void cpa16(uint32_t dst, const float4* src) {
    asm volatile("cp.async.cg.shared.global [%0], [%1], 16;"
        :: "r"(dst), "l"(src) : "memory");
}
#define CP_COMMIT() asm volatile("cp.async.commit_group;" ::: "memory")
#define CP_WAIT1()  asm volatile("cp.async.wait_group 1;" ::: "memory")
#define CP_WAIT0()  asm volatile("cp.async.wait_group 0;" ::: "memory")

// ---------------- conv3d (3x3x3, pad 1, 64->64) via tf32 mma.sync ------------
// Block = (b, h, j): 128 pos (4 w × 32 d) × 64 co. 8 warps: warp (wm, wn)
// owns pos [wm*32, +32) × co [wn*32, +32) as 2 m-tiles × 4 n-tiles of m16n8k8.
// K = 64 ci × 32 taps (27 real). Single-tf32 A and B (both rna-rounded);
// measured error budget ~3e-4 vs 1e-3 threshold.
// cp.async double-buffered staging; patch SMEM rows are 36-stride.
template<bool FIRST>
__global__ __launch_bounds__(256, 3) void conv3d_m(
    const float* __restrict__ in, const float* __restrict__ cb,
    float* __restrict__ outp)
{
    __shared__ __align__(16) float sP[2][648];       // raw patch [3h*6w][36]
    __shared__ __align__(16) float sBh[2][32*72];    // [k][co] pad 72

    int tid  = threadIdx.x;
    int lane = tid & 31;
    int warp = tid >> 5;
    int wm = warp & 3;               // pos group (also wl, since pos = wl*32+d)
    int wn = warp >> 2;              // co group
    int bid = blockIdx.x;            // 512 = b(2) × h(32) × j(8)
    int b = bid >> 8;
    int h = (bid >> 3) & 31;
    int j = bid & 7;

    const float* src  = FIRST ? in : (const float*)g_vol2;
    const float* srcb = src + (size_t)b * 64 * LL;

    int r = lane & 3;                // threadID_in_group
    int q = lane >> 2;               // groupID

    // ---- precomputed per-thread staging descriptors ----
    int   pOff[3]; int pSz[3]; uint32_t pDst0[3], pDst1[3];
    int nP = (tid < 100) ? 3 : 2;
#pragma unroll
    for (int e = 0; e < 3; e++) {
        int idx = tid + e*256;
        if (idx < 612) {
            int row = idx / 34, col = idx - row*34;
            int kh = row / 6, iww = row - kh*6;
            int ih = h + kh - 1;
            int iw = j*4 + iww - 1;
            int id = col - 1;
            bool ok = (unsigned)ih < 32u && (unsigned)iw < 32u && (unsigned)id < 32u;
            pOff[e] = ok ? (ih*1024 + iw*32 + id) : 0;
            pSz[e]  = ok ? 4 : 0;
            pDst0[e] = s2u32(&sP[0][row*36 + col]);   // 36-stride (matches koff)
            pDst1[e] = s2u32(&sP[1][row*36 + col]);
        }
    }
    // B: 512 16B-chunks; thread handles c = tid, tid+256
    uint32_t bDst0[2], bDst1[2];
    int bSrcOff[2];
#pragma unroll
    for (int t = 0; t < 2; t++) {
        int c = tid + t*256;
        int k = c >> 4, cc = c & 15;
        bSrcOff[t] = c*4;
        bDst0[t] = s2u32(&sBh[0][k*72 + cc*4]);
        bDst1[t] = s2u32(&sBh[1][k*72 + cc*4]);
    }

    // Per-thread patch offsets for the 8 k columns this lane touches
    int koff[4][2];
#pragma unroll
    for (int ks = 0; ks < 4; ks++)
#pragma unroll
        for (int hf = 0; hf < 2; hf++) {
            int k = ks*8 + r + hf*4;
            if (k < 27) {
                int kh = k/9, kw = (k%9)/3, kd = k%3;
                koff[ks][hf] = (kh*6 + kw + wm)*36 + kd;
            } else koff[ks][hf] = -1;
        }

    float acc[2][4][4];
#pragma unroll
    for (int mt = 0; mt < 2; mt++)
#pragma unroll
        for (int nt = 0; nt < 4; nt++)
#pragma unroll
            for (int e = 0; e < 4; e++) acc[mt][nt][e] = 0.f;

    // ---- prefetch ci = 0 into buffer 0 ----
    {
        const float* sc = srcb;
        for (int e = 0; e < nP; e++) cpa4(pDst0[e], sc + pOff[e], pSz[e]);
#pragma unroll
        for (int t = 0; t < 2; t++)
            cpa16(bDst0[t], (const float4*)(g_wBh + bSrcOff[t]));
        CP_COMMIT();
    }

    for (int ci = 0; ci < 64; ci++) {
        int cur = ci & 1;
        if (ci < 63) {
            const float* sc = srcb + (size_t)(ci+1) * LL;
            int bo = (ci+1) * 2048;
            if (cur == 0) {
                for (int e = 0; e < nP; e++) cpa4(pDst1[e], sc + pOff[e], pSz[e]);
#pragma unroll
                for (int t = 0; t < 2; t++)
                    cpa16(bDst1[t], (const float4*)(g_wBh + bo + bSrcOff[t]));
            } else {
                for (int e = 0; e < nP; e++) cpa4(pDst0[e], sc + pOff[e], pSz[e]);
#pragma unroll
                for (int t = 0; t < 2; t++)
                    cpa16(bDst0[t], (const float4*)(g_wBh + bo + bSrcOff[t]));
            }
            CP_COMMIT();
            CP_WAIT1();
        } else {
            CP_WAIT0();
        }
        __syncthreads();

        const float* sPc  = sP[cur];
        const float* sBhc = sBh[cur];

#pragma unroll
        for (int ks = 0; ks < 4; ks++) {
            // A fragments (pos × k), single tf32
            uint32_t ah[2][4];
#pragma unroll
            for (int mt = 0; mt < 2; mt++) {
                int dA = mt*16 + q;
#pragma unroll
                for (int e = 0; e < 4; e++) {
                    int hf = e >> 1;
                    int dd = dA + ((e & 1) ? 8 : 0);
                    int off = koff[ks][hf];
                    float v = (off >= 0) ? sPc[off + dd] : 0.f;
                    uint32_t hb; asm("cvt.rna.tf32.f32 %0, %1;" : "=r"(hb) : "f"(v));
                    ah[mt][e] = hb;
                }
            }
            // B fragments (k × co) — conflict-free (pad 72)
            uint32_t bhf[4][2];
            int k0 = ks*8 + r;
#pragma unroll
            for (int nt = 0; nt < 4; nt++) {
                int co = wn*32 + nt*8 + q;
                bhf[nt][0] = __float_as_uint(sBhc[k0*72 + co]);
                bhf[nt][1] = __float_as_uint(sBhc[(k0+4)*72 + co]);
            }
#pragma unroll
            for (int mt = 0; mt < 2; mt++)
#pragma unroll
                for (int nt = 0; nt < 4; nt++)
                    mma8(acc[mt][nt], ah[mt], bhf[nt]);
        }
        __syncthreads();
    }

    // epilogue: c0:(q,2r) c1:(q,2r+1) c2:(q+8,2r) c3:(q+8,2r+1)
    int w = j*4 + wm;
#pragma unroll
    for (int mt = 0; mt < 2; mt++)
#pragma unroll
        for (int nt = 0; nt < 4; nt++)
#pragma unroll
            for (int e = 0; e < 4; e++) {
                int dd = mt*16 + q + ((e >= 2) ? 8 : 0);
                int co = wn*32 + nt*8 + 2*r + (e & 1);
                size_t gidx = (size_t)(b*64 + co)*LL + h*1024 + w*32 + dd;
                float v = acc[mt][nt][e] + cb[co];
                if (FIRST) {
                    g_tmp1[gidx] = v;
                } else {
                    float mean = g_mr[(b*64 + co)*2];
                    float rstd = g_mr[(b*64 + co)*2 + 1];
                    float s = (g_tmp1[gidx] - mean) * rstd;
                    outp[gidx] = v + (s > 0.f ? s : 0.f);
                }
            }
}

// ---------------- instance-norm stats (deterministic) ------------------------
__global__ __launch_bounds__(256) void stats_k()
{
    int bc = blockIdx.x;  // 0..127
    const float* p = g_tmp1 + (size_t)bc * LL;
    float s = 0.f, sq = 0.f;
    for (int i = threadIdx.x; i < LL; i += 256) { float v = p[i]; s += v; sq += v*v; }
    __shared__ float sh0[256], sh1[256];
    sh0[threadIdx.x] = s; sh1[threadIdx.x] = sq;
    __syncthreads();
    for (int o = 128; o > 0; o >>= 1) {
        if (threadIdx.x < o) { sh0[threadIdx.x] += sh0[threadIdx.x+o]; sh1[threadIdx.x] += sh1[threadIdx.x+o]; }
        __syncthreads();
    }
    if (threadIdx.x == 0) {
        float mean = sh0[0] * (1.f/LL);
        float var  = sh1[0] * (1.f/LL) - mean*mean;
        g_mr[bc*2]   = mean;
        g_mr[bc*2+1] = rsqrtf(var + 1e-5f);
    }
}

// ---------------- in_proj: xz[b][l][j] = sum_c in[b][c][l] * W[j][c] ----------
__global__ __launch_bounds__(256) void inproj_k(const float* __restrict__ in,
                                                const float* __restrict__ ipw)
{
    __shared__ float s_w[128][66];
    __shared__ float s_x[32][64];
    int b = blockIdx.y;
    int l0 = blockIdx.x * 64;
    int tid = threadIdx.x;
    for (int idx = tid; idx < 128*64; idx += 256) s_w[idx >> 6][idx & 63] = ipw[idx];

    int lq = tid & 15;
    int jq = tid >> 4;
    float acc[4][8];
#pragma unroll
    for (int i = 0; i < 4; i++)
#pragma unroll
        for (int j = 0; j < 8; j++) acc[i][j] = 0.f;

    for (int ch = 0; ch < 2; ch++) {
        __syncthreads();
        for (int idx = tid; idx < 32*64; idx += 256) {
            int c = idx >> 6, ll = idx & 63;
            s_x[c][ll] = in[(size_t)(b*64 + ch*32 + c)*LL + l0 + ll];
        }
        __syncthreads();
        for (int c = 0; c < 32; c++) {
            float xv[4], wv[8];
#pragma unroll
            for (int i = 0; i < 4; i++) xv[i] = s_x[c][lq*4 + i];
#pragma unroll
            for (int j = 0; j < 8; j++) wv[j] = s_w[jq*8 + j][ch*32 + c];
#pragma unroll
            for (int i = 0; i < 4; i++)
#pragma unroll
                for (int j = 0; j < 8; j++) acc[i][j] += xv[i] * wv[j];
        }
    }
#pragma unroll
    for (int i = 0; i < 4; i++) {
        int l = l0 + lq*4 + i;
        float4 v0 = make_float4(acc[i][0], acc[i][1], acc[i][2], acc[i][3]);
        float4 v1 = make_float4(acc[i][4], acc[i][5], acc[i][6], acc[i][7]);
        float4* dst = (float4*)&g_xz[((size_t)b*LL + l)*128 + jq*8];
        dst[0] = v0; dst[1] = v1;
    }
}

// ---------------- prep (both dirs): conv1d+silu, x_proj, dt_proj -------------
// grid (512 chunks, B, 2 dirs); dir from blockIdx.z (runtime).
__global__ __launch_bounds__(256) void prep_k(
    const float* __restrict__ w1d_g, const float* __restrict__ b1d_g,
    const float* __restrict__ xpw_g, const float* __restrict__ dtw_g,
    const float* __restrict__ dtb_g)
{
    __shared__ float xs[67][64];
    __shared__ float xc_s[64][65];
    __shared__ float dbl_s[64][20];
    __shared__ float xpw[20][65];
    __shared__ float w1d[64][4];
    __shared__ float dtw[64][5];
    __shared__ float b1d[64], dtb[64];

    int b = blockIdx.y;
    int dir = blockIdx.z;
    int s0 = blockIdx.x * 64;
    int tid = threadIdx.x;
    size_t xcb = (size_t)dir*XCSTR;
    size_t bmb = (size_t)dir*BMSTR;

    for (int idx = tid; idx < 20*64; idx += 256) xpw[idx/64][idx%64] = xpw_g[idx];
    if (tid < 64) {
#pragma unroll
        for (int k = 0; k < 4; k++) { w1d[tid][k] = w1d_g[tid*4 + k]; dtw[tid][k] = dtw_g[tid*4 + k]; }
        b1d[tid] = b1d_g[tid];
        dtb[tid] = dtb_g[tid];
    }
    for (int idx = tid; idx < 67*64; idx += 256) {
        int sr = idx / 64, d = idx % 64;
        int s = s0 + sr - 3;
        float v = 0.f;
        if (s >= 0) {
            int l = (dir == 0) ? s : (LL - 1 - s);
            v = g_xz[((size_t)b*LL + l)*128 + d];
        }
        xs[sr][d] = v;
    }
    __syncthreads();

    // causal depthwise conv1d (k=4) + silu
    for (int idx = tid; idx < 64*64; idx += 256) {
        int sl = idx >> 6, d = idx & 63;
        float v = b1d[d];
#pragma unroll
        for (int k = 0; k < 4; k++) v += w1d[d][k] * xs[sl + k][d];
        v = v / (1.f + __expf(-v));
        xc_s[sl][d] = v;
        g_xc[xcb + ((size_t)b*LL + s0 + sl)*64 + d] = v;
    }
    __syncthreads();

    // dbl = xc @ x_proj_w.T  (20 outputs)
    for (int idx = tid; idx < 64*20; idx += 256) {
        int sl = idx / 20, j = idx % 20;
        float v = 0.f;
        for (int d = 0; d < 64; d++) v += xc_s[sl][d] * xpw[j][d];
        dbl_s[sl][j] = v;
        int s = s0 + sl;
        if (j >= 4 && j < 12)      g_Bm[bmb + ((size_t)b*LL + s)*8 + (j-4)]  = v;
        else if (j >= 12)          g_Cm[bmb + ((size_t)b*LL + s)*8 + (j-12)] = v;
    }
    __syncthreads();

    // dt = softplus(dt_r @ dt_proj_w.T + b)
    for (int idx = tid; idx < 64*64; idx += 256) {
        int sl = idx >> 6, dd = idx & 63;
        float t = dtb[dd];
#pragma unroll
        for (int r = 0; r < 4; r++) t += dbl_s[sl][r] * dtw[dd][r];
        float sp = (t > 20.f) ? t : log1pf(__expf(t));
        g_dt[xcb + ((size_t)b*LL + s0 + sl)*64 + dd] = sp;
    }
}

// ---------------- scan pass A (both dirs): per-chunk (P, Q) reduction --------
__global__ __launch_bounds__(512) void scanA_k(const float* __restrict__ alog_f,
                                               const float* __restrict__ alog_b)
{
    __shared__ float s_dt[32][64];
    __shared__ float s_xc[32][64];
    __shared__ float s_B[32][8];
    int b = blockIdx.y;
    int dir = blockIdx.z;
    int chunk = blockIdx.x;
    int tid = threadIdx.x;
    int d = tid >> 3, n = tid & 7;
    const float* alog = dir ? alog_b : alog_f;
    float a = -__expf(alog[d*8 + n]);
    size_t xcb = (size_t)dir*XCSTR;
    size_t bmb = (size_t)dir*BMSTR;
    float P = 1.f, Q = 0.f;
    int sbase = chunk * CS;
    for (int sub = 0; sub < CS/32; sub++) {
        __syncthreads();
        int st = sbase + sub*32;
        for (int idx = tid; idx < 32*64; idx += 512) {
            int sl = idx >> 6, dd = idx & 63;
            size_t g = xcb + ((size_t)b*LL + st + sl)*64 + dd;
            s_dt[sl][dd] = g_dt[g];
            s_xc[sl][dd] = g_xc[g];
        }
        if (tid < 256) {
            int sl = tid >> 3, nn = tid & 7;
            s_B[sl][nn] = g_Bm[bmb + ((size_t)b*LL + st + sl)*8 + nn];
        }
        __syncthreads();
#pragma unroll 8
        for (int sl = 0; sl < 32; sl++) {
            float dtv = s_dt[sl][d];
            float ex = __expf(dtv * a);
            float u = dtv * s_xc[sl][d] * s_B[sl][n];
            P *= ex;
            Q = ex*Q + u;
        }
    }
    size_t o = (size_t)dir*PQSTR + ((size_t)(b*NCK + chunk))*512 + tid;
    g_P[o] = P; g_Q[o] = Q;
}

// ---------------- scan pass B (both dirs): sequential carry over chunks ------
__global__ __launch_bounds__(512) void scanB_k()
{
    int idx = blockIdx.x*512 + threadIdx.x;  // 0..2047 = (dir, b, dn)
    int dir = idx >> 10;
    int b = (idx >> 9) & 1;
    int dn = idx & 511;
    size_t base = (size_t)dir*PQSTR;
    float h = 0.f;
    for (int j = 0; j < NCK; j++) {
        size_t o = base + ((size_t)(b*NCK + j))*512 + dn;
        g_cin[o] = h;
        h = g_P[o]*h + g_Q[o];
    }
}

// ---------------- scan pass C (both dirs): replay with carry, y epilogue -----
__global__ __launch_bounds__(512) void scanC_k(const float* __restrict__ alog_f,
                                               const float* __restrict__ alog_b,
                                               const float* __restrict__ Dsk)
{
    __shared__ float s_dt[32][64];
    __shared__ float s_xc[32][64];
    __shared__ float s_B[32][8];
    __shared__ float s_C[32][8];
    __shared__ float s_y[32][64];
    int b = blockIdx.y;
    int dir = blockIdx.z;
    int chunk = blockIdx.x;
    int tid = threadIdx.x;
    int d = tid >> 3, n = tid & 7;
    const float* alog = dir ? alog_b : alog_f;
    float a = -__expf(alog[d*8 + n]);
    float Dv = Dsk[d];
    size_t xcb = (size_t)dir*XCSTR;
    size_t bmb = (size_t)dir*BMSTR;
    float h = g_cin[(size_t)dir*PQSTR + ((size_t)(b*NCK + chunk))*512 + tid];
    int sbase = chunk * CS;

    for (int sub = 0; sub < CS/32; sub++) {
        int st = sbase + sub*32;
        __syncthreads();
        for (int idx = tid; idx < 32*64; idx += 512) {
            int sl = idx >> 6, dd = idx & 63;
            size_t g = xcb + ((size_t)b*LL + st + sl)*64 + dd;
            s_dt[sl][dd] = g_dt[g];
            s_xc[sl][dd] = g_xc[g];
        }
        if (tid < 256) {
            int sl = tid >> 3, nn = tid & 7;
            size_t g = bmb + ((size_t)b*LL + st + sl)*8 + nn;
            s_B[sl][nn] = g_Bm[g];
            s_C[sl][nn] = g_Cm[g];
        }
        __syncthreads();
        for (int sl = 0; sl < 32; sl++) {
            float dtv = s_dt[sl][d];
            float xcv = s_xc[sl][d];
            float ex = __expf(dtv * a);
            h = ex*h + dtv * xcv * s_B[sl][n];
            float part = h * s_C[sl][n];
            part += __shfl_xor_sync(0xffffffffu, part, 1);
            part += __shfl_xor_sync(0xffffffffu, part, 2);
            part += __shfl_xor_sync(0xffffffffu, part, 4);
            if (n == 0) s_y[sl][d] = part + xcv * Dv;
        }
        __syncthreads();
        // multiply silu(z) and store at ORIGINAL l (per-dir buffer; outln sums)
        for (int idx = tid; idx < 32*64; idx += 512) {
            int sl = idx >> 6, dd = idx & 63;
            int s = st + sl;
            int l = (dir == 0) ? s : (LL - 1 - s);
            float z = g_xz[((size_t)b*LL + l)*128 + 64 + dd];
            float sil = z / (1.f + __expf(-z));
            g_y[xcb + ((size_t)b*LL + l)*64 + dd] = s_y[sl][dd] * sil;
        }
    }
}

// ---------------- out_proj (×0.5) + LayerNorm, write volume layout -----------
__global__ __launch_bounds__(256) void outln_k(const float* __restrict__ opw,
                                               const float* __restrict__ lng,
                                               const float* __restrict__ lnb)
{
    __shared__ float s_y[64][65];   // reused as r_s after GEMM
    __shared__ float s_w[64][65];
    __shared__ float mu_s[64], rs_s[64];
    int b = blockIdx.y;
    int l0 = blockIdx.x * 64;
    int tid = threadIdx.x;
    for (int idx = tid; idx < 64*64; idx += 256) s_w[idx >> 6][idx & 63] = opw[idx];
    for (int idx = tid; idx < 64*64; idx += 256) {
        int ll = idx >> 6, dd = idx & 63;
        size_t o = ((size_t)b*LL + l0 + ll)*64 + dd;
        s_y[ll][dd] = g_y[o] + g_y[XCSTR + o];   // y_f + y_b
    }
    __syncthreads();

    int lq = tid & 15, cq = tid >> 4;
    float acc[4][4];
#pragma unroll
    for (int i = 0; i < 4; i++)
#pragma unroll
        for (int j = 0; j < 4; j++) acc[i][j] = 0.f;
    for (int dd = 0; dd < 64; dd++) {
        float yv[4], wv[4];
#pragma unroll
        for (int i = 0; i < 4; i++) yv[i] = s_y[lq*4 + i][dd];
#pragma unroll
        for (int j = 0; j < 4; j++) wv[j] = s_w[cq*4 + j][dd];
#pragma unroll
        for (int i = 0; i < 4; i++)
#pragma unroll
            for (int j = 0; j < 4; j++) acc[i][j] += yv[i] * wv[j];
    }
    __syncthreads();
#pragma unroll
    for (int i = 0; i < 4; i++)
#pragma unroll
        for (int j = 0; j < 4; j++)
            s_y[lq*4 + i][cq*4 + j] = 0.5f * acc[i][j];
    __syncthreads();
    if (tid < 64) {
        float s = 0.f, sq = 0.f;
        for (int c = 0; c < 64; c++) { float v = s_y[tid][c]; s += v; sq += v*v; }
        float mu = s * (1.f/64.f);
        float var = sq * (1.f/64.f) - mu*mu;
        mu_s[tid] = mu; rs_s[tid] = rsqrtf(var + 1e-5f);
    }
    __syncthreads();
    for (int idx = tid; idx < 64*64; idx += 256) {
        int c = idx >> 6, ll = idx & 63;
        float v = (s_y[ll][c] - mu_s[ll]) * rs_s[ll] * lng[c] + lnb[c];
        g_vol2[(size_t)(b*64 + c)*LL + l0 + ll] = v;
    }
}

// ------------------------------- launcher ------------------------------------
extern "C" void kernel_launch(void* const* d_in, const int* in_sizes, int n_in,
                              void* d_out, int out_size)
{
    (void)in_sizes; (void)n_in; (void)out_size;
    const float* input     = (const float*)d_in[0];
    const float* conv_w    = (const float*)d_in[1];
    const float* conv_b    = (const float*)d_in[2];
    const float* in_proj_w = (const float*)d_in[3];
    const float* conv1d_w  = (const float*)d_in[4];
    const float* conv1d_b  = (const float*)d_in[5];
    const float* x_proj_w  = (const float*)d_in[6];
    const float* dt_proj_w = (const float*)d_in[7];
    const float* dt_proj_b = (const float*)d_in[8];
    const float* A_log     = (const float*)d_in[9];
    const float* A_b_log   = (const float*)d_in[10];
    const float* D_skip    = (const float*)d_in[11];
    const float* out_proj_w= (const float*)d_in[12];
    const float* ln_g      = (const float*)d_in[13];
    const float* ln_b      = (const float*)d_in[14];
    float* out = (float*)d_out;

    // one-time weight tf32 prep (shared by both convs)
    wsplit_k<<<512, 256>>>(conv_w);

    // token projection + fused both-direction prep (conv1 stays in the
    // ncu-profiled launch slot #4)
    inproj_k<<<dim3(512, 2), 256>>>(input, in_proj_w);
    prep_k<<<dim3(512, 2, 2), 256>>>(conv1d_w, conv1d_b, x_proj_w, dt_proj_w, dt_proj_b);

    // conv #1 + instance-norm stats (skip branch deferred to final conv)
    conv3d_m<true><<<512, 256>>>(input, conv_b, nullptr);
    stats_k<<<128, 256>>>();

    // scans, both directions concurrently
    scanA_k<<<dim3(NCK, 2, 2), 512>>>(A_log, A_b_log);
    scanB_k<<<4, 512>>>();
    scanC_k<<<dim3(NCK, 2, 2), 512>>>(A_log, A_b_log, D_skip);

    // out_proj + layernorm into volume layout
    outln_k<<<dim3(512, 2), 256>>>(out_proj_w, ln_g, ln_b);

    // conv #2 + residual skip; input g_vol2 is read from DEVICE code
    conv3d_m<false><<<512, 256>>>(nullptr, conv_b, out);
}

// round 14
// speedup vs baseline: 3.8896x; 1.0746x over previous
#include <cuda_runtime.h>
#include <math.h>
#include <stdint.h>

#define BB 2
#define CC 64
#define LL 32768      // 32*32*32 spatial = token count
#define DI 64
#define DS 8
#define CS 256        // scan chunk length
#define NCK 128       // number of chunks = LL/CS

// per-direction buffer strides
#define XZSTR ((size_t)BB*LL*128)
#define XCSTR ((size_t)BB*LL*DI)      // g_xc/g_dt/g_y per-dir stride
#define BMSTR ((size_t)BB*LL*DS)
#define PQSTR ((size_t)BB*NCK*DI*DS)  // = BB*NCK*512

// ---------------- scratch (static device globals; no allocation) -------------
__device__ float g_tmp1[BB*CC*LL];     // conv1 output
__device__ float g_mr[BB*CC*2];        // per (b,c) mean / rstd
__device__ float g_xz[XZSTR];          // in_proj output, [b][l][128]
__device__ float g_xc[2*XCSTR];        // [dir][b][l][d]
__device__ float g_dt[2*XCSTR];
__device__ float g_Bm[2*BMSTR];
__device__ float g_Cm[2*BMSTR];
__device__ float g_P[2*PQSTR];
__device__ float g_Q[2*PQSTR];
__device__ float g_y[2*XCSTR];         // [dir][b][l][d] at ORIGINAL l
__device__ float g_vol2[BB*CC*LL];     // LN output in volume layout (input of conv2)
__device__ float g_wB[64*2048];        // tf32 weights, FRAGMENT-READY layout (see wsplit)

// ---------------- one-time weight prep -> fragment-ready permuted layout -----
// For warp class wn (co/32), k-step ks, lane: the 8 values thread `lane` needs
// are stored as two float4s: [ci][wn*1024 + ks*256 + half*128 + lane*4 + elem],
// value = W[k = ks*8 + (lane&3) + hf*4][co = wn*32 + nt*8 + (lane>>2)],
// vecidx = nt*2+hf, half = vecidx>>2, elem = vecidx&3. lane*16B contiguous ->
// minimum-phase conflict-free LDS.128.
__global__ __launch_bounds__(256) void wsplit_k(const float* __restrict__ cw)
{
    int idx = blockIdx.x*256 + threadIdx.x;   // 64ci * 32k * 64co = 131072
    if (idx >= 64*32*64) return;
    int ci = idx >> 11;
    int k  = (idx >> 6) & 31;
    int co = idx & 63;
    float w = (k < 27) ? cw[(co*64 + ci)*27 + k] : 0.f;
    uint32_t hb; asm("cvt.rna.tf32.f32 %0, %1;" : "=r"(hb) : "f"(w));
    int ks = k >> 3, rr = k & 7, hf = rr >> 2, r = rr & 3;
    int wn = co >> 5, rem = co & 31, nt = rem >> 3, q = rem & 7;
    int lane = q*4 + r;
    int vecidx = nt*2 + hf;
    g_wB[ci*2048 + wn*1024 + ks*256 + (vecidx>>2)*128 + lane*4 + (vecidx&3)]
        = __uint_as_float(hb);
}

// ---------------- mma.sync m16n8k8 tf32 helper (sm_80+ baseline PTX) ---------
__device__ __forceinline__ void mma8(float* c, const uint32_t* a, const uint32_t* b)
{
    asm volatile("mma.sync.aligned.m16n8k8.row.col.f32.tf32.tf32.f32 "
        "{%0,%1,%2,%3}, {%4,%5,%6,%7}, {%8,%9}, {%0,%1,%2,%3};"
        : "+f"(c[0]), "+f"(c[1]), "+f"(c[2]), "+f"(c[3])
        : "r"(a[0]), "r"(a[1]), "r"(a[2]), "r"(a[3]), "r"(b[0]), "r"(b[1]));
}

// ---------------- cp.async helpers (sm_80+ baseline PTX) ---------------------
__device__ __forceinline__ uint32_t s2u32(const void* p) {
    uint32_t a;
    asm("{ .reg .u64 t; cvta.to.shared.u64 t, %1; cvt.u32.u64 %0, t; }" : "=r"(a) : "l"(p));
    return a;
}
__device__ __forceinline__ void cpa4(uint32_t dst, const float* src, int srcsz) {
    asm volatile("cp.async.ca.shared.global [%0], [%1], 4, %2;"
        :: "r"(dst), "l"(src), "r"(srcsz) : "memory");
}
__device__ __forceinline__ void cpa16(uint32_t dst, const float4* src) {
    asm volatile("cp.async.cg.shared.global [%0], [%1], 16;"
        :: "r"(dst), "l"(src) : "memory");
}
#define CP_COMMIT() asm volatile("cp.async.commit_group;" ::: "memory")
#define CP_WAIT1()  asm volatile("cp.async.wait_group 1;" ::: "memory")
#define CP_WAIT0()  asm volatile("cp.async.wait_group 0;" ::: "memory")

// ---------------- conv3d (3x3x3, pad 1, 64->64) via tf32 mma.sync ------------
// Block = (b, h, j): 128 pos (4 w × 32 d) × 64 co. 8 warps: warp (wm, wn)
// owns pos [wm*32, +32) × co [wn*32, +32) as 2 m-tiles × 4 n-tiles of m16n8k8.
// 2 ci per pipeline stage (32 stages), cp.async double-buffered.
// A patch is pre-converted to tf32 in shared once per stage; B fragments are
// vector LDS from the fragment-ready layout.
template<bool FIRST>
__global__ __launch_bounds__(256, 3) void conv3d_m(
    const float* __restrict__ in, const float* __restrict__ cb,
    float* __restrict__ outp)
{
    __shared__ __align__(16) float sP[2][2*648];     // 2 ci patches [18 rows][36]
    __shared__ __align__(16) float sB[2][2*2048];    // 2 ci fragment-ready B

    int tid  = threadIdx.x;
    int lane = tid & 31;
    int warp = tid >> 5;
    int wm = warp & 3;               // pos group (also wl, since pos = wl*32+d)
    int wn = warp >> 2;              // co group
    int bid = blockIdx.x;            // 512 = b(2) × h(32) × j(8)
    int b = bid >> 8;
    int h = (bid >> 3) & 31;
    int j = bid & 7;

    const float* src  = FIRST ? in : (const float*)g_vol2;
    const float* srcb = src + (size_t)b * 64 * LL;

    int r = lane & 3;                // threadID_in_group
    int q = lane >> 2;               // groupID

    // ---- per-thread staging descriptors (patch: 612 logical elems/ci) ----
    int   pOff[3]; int pSz[3]; uint32_t pDst[2][3];
    int nP = (tid < 100) ? 3 : 2;
#pragma unroll
    for (int e = 0; e < 3; e++) {
        int idx = tid + e*256;
        if (idx < 612) {
            int row = idx / 34, col = idx - row*34;
            int kh = row / 6, iww = row - kh*6;
            int ih = h + kh - 1;
            int iw = j*4 + iww - 1;
            int id = col - 1;
            bool ok = (unsigned)ih < 32u && (unsigned)iw < 32u && (unsigned)id < 32u;
            pOff[e] = ok ? (ih*1024 + iw*32 + id) : 0;
            pSz[e]  = ok ? 4 : 0;
            pDst[0][e] = s2u32(&sP[0][row*36 + col]);   // 36-stride (matches koff)
            pDst[1][e] = s2u32(&sP[1][row*36 + col]);
        }
    }
    uint32_t bDst[2] = { s2u32(&sB[0][0]) + (uint32_t)tid*16,
                         s2u32(&sB[1][0]) + (uint32_t)tid*16 };

    // Per-thread patch offsets for the 8 k columns this lane touches
    int koff[4][2];
#pragma unroll
    for (int ks = 0; ks < 4; ks++)
#pragma unroll
        for (int hf = 0; hf < 2; hf++) {
            int k = ks*8 + r + hf*4;
            if (k < 27) {
                int kh = k/9, kw = (k%9)/3, kd = k%3;
                koff[ks][hf] = (kh*6 + kw + wm)*36 + kd;
            } else koff[ks][hf] = -1;
        }

    float acc[2][4][4];
#pragma unroll
    for (int mt = 0; mt < 2; mt++)
#pragma unroll
        for (int nt = 0; nt < 4; nt++)
#pragma unroll
            for (int e = 0; e < 4; e++) acc[mt][nt][e] = 0.f;

    // ---- stage loader (2 ci) ----
    auto stage_load = [&](int st, int ci0) {
        const float* sc0 = srcb + (size_t)ci0 * LL;
        for (int e = 0; e < nP; e++) {
            cpa4(pDst[st][e],        sc0 + pOff[e],      pSz[e]);
            cpa4(pDst[st][e] + 2592, sc0 + LL + pOff[e], pSz[e]);   // ci0+1, +648 floats
        }
        const float4* bs = (const float4*)(g_wB + ci0*2048);
#pragma unroll
        for (int t = 0; t < 4; t++)
            cpa16(bDst[st] + (uint32_t)(t*256*16), bs + tid + t*256);
    };

    stage_load(0, 0);
    CP_COMMIT();

    for (int s = 0; s < 32; s++) {
        int cur = s & 1;
        if (s < 31) {
            stage_load(cur ^ 1, (s+1)*2);
            CP_COMMIT();
            CP_WAIT1();
        } else {
            CP_WAIT0();
        }
        __syncthreads();

        // pre-convert this stage's A patches to tf32 in place
        {
            float* p = sP[cur];
            for (int idx = tid; idx < 2*648; idx += 256) {
                float v = p[idx];
                uint32_t hb; asm("cvt.rna.tf32.f32 %0, %1;" : "=r"(hb) : "f"(v));
                p[idx] = __uint_as_float(hb);
            }
        }
        __syncthreads();

#pragma unroll
        for (int cii = 0; cii < 2; cii++) {
            const float* sPc = sP[cur] + cii*648;
            const float* sBc = sB[cur] + cii*2048 + wn*1024;
#pragma unroll
            for (int ks = 0; ks < 4; ks++) {
                // A fragments: plain LDS (already tf32)
                uint32_t ah[2][4];
#pragma unroll
                for (int mt = 0; mt < 2; mt++) {
                    int dA = mt*16 + q;
#pragma unroll
                    for (int e = 0; e < 4; e++) {
                        int hf = e >> 1;
                        int dd = dA + ((e & 1) ? 8 : 0);
                        int off = koff[ks][hf];
                        ah[mt][e] = (off >= 0) ? __float_as_uint(sPc[off + dd]) : 0u;
                    }
                }
                // B fragments: two conflict-free LDS.128
                const float* bb = sBc + ks*256 + lane*4;
                float4 v0 = *(const float4*)&bb[0];
                float4 v1 = *(const float4*)&bb[128];
                uint32_t bhf[4][2];
                bhf[0][0] = __float_as_uint(v0.x); bhf[0][1] = __float_as_uint(v0.y);
                bhf[1][0] = __float_as_uint(v0.z); bhf[1][1] = __float_as_uint(v0.w);
                bhf[2][0] = __float_as_uint(v1.x); bhf[2][1] = __float_as_uint(v1.y);
                bhf[3][0] = __float_as_uint(v1.z); bhf[3][1] = __float_as_uint(v1.w);
#pragma unroll
                for (int mt = 0; mt < 2; mt++)
#pragma unroll
                    for (int nt = 0; nt < 4; nt++)
                        mma8(acc[mt][nt], ah[mt], bhf[nt]);
            }
        }
        __syncthreads();
    }

    // epilogue: c0:(q,2r) c1:(q,2r+1) c2:(q+8,2r) c3:(q+8,2r+1)
    int w = j*4 + wm;
#pragma unroll
    for (int mt = 0; mt < 2; mt++)
#pragma unroll
        for (int nt = 0; nt < 4; nt++)
#pragma unroll
            for (int e = 0; e < 4; e++) {
                int dd = mt*16 + q + ((e >= 2) ? 8 : 0);
                int co = wn*32 + nt*8 + 2*r + (e & 1);
                size_t gidx = (size_t)(b*64 + co)*LL + h*1024 + w*32 + dd;
                float v = acc[mt][nt][e] + cb[co];
                if (FIRST) {
                    g_tmp1[gidx] = v;
                } else {
                    float mean = g_mr[(b*64 + co)*2];
                    float rstd = g_mr[(b*64 + co)*2 + 1];
                    float s = (g_tmp1[gidx] - mean) * rstd;
                    outp[gidx] = v + (s > 0.f ? s : 0.f);
                }
            }
}

// ---------------- instance-norm stats (deterministic) ------------------------
__global__ __launch_bounds__(256) void stats_k()
{
    int bc = blockIdx.x;  // 0..127
    const float* p = g_tmp1 + (size_t)bc * LL;
    float s = 0.f, sq = 0.f;
    for (int i = threadIdx.x; i < LL; i += 256) { float v = p[i]; s += v; sq += v*v; }
    __shared__ float sh0[256], sh1[256];
    sh0[threadIdx.x] = s; sh1[threadIdx.x] = sq;
    __syncthreads();
    for (int o = 128; o > 0; o >>= 1) {
        if (threadIdx.x < o) { sh0[threadIdx.x] += sh0[threadIdx.x+o]; sh1[threadIdx.x] += sh1[threadIdx.x+o]; }
        __syncthreads();
    }
    if (threadIdx.x == 0) {
        float mean = sh0[0] * (1.f/LL);
        float var  = sh1[0] * (1.f/LL) - mean*mean;
        g_mr[bc*2]   = mean;
        g_mr[bc*2+1] = rsqrtf(var + 1e-5f);
    }
}

// ---------------- in_proj: xz[b][l][j] = sum_c in[b][c][l] * W[j][c] ----------
__global__ __launch_bounds__(256) void inproj_k(const float* __restrict__ in,
                                                const float* __restrict__ ipw)
{
    __shared__ float s_w[128][66];
    __shared__ float s_x[32][64];
    int b = blockIdx.y;
    int l0 = blockIdx.x * 64;
    int tid = threadIdx.x;
    for (int idx = tid; idx < 128*64; idx += 256) s_w[idx >> 6][idx & 63] = ipw[idx];

    int lq = tid & 15;
    int jq = tid >> 4;
    float acc[4][8];
#pragma unroll
    for (int i = 0; i < 4; i++)
#pragma unroll
        for (int j = 0; j < 8; j++) acc[i][j] = 0.f;

    for (int ch = 0; ch < 2; ch++) {
        __syncthreads();
        for (int idx = tid; idx < 32*64; idx += 256) {
            int c = idx >> 6, ll = idx & 63;
            s_x[c][ll] = in[(size_t)(b*64 + ch*32 + c)*LL + l0 + ll];
        }
        __syncthreads();
        for (int c = 0; c < 32; c++) {
            float xv[4], wv[8];
#pragma unroll
            for (int i = 0; i < 4; i++) xv[i] = s_x[c][lq*4 + i];
#pragma unroll
            for (int j = 0; j < 8; j++) wv[j] = s_w[jq*8 + j][ch*32 + c];
#pragma unroll
            for (int i = 0; i < 4; i++)
#pragma unroll
                for (int j = 0; j < 8; j++) acc[i][j] += xv[i] * wv[j];
        }
    }
#pragma unroll
    for (int i = 0; i < 4; i++) {
        int l = l0 + lq*4 + i;
        float4 v0 = make_float4(acc[i][0], acc[i][1], acc[i][2], acc[i][3]);
        float4 v1 = make_float4(acc[i][4], acc[i][5], acc[i][6], acc[i][7]);
        float4* dst = (float4*)&g_xz[((size_t)b*LL + l)*128 + jq*8];
        dst[0] = v0; dst[1] = v1;
    }
}

// ---------------- prep (both dirs): conv1d+silu, x_proj, dt_proj -------------
__global__ __launch_bounds__(256) void prep_k(
    const float* __restrict__ w1d_g, const float* __restrict__ b1d_g,
    const float* __restrict__ xpw_g, const float* __restrict__ dtw_g,
    const float* __restrict__ dtb_g)
{
    __shared__ float xs[67][64];
    __shared__ float xc_s[64][65];
    __shared__ float dbl_s[64][20];
    __shared__ float xpw[20][65];
    __shared__ float w1d[64][4];
    __shared__ float dtw[64][5];
    __shared__ float b1d[64], dtb[64];

    int b = blockIdx.y;
    int dir = blockIdx.z;
    int s0 = blockIdx.x * 64;
    int tid = threadIdx.x;
    size_t xcb = (size_t)dir*XCSTR;
    size_t bmb = (size_t)dir*BMSTR;

    for (int idx = tid; idx < 20*64; idx += 256) xpw[idx/64][idx%64] = xpw_g[idx];
    if (tid < 64) {
#pragma unroll
        for (int k = 0; k < 4; k++) { w1d[tid][k] = w1d_g[tid*4 + k]; dtw[tid][k] = dtw_g[tid*4 + k]; }
        b1d[tid] = b1d_g[tid];
        dtb[tid] = dtb_g[tid];
    }
    for (int idx = tid; idx < 67*64; idx += 256) {
        int sr = idx / 64, d = idx % 64;
        int s = s0 + sr - 3;
        float v = 0.f;
        if (s >= 0) {
            int l = (dir == 0) ? s : (LL - 1 - s);
            v = g_xz[((size_t)b*LL + l)*128 + d];
        }
        xs[sr][d] = v;
    }
    __syncthreads();

    // causal depthwise conv1d (k=4) + silu
    for (int idx = tid; idx < 64*64; idx += 256) {
        int sl = idx >> 6, d = idx & 63;
        float v = b1d[d];
#pragma unroll
        for (int k = 0; k < 4; k++) v += w1d[d][k] * xs[sl + k][d];
        v = v / (1.f + __expf(-v));
        xc_s[sl][d] = v;
        g_xc[xcb + ((size_t)b*LL + s0 + sl)*64 + d] = v;
    }
    __syncthreads();

    // dbl = xc @ x_proj_w.T  (20 outputs)
    for (int idx = tid; idx < 64*20; idx += 256) {
        int sl = idx / 20, j = idx % 20;
        float v = 0.f;
        for (int d = 0; d < 64; d++) v += xc_s[sl][d] * xpw[j][d];
        dbl_s[sl][j] = v;
        int s = s0 + sl;
        if (j >= 4 && j < 12)      g_Bm[bmb + ((size_t)b*LL + s)*8 + (j-4)]  = v;
        else if (j >= 12)          g_Cm[bmb + ((size_t)b*LL + s)*8 + (j-12)] = v;
    }
    __syncthreads();

    // dt = softplus(dt_r @ dt_proj_w.T + b)
    for (int idx = tid; idx < 64*64; idx += 256) {
        int sl = idx >> 6, dd = idx & 63;
        float t = dtb[dd];
#pragma unroll
        for (int r = 0; r < 4; r++) t += dbl_s[sl][r] * dtw[dd][r];
        float sp = (t > 20.f) ? t : log1pf(__expf(t));
        g_dt[xcb + ((size_t)b*LL + s0 + sl)*64 + dd] = sp;
    }
}

// ---------------- scan pass A (both dirs): per-chunk (P, Q) reduction --------
__global__ __launch_bounds__(512) void scanA_k(const float* __restrict__ alog_f,
                                               const float* __restrict__ alog_b)
{
    __shared__ float s_dt[32][64];
    __shared__ float s_xc[32][64];
    __shared__ float s_B[32][8];
    int b = blockIdx.y;
    int dir = blockIdx.z;
    int chunk = blockIdx.x;
    int tid = threadIdx.x;
    int d = tid >> 3, n = tid & 7;
    const float* alog = dir ? alog_b : alog_f;
    float a = -__expf(alog[d*8 + n]);
    size_t xcb = (size_t)dir*XCSTR;
    size_t bmb = (size_t)dir*BMSTR;
    float P = 1.f, Q = 0.f;
    int sbase = chunk * CS;
    for (int sub = 0; sub < CS/32; sub++) {
        __syncthreads();
        int st = sbase + sub*32;
        for (int idx = tid; idx < 32*64; idx += 512) {
            int sl = idx >> 6, dd = idx & 63;
            size_t g = xcb + ((size_t)b*LL + st + sl)*64 + dd;
            s_dt[sl][dd] = g_dt[g];
            s_xc[sl][dd] = g_xc[g];
        }
        if (tid < 256) {
            int sl = tid >> 3, nn = tid & 7;
            s_B[sl][nn] = g_Bm[bmb + ((size_t)b*LL + st + sl)*8 + nn];
        }
        __syncthreads();
#pragma unroll 8
        for (int sl = 0; sl < 32; sl++) {
            float dtv = s_dt[sl][d];
            float ex = __expf(dtv * a);
            float u = dtv * s_xc[sl][d] * s_B[sl][n];
            P *= ex;
            Q = ex*Q + u;
        }
    }
    size_t o = (size_t)dir*PQSTR + ((size_t)(b*NCK + chunk))*512 + tid;
    g_P[o] = P; g_Q[o] = Q;
}

// ---------------- scan pass C (both dirs): inline carry + replay + epilogue --
__global__ __launch_bounds__(512) void scanC_k(const float* __restrict__ alog_f,
                                               const float* __restrict__ alog_b,
                                               const float* __restrict__ Dsk)
{
    __shared__ float s_dt[32][64];
    __shared__ float s_xc[32][64];
    __shared__ float s_B[32][8];
    __shared__ float s_C[32][8];
    __shared__ float s_y[32][64];
    int b = blockIdx.y;
    int dir = blockIdx.z;
    int chunk = blockIdx.x;
    int tid = threadIdx.x;
    int d = tid >> 3, n = tid & 7;
    const float* alog = dir ? alog_b : alog_f;
    float a = -__expf(alog[d*8 + n]);
    float Dv = Dsk[d];
    size_t xcb = (size_t)dir*XCSTR;
    size_t bmb = (size_t)dir*BMSTR;

    // inline carry: prefix chain over preceding chunks' (P, Q) — L2-resident
    float h = 0.f;
    {
        size_t pqb = (size_t)dir*PQSTR + (size_t)b*NCK*512 + tid;
        for (int jj = 0; jj < chunk; jj++) {
            size_t o = pqb + (size_t)jj*512;
            h = g_P[o]*h + g_Q[o];
        }
    }
    int sbase = chunk * CS;

    for (int sub = 0; sub < CS/32; sub++) {
        int st = sbase + sub*32;
        __syncthreads();
        for (int idx = tid; idx < 32*64; idx += 512) {
            int sl = idx >> 6, dd = idx & 63;
            size_t g = xcb + ((size_t)b*LL + st + sl)*64 + dd;
            s_dt[sl][dd] = g_dt[g];
            s_xc[sl][dd] = g_xc[g];
        }
        if (tid < 256) {
            int sl = tid >> 3, nn = tid & 7;
            size_t g = bmb + ((size_t)b*LL + st + sl)*8 + nn;
            s_B[sl][nn] = g_Bm[g];
            s_C[sl][nn] = g_Cm[g];
        }
        __syncthreads();
        for (int sl = 0; sl < 32; sl++) {
            float dtv = s_dt[sl][d];
            float xcv = s_xc[sl][d];
            float ex = __expf(dtv * a);
            h = ex*h + dtv * xcv * s_B[sl][n];
            float part = h * s_C[sl][n];
            part += __shfl_xor_sync(0xffffffffu, part, 1);
            part += __shfl_xor_sync(0xffffffffu, part, 2);
            part += __shfl_xor_sync(0xffffffffu, part, 4);
            if (n == 0) s_y[sl][d] = part + xcv * Dv;
        }
        __syncthreads();
        // multiply silu(z) and store at ORIGINAL l (per-dir buffer; outln sums)
        for (int idx = tid; idx < 32*64; idx += 512) {
            int sl = idx >> 6, dd = idx & 63;
            int s = st + sl;
            int l = (dir == 0) ? s : (LL - 1 - s);
            float z = g_xz[((size_t)b*LL + l)*128 + 64 + dd];
            float sil = z / (1.f + __expf(-z));
            g_y[xcb + ((size_t)b*LL + l)*64 + dd] = s_y[sl][dd] * sil;
        }
    }
}

// ---------------- out_proj (×0.5) + LayerNorm, write volume layout -----------
__global__ __launch_bounds__(256) void outln_k(const float* __restrict__ opw,
                                               const float* __restrict__ lng,
                                               const float* __restrict__ lnb)
{
    __shared__ float s_y[64][65];   // reused as r_s after GEMM
    __shared__ float s_w[64][65];
    __shared__ float mu_s[64], rs_s[64];
    int b = blockIdx.y;
    int l0 = blockIdx.x * 64;
    int tid = threadIdx.x;
    for (int idx = tid; idx < 64*64; idx += 256) s_w[idx >> 6][idx & 63] = opw[idx];
    for (int idx = tid; idx < 64*64; idx += 256) {
        int ll = idx >> 6, dd = idx & 63;
        size_t o = ((size_t)b*LL + l0 + ll)*64 + dd;
        s_y[ll][dd] = g_y[o] + g_y[XCSTR + o];   // y_f + y_b
    }
    __syncthreads();

    int lq = tid & 15, cq = tid >> 4;
    float acc[4][4];
#pragma unroll
    for (int i = 0; i < 4; i++)
#pragma unroll
        for (int j = 0; j < 4; j++) acc[i][j] = 0.f;
    for (int dd = 0; dd < 64; dd++) {
        float yv[4], wv[4];
#pragma unroll
        for (int i = 0; i < 4; i++) yv[i] = s_y[lq*4 + i][dd];
#pragma unroll
        for (int j = 0; j < 4; j++) wv[j] = s_w[cq*4 + j][dd];
#pragma unroll
        for (int i = 0; i < 4; i++)
#pragma unroll
            for (int j = 0; j < 4; j++) acc[i][j] += yv[i] * wv[j];
    }
    __syncthreads();
#pragma unroll
    for (int i = 0; i < 4; i++)
#pragma unroll
        for (int j = 0; j < 4; j++)
            s_y[lq*4 + i][cq*4 + j] = 0.5f * acc[i][j];
    __syncthreads();
    if (tid < 64) {
        float s = 0.f, sq = 0.f;
        for (int c = 0; c < 64; c++) { float v = s_y[tid][c]; s += v; sq += v*v; }
        float mu = s * (1.f/64.f);
        float var = sq * (1.f/64.f) - mu*mu;
        mu_s[tid] = mu; rs_s[tid] = rsqrtf(var + 1e-5f);
    }
    __syncthreads();
    for (int idx = tid; idx < 64*64; idx += 256) {
        int c = idx >> 6, ll = idx & 63;
        float v = (s_y[ll][c] - mu_s[ll]) * rs_s[ll] * lng[c] + lnb[c];
        g_vol2[(size_t)(b*64 + c)*LL + l0 + ll] = v;
    }
}

// ------------------------------- launcher ------------------------------------
extern "C" void kernel_launch(void* const* d_in, const int* in_sizes, int n_in,
                              void* d_out, int out_size)
{
    (void)in_sizes; (void)n_in; (void)out_size;
    const float* input     = (const float*)d_in[0];
    const float* conv_w    = (const float*)d_in[1];
    const float* conv_b    = (const float*)d_in[2];
    const float* in_proj_w = (const float*)d_in[3];
    const float* conv1d_w  = (const float*)d_in[4];
    const float* conv1d_b  = (const float*)d_in[5];
    const float* x_proj_w  = (const float*)d_in[6];
    const float* dt_proj_w = (const float*)d_in[7];
    const float* dt_proj_b = (const float*)d_in[8];
    const float* A_log     = (const float*)d_in[9];
    const float* A_b_log   = (const float*)d_in[10];
    const float* D_skip    = (const float*)d_in[11];
    const float* out_proj_w= (const float*)d_in[12];
    const float* ln_g      = (const float*)d_in[13];
    const float* ln_b      = (const float*)d_in[14];
    float* out = (float*)d_out;

    // one-time weight tf32 prep into fragment-ready layout
    wsplit_k<<<512, 256>>>(conv_w);

    // token projection + fused both-direction prep (conv1 stays in the
    // ncu-profiled launch slot #4)
    inproj_k<<<dim3(512, 2), 256>>>(input, in_proj_w);
    prep_k<<<dim3(512, 2, 2), 256>>>(conv1d_w, conv1d_b, x_proj_w, dt_proj_w, dt_proj_b);

    // conv #1 + instance-norm stats
    conv3d_m<true><<<512, 256>>>(input, conv_b, nullptr);
    stats_k<<<128, 256>>>();

    // scans, both directions concurrently (carry computed inline in scanC)
    scanA_k<<<dim3(NCK, 2, 2), 512>>>(A_log, A_b_log);
    scanC_k<<<dim3(NCK, 2, 2), 512>>>(A_log, A_b_log, D_skip);

    // out_proj + layernorm into volume layout
    outln_k<<<dim3(512, 2), 256>>>(out_proj_w, ln_g, ln_b);

    // conv #2 + residual skip; input g_vol2 is read from DEVICE code
    conv3d_m<false><<<512, 256>>>(nullptr, conv_b, out);
}

// round 15
// speedup vs baseline: 4.1287x; 1.0615x over previous
#include <cuda_runtime.h>
#include <math.h>
#include <stdint.h>

#define BB 2
#define CC 64
#define LL 32768      // 32*32*32 spatial = token count
#define DI 64
#define DS 8
#define CS 256        // scan chunk length
#define NCK 128       // number of chunks = LL/CS

// per-direction buffer strides
#define XZSTR ((size_t)BB*LL*128)
#define XCSTR ((size_t)BB*LL*DI)      // g_xc/g_dt/g_y per-dir stride
#define BMSTR ((size_t)BB*LL*DS)
#define PQSTR ((size_t)BB*NCK*DI*DS)  // = BB*NCK*512

// ---------------- scratch (static device globals; no allocation) -------------
__device__ float g_tmp1[BB*CC*LL];     // conv1 output
__device__ float g_mr[BB*CC*2];        // per (b,c) mean / rstd
__device__ float g_xz[XZSTR];          // in_proj output, [b][l][128]
__device__ float g_xc[2*XCSTR];        // [dir][b][l][d]
__device__ float g_dt[2*XCSTR];
__device__ float g_Bm[2*BMSTR];
__device__ float g_Cm[2*BMSTR];
__device__ float g_P[2*PQSTR];
__device__ float g_Q[2*PQSTR];
__device__ float g_y[2*XCSTR];         // [dir][b][l][d] at ORIGINAL l
__device__ float g_vol2[BB*CC*LL];     // LN output in volume layout (input of conv2)
__device__ float g_wB[64*2048];        // tf32 weights, FRAGMENT-READY layout (see wsplit)

// ---------------- one-time weight prep -> fragment-ready permuted layout -----
__global__ __launch_bounds__(256) void wsplit_k(const float* __restrict__ cw)
{
    int idx = blockIdx.x*256 + threadIdx.x;   // 64ci * 32k * 64co = 131072
    if (idx >= 64*32*64) return;
    int ci = idx >> 11;
    int k  = (idx >> 6) & 31;
    int co = idx & 63;
    float w = (k < 27) ? cw[(co*64 + ci)*27 + k] : 0.f;
    uint32_t hb; asm("cvt.rna.tf32.f32 %0, %1;" : "=r"(hb) : "f"(w));
    int ks = k >> 3, rr = k & 7, hf = rr >> 2, r = rr & 3;
    int wn = co >> 5, rem = co & 31, nt = rem >> 3, q = rem & 7;
    int lane = q*4 + r;
    int vecidx = nt*2 + hf;
    g_wB[ci*2048 + wn*1024 + ks*256 + (vecidx>>2)*128 + lane*4 + (vecidx&3)]
        = __uint_as_float(hb);
}

// ---------------- mma.sync m16n8k8 tf32 helper (sm_80+ baseline PTX) ---------
__device__ __forceinline__ void mma8(float* c, const uint32_t* a, const uint32_t* b)
{
    asm volatile("mma.sync.aligned.m16n8k8.row.col.f32.tf32.tf32.f32 "
        "{%0,%1,%2,%3}, {%4,%5,%6,%7}, {%8,%9}, {%0,%1,%2,%3};"
        : "+f"(c[0]), "+f"(c[1]), "+f"(c[2]), "+f"(c[3])
        : "r"(a[0]), "r"(a[1]), "r"(a[2]), "r"(a[3]), "r"(b[0]), "r"(b[1]));
}

// ---------------- cp.async helpers (sm_80+ baseline PTX) ---------------------
__device__ __forceinline__ uint32_t s2u32(const void* p) {
    uint32_t a;
    asm("{ .reg .u64 t; cvta.to.shared.u64 t, %1; cvt.u32.u64 %0, t; }" : "=r"(a) : "l"(p));
    return a;
}
__device__ __forceinline__ void cpa4(uint32_t dst, const float* src, int srcsz) {
    asm volatile("cp.async.ca.shared.global [%0], [%1], 4, %2;"
        :: "r"(dst), "l"(src), "r"(srcsz) : "memory");
}
__device__ __forceinline__ void cpa16(uint32_t dst, const float4* src) {
    asm volatile("cp.async.cg.shared.global [%0], [%1], 16;"
        :: "r"(dst), "l"(src) : "memory");
}
#define CP_COMMIT() asm volatile("cp.async.commit_group;" ::: "memory")
#define CP_WAIT1()  asm volatile("cp.async.wait_group 1;" ::: "memory")
#define CP_WAIT0()  asm volatile("cp.async.wait_group 0;" ::: "memory")

// ---------------- conv3d (3x3x3, pad 1, 64->64) via tf32 mma.sync ------------
// Block = (b, h, j): 128 pos (4 w × 32 d) × 64 co. 8 warps: warp (wm, wn)
// owns pos [wm*32, +32) × co [wn*32, +32) as 2 m-tiles × 4 n-tiles of m16n8k8.
// 2 ci per pipeline stage (32 stages), cp.async double-buffered.
// A patch is pre-converted to tf32 in shared once per stage; B fragments are
// vector LDS from the fragment-ready layout.
template<bool FIRST>
__global__ __launch_bounds__(256, 3) void conv3d_m(
    const float* __restrict__ in, const float* __restrict__ cb,
    float* __restrict__ outp)
{
    __shared__ __align__(16) float sP[2][2*648];     // 2 ci patches [18 rows][36]
    __shared__ __align__(16) float sB[2][2*2048];    // 2 ci fragment-ready B

    int tid  = threadIdx.x;
    int lane = tid & 31;
    int warp = tid >> 5;
    int wm = warp & 3;               // pos group (also wl, since pos = wl*32+d)
    int wn = warp >> 2;              // co group
    int bid = blockIdx.x;            // 512 = b(2) × h(32) × j(8)
    int b = bid >> 8;
    int h = (bid >> 3) & 31;
    int j = bid & 7;

    const float* src  = FIRST ? in : (const float*)g_vol2;
    const float* srcb = src + (size_t)b * 64 * LL;

    int r = lane & 3;                // threadID_in_group
    int q = lane >> 2;               // groupID

    // ---- per-thread staging descriptors (patch: 612 logical elems/ci) ----
    int   pOff[3]; int pSz[3]; uint32_t pDst[2][3];
    int nP = (tid < 100) ? 3 : 2;
#pragma unroll
    for (int e = 0; e < 3; e++) {
        int idx = tid + e*256;
        if (idx < 612) {
            int row = idx / 34, col = idx - row*34;
            int kh = row / 6, iww = row - kh*6;
            int ih = h + kh - 1;
            int iw = j*4 + iww - 1;
            int id = col - 1;
            bool ok = (unsigned)ih < 32u && (unsigned)iw < 32u && (unsigned)id < 32u;
            pOff[e] = ok ? (ih*1024 + iw*32 + id) : 0;
            pSz[e]  = ok ? 4 : 0;
            pDst[0][e] = s2u32(&sP[0][row*36 + col]);   // 36-stride (matches koff)
            pDst[1][e] = s2u32(&sP[1][row*36 + col]);
        }
    }
    uint32_t bDst[2] = { s2u32(&sB[0][0]) + (uint32_t)tid*16,
                         s2u32(&sB[1][0]) + (uint32_t)tid*16 };

    // Per-thread patch offsets for the 8 k columns this lane touches
    int koff[4][2];
#pragma unroll
    for (int ks = 0; ks < 4; ks++)
#pragma unroll
        for (int hf = 0; hf < 2; hf++) {
            int k = ks*8 + r + hf*4;
            if (k < 27) {
                int kh = k/9, kw = (k%9)/3, kd = k%3;
                koff[ks][hf] = (kh*6 + kw + wm)*36 + kd;
            } else koff[ks][hf] = -1;
        }

    float acc[2][4][4];
#pragma unroll
    for (int mt = 0; mt < 2; mt++)
#pragma unroll
        for (int nt = 0; nt < 4; nt++)
#pragma unroll
            for (int e = 0; e < 4; e++) acc[mt][nt][e] = 0.f;

    // ---- stage loader (2 ci) ----
    auto stage_load = [&](int st, int ci0) {
        const float* sc0 = srcb + (size_t)ci0 * LL;
        for (int e = 0; e < nP; e++) {
            cpa4(pDst[st][e],        sc0 + pOff[e],      pSz[e]);
            cpa4(pDst[st][e] + 2592, sc0 + LL + pOff[e], pSz[e]);   // ci0+1, +648 floats
        }
        const float4* bs = (const float4*)(g_wB + ci0*2048);
#pragma unroll
        for (int t = 0; t < 4; t++)
            cpa16(bDst[st] + (uint32_t)(t*256*16), bs + tid + t*256);
    };

    stage_load(0, 0);
    CP_COMMIT();

    for (int s = 0; s < 32; s++) {
        int cur = s & 1;
        if (s < 31) {
            stage_load(cur ^ 1, (s+1)*2);
            CP_COMMIT();
            CP_WAIT1();
        } else {
            CP_WAIT0();
        }
        __syncthreads();

        // pre-convert this stage's A patches to tf32 in place
        {
            float* p = sP[cur];
            for (int idx = tid; idx < 2*648; idx += 256) {
                float v = p[idx];
                uint32_t hb; asm("cvt.rna.tf32.f32 %0, %1;" : "=r"(hb) : "f"(v));
                p[idx] = __uint_as_float(hb);
            }
        }
        __syncthreads();

#pragma unroll
        for (int cii = 0; cii < 2; cii++) {
            const float* sPc = sP[cur] + cii*648;
            const float* sBc = sB[cur] + cii*2048 + wn*1024;
#pragma unroll
            for (int ks = 0; ks < 4; ks++) {
                // A fragments: plain LDS (already tf32)
                uint32_t ah[2][4];
#pragma unroll
                for (int mt = 0; mt < 2; mt++) {
                    int dA = mt*16 + q;
#pragma unroll
                    for (int e = 0; e < 4; e++) {
                        int hf = e >> 1;
                        int dd = dA + ((e & 1) ? 8 : 0);
                        int off = koff[ks][hf];
                        ah[mt][e] = (off >= 0) ? __float_as_uint(sPc[off + dd]) : 0u;
                    }
                }
                // B fragments: two conflict-free LDS.128
                const float* bb = sBc + ks*256 + lane*4;
                float4 v0 = *(const float4*)&bb[0];
                float4 v1 = *(const float4*)&bb[128];
                uint32_t bhf[4][2];
                bhf[0][0] = __float_as_uint(v0.x); bhf[0][1] = __float_as_uint(v0.y);
                bhf[1][0] = __float_as_uint(v0.z); bhf[1][1] = __float_as_uint(v0.w);
                bhf[2][0] = __float_as_uint(v1.x); bhf[2][1] = __float_as_uint(v1.y);
                bhf[3][0] = __float_as_uint(v1.z); bhf[3][1] = __float_as_uint(v1.w);
#pragma unroll
                for (int mt = 0; mt < 2; mt++)
#pragma unroll
                    for (int nt = 0; nt < 4; nt++)
                        mma8(acc[mt][nt], ah[mt], bhf[nt]);
            }
        }
        __syncthreads();
    }

    // epilogue: c0:(q,2r) c1:(q,2r+1) c2:(q+8,2r) c3:(q+8,2r+1)
    int w = j*4 + wm;
#pragma unroll
    for (int mt = 0; mt < 2; mt++)
#pragma unroll
        for (int nt = 0; nt < 4; nt++)
#pragma unroll
            for (int e = 0; e < 4; e++) {
                int dd = mt*16 + q + ((e >= 2) ? 8 : 0);
                int co = wn*32 + nt*8 + 2*r + (e & 1);
                size_t gidx = (size_t)(b*64 + co)*LL + h*1024 + w*32 + dd;
                float v = acc[mt][nt][e] + cb[co];
                if (FIRST) {
                    g_tmp1[gidx] = v;
                } else {
                    float mean = g_mr[(b*64 + co)*2];
                    float rstd = g_mr[(b*64 + co)*2 + 1];
                    float s = (g_tmp1[gidx] - mean) * rstd;
                    outp[gidx] = v + (s > 0.f ? s : 0.f);
                }
            }
}

// ---------------- instance-norm stats (deterministic) ------------------------
__global__ __launch_bounds__(256) void stats_k()
{
    int bc = blockIdx.x;  // 0..127
    const float* p = g_tmp1 + (size_t)bc * LL;
    float s = 0.f, sq = 0.f;
    for (int i = threadIdx.x; i < LL; i += 256) { float v = p[i]; s += v; sq += v*v; }
    __shared__ float sh0[256], sh1[256];
    sh0[threadIdx.x] = s; sh1[threadIdx.x] = sq;
    __syncthreads();
    for (int o = 128; o > 0; o >>= 1) {
        if (threadIdx.x < o) { sh0[threadIdx.x] += sh0[threadIdx.x+o]; sh1[threadIdx.x] += sh1[threadIdx.x+o]; }
        __syncthreads();
    }
    if (threadIdx.x == 0) {
        float mean = sh0[0] * (1.f/LL);
        float var  = sh1[0] * (1.f/LL) - mean*mean;
        g_mr[bc*2]   = mean;
        g_mr[bc*2+1] = rsqrtf(var + 1e-5f);
    }
}

// ---------------- in_proj: xz[b][l][j] = sum_c in[b][c][l] * W[j][c] ----------
__global__ __launch_bounds__(256) void inproj_k(const float* __restrict__ in,
                                                const float* __restrict__ ipw)
{
    __shared__ float s_w[128][66];
    __shared__ float s_x[32][64];
    int b = blockIdx.y;
    int l0 = blockIdx.x * 64;
    int tid = threadIdx.x;
    for (int idx = tid; idx < 128*64; idx += 256) s_w[idx >> 6][idx & 63] = ipw[idx];

    int lq = tid & 15;
    int jq = tid >> 4;
    float acc[4][8];
#pragma unroll
    for (int i = 0; i < 4; i++)
#pragma unroll
        for (int j = 0; j < 8; j++) acc[i][j] = 0.f;

    for (int ch = 0; ch < 2; ch++) {
        __syncthreads();
        for (int idx = tid; idx < 32*64; idx += 256) {
            int c = idx >> 6, ll = idx & 63;
            s_x[c][ll] = in[(size_t)(b*64 + ch*32 + c)*LL + l0 + ll];
        }
        __syncthreads();
        for (int c = 0; c < 32; c++) {
            float xv[4], wv[8];
#pragma unroll
            for (int i = 0; i < 4; i++) xv[i] = s_x[c][lq*4 + i];
#pragma unroll
            for (int j = 0; j < 8; j++) wv[j] = s_w[jq*8 + j][ch*32 + c];
#pragma unroll
            for (int i = 0; i < 4; i++)
#pragma unroll
                for (int j = 0; j < 8; j++) acc[i][j] += xv[i] * wv[j];
        }
    }
#pragma unroll
    for (int i = 0; i < 4; i++) {
        int l = l0 + lq*4 + i;
        float4 v0 = make_float4(acc[i][0], acc[i][1], acc[i][2], acc[i][3]);
        float4 v1 = make_float4(acc[i][4], acc[i][5], acc[i][6], acc[i][7]);
        float4* dst = (float4*)&g_xz[((size_t)b*LL + l)*128 + jq*8];
        dst[0] = v0; dst[1] = v1;
    }
}

// ---------------- prep (both dirs): conv1d+silu, x_proj, dt_proj -------------
__global__ __launch_bounds__(256) void prep_k(
    const float* __restrict__ w1d_g, const float* __restrict__ b1d_g,
    const float* __restrict__ xpw_g, const float* __restrict__ dtw_g,
    const float* __restrict__ dtb_g)
{
    __shared__ float xs[67][64];
    __shared__ float xc_s[64][65];
    __shared__ float dbl_s[64][20];
    __shared__ float xpw[20][65];
    __shared__ float w1d[64][4];
    __shared__ float dtw[64][5];
    __shared__ float b1d[64], dtb[64];

    int b = blockIdx.y;
    int dir = blockIdx.z;
    int s0 = blockIdx.x * 64;
    int tid = threadIdx.x;
    size_t xcb = (size_t)dir*XCSTR;
    size_t bmb = (size_t)dir*BMSTR;

    for (int idx = tid; idx < 20*64; idx += 256) xpw[idx/64][idx%64] = xpw_g[idx];
    if (tid < 64) {
#pragma unroll
        for (int k = 0; k < 4; k++) { w1d[tid][k] = w1d_g[tid*4 + k]; dtw[tid][k] = dtw_g[tid*4 + k]; }
        b1d[tid] = b1d_g[tid];
        dtb[tid] = dtb_g[tid];
    }
    for (int idx = tid; idx < 67*64; idx += 256) {
        int sr = idx / 64, d = idx % 64;
        int s = s0 + sr - 3;
        float v = 0.f;
        if (s >= 0) {
            int l = (dir == 0) ? s : (LL - 1 - s);
            v = g_xz[((size_t)b*LL + l)*128 + d];
        }
        xs[sr][d] = v;
    }
    __syncthreads();

    // causal depthwise conv1d (k=4) + silu
    for (int idx = tid; idx < 64*64; idx += 256) {
        int sl = idx >> 6, d = idx & 63;
        float v = b1d[d];
#pragma unroll
        for (int k = 0; k < 4; k++) v += w1d[d][k] * xs[sl + k][d];
        v = v / (1.f + __expf(-v));
        xc_s[sl][d] = v;
        g_xc[xcb + ((size_t)b*LL + s0 + sl)*64 + d] = v;
    }
    __syncthreads();

    // dbl = xc @ x_proj_w.T  (20 outputs)
    for (int idx = tid; idx < 64*20; idx += 256) {
        int sl = idx / 20, j = idx % 20;
        float v = 0.f;
        for (int d = 0; d < 64; d++) v += xc_s[sl][d] * xpw[j][d];
        dbl_s[sl][j] = v;
        int s = s0 + sl;
        if (j >= 4 && j < 12)      g_Bm[bmb + ((size_t)b*LL + s)*8 + (j-4)]  = v;
        else if (j >= 12)          g_Cm[bmb + ((size_t)b*LL + s)*8 + (j-12)] = v;
    }
    __syncthreads();

    // dt = softplus(dt_r @ dt_proj_w.T + b)
    for (int idx = tid; idx < 64*64; idx += 256) {
        int sl = idx >> 6, dd = idx & 63;
        float t = dtb[dd];
#pragma unroll
        for (int r = 0; r < 4; r++) t += dbl_s[sl][r] * dtw[dd][r];
        float sp = (t > 20.f) ? t : log1pf(__expf(t));
        g_dt[xcb + ((size_t)b*LL + s0 + sl)*64 + dd] = sp;
    }
}

// ---------------- scan pass A (both dirs): per-chunk (P, Q) reduction --------
__global__ __launch_bounds__(512) void scanA_k(const float* __restrict__ alog_f,
                                               const float* __restrict__ alog_b)
{
    __shared__ float s_dt[32][64];
    __shared__ float s_xc[32][64];
    __shared__ float s_B[32][8];
    int b = blockIdx.y;
    int dir = blockIdx.z;
    int chunk = blockIdx.x;
    int tid = threadIdx.x;
    int d = tid >> 3, n = tid & 7;
    const float* alog = dir ? alog_b : alog_f;
    float a = -__expf(alog[d*8 + n]);
    size_t xcb = (size_t)dir*XCSTR;
    size_t bmb = (size_t)dir*BMSTR;
    float P = 1.f, Q = 0.f;
    int sbase = chunk * CS;
    for (int sub = 0; sub < CS/32; sub++) {
        __syncthreads();
        int st = sbase + sub*32;
        for (int idx = tid; idx < 32*64; idx += 512) {
            int sl = idx >> 6, dd = idx & 63;
            size_t g = xcb + ((size_t)b*LL + st + sl)*64 + dd;
            s_dt[sl][dd] = g_dt[g];
            s_xc[sl][dd] = g_xc[g];
        }
        if (tid < 256) {
            int sl = tid >> 3, nn = tid & 7;
            s_B[sl][nn] = g_Bm[bmb + ((size_t)b*LL + st + sl)*8 + nn];
        }
        __syncthreads();
#pragma unroll 8
        for (int sl = 0; sl < 32; sl++) {
            float dtv = s_dt[sl][d];
            float ex = __expf(dtv * a);
            float u = dtv * s_xc[sl][d] * s_B[sl][n];
            P *= ex;
            Q = ex*Q + u;
        }
    }
    size_t o = (size_t)dir*PQSTR + ((size_t)(b*NCK + chunk))*512 + tid;
    g_P[o] = P; g_Q[o] = Q;
}

// ---------------- scan pass C (both dirs): inline carry + replay + epilogue --
__global__ __launch_bounds__(512) void scanC_k(const float* __restrict__ alog_f,
                                               const float* __restrict__ alog_b,
                                               const float* __restrict__ Dsk)
{
    __shared__ float s_dt[32][64];
    __shared__ float s_xc[32][64];
    __shared__ float s_B[32][8];
    __shared__ float s_C[32][8];
    __shared__ float s_y[32][64];
    int b = blockIdx.y;
    int dir = blockIdx.z;
    int chunk = blockIdx.x;
    int tid = threadIdx.x;
    int d = tid >> 3, n = tid & 7;
    const float* alog = dir ? alog_b : alog_f;
    float a = -__expf(alog[d*8 + n]);
    float Dv = Dsk[d];
    size_t xcb = (size_t)dir*XCSTR;
    size_t bmb = (size_t)dir*BMSTR;

    // inline carry: prefix chain over preceding chunks' (P, Q) — L2-resident
    float h = 0.f;
    {
        size_t pqb = (size_t)dir*PQSTR + (size_t)b*NCK*512 + tid;
        for (int jj = 0; jj < chunk; jj++) {
            size_t o = pqb + (size_t)jj*512;
            h = g_P[o]*h + g_Q[o];
        }
    }
    int sbase = chunk * CS;

    for (int sub = 0; sub < CS/32; sub++) {
        int st = sbase + sub*32;
        __syncthreads();
        for (int idx = tid; idx < 32*64; idx += 512) {
            int sl = idx >> 6, dd = idx & 63;
            size_t g = xcb + ((size_t)b*LL + st + sl)*64 + dd;
            s_dt[sl][dd] = g_dt[g];
            s_xc[sl][dd] = g_xc[g];
        }
        if (tid < 256) {
            int sl = tid >> 3, nn = tid & 7;
            size_t g = bmb + ((size_t)b*LL + st + sl)*8 + nn;
            s_B[sl][nn] = g_Bm[g];
            s_C[sl][nn] = g_Cm[g];
        }
        __syncthreads();
        for (int sl = 0; sl < 32; sl++) {
            float dtv = s_dt[sl][d];
            float xcv = s_xc[sl][d];
            float ex = __expf(dtv * a);
            h = ex*h + dtv * xcv * s_B[sl][n];
            float part = h * s_C[sl][n];
            part += __shfl_xor_sync(0xffffffffu, part, 1);
            part += __shfl_xor_sync(0xffffffffu, part, 2);
            part += __shfl_xor_sync(0xffffffffu, part, 4);
            if (n == 0) s_y[sl][d] = part + xcv * Dv;
        }
        __syncthreads();
        // multiply silu(z) and store at ORIGINAL l (per-dir buffer; outln sums)
        for (int idx = tid; idx < 32*64; idx += 512) {
            int sl = idx >> 6, dd = idx & 63;
            int s = st + sl;
            int l = (dir == 0) ? s : (LL - 1 - s);
            float z = g_xz[((size_t)b*LL + l)*128 + 64 + dd];
            float sil = z / (1.f + __expf(-z));
            g_y[xcb + ((size_t)b*LL + l)*64 + dd] = s_y[sl][dd] * sil;
        }
    }
}

// ---------------- out_proj (×0.5) + LayerNorm, write volume layout -----------
__global__ __launch_bounds__(256) void outln_k(const float* __restrict__ opw,
                                               const float* __restrict__ lng,
                                               const float* __restrict__ lnb)
{
    __shared__ float s_y[64][65];   // reused as r_s after GEMM
    __shared__ float s_w[64][65];
    __shared__ float mu_s[64], rs_s[64];
    int b = blockIdx.y;
    int l0 = blockIdx.x * 64;
    int tid = threadIdx.x;
    for (int idx = tid; idx < 64*64; idx += 256) s_w[idx >> 6][idx & 63] = opw[idx];
    for (int idx = tid; idx < 64*64; idx += 256) {
        int ll = idx >> 6, dd = idx & 63;
        size_t o = ((size_t)b*LL + l0 + ll)*64 + dd;
        s_y[ll][dd] = g_y[o] + g_y[XCSTR + o];   // y_f + y_b
    }
    __syncthreads();

    int lq = tid & 15, cq = tid >> 4;
    float acc[4][4];
#pragma unroll
    for (int i = 0; i < 4; i++)
#pragma unroll
        for (int j = 0; j < 4; j++) acc[i][j] = 0.f;
    for (int dd = 0; dd < 64; dd++) {
        float yv[4], wv[4];
#pragma unroll
        for (int i = 0; i < 4; i++) yv[i] = s_y[lq*4 + i][dd];
#pragma unroll
        for (int j = 0; j < 4; j++) wv[j] = s_w[cq*4 + j][dd];
#pragma unroll
        for (int i = 0; i < 4; i++)
#pragma unroll
            for (int j = 0; j < 4; j++) acc[i][j] += yv[i] * wv[j];
    }
    __syncthreads();
#pragma unroll
    for (int i = 0; i < 4; i++)
#pragma unroll
        for (int j = 0; j < 4; j++)
            s_y[lq*4 + i][cq*4 + j] = 0.5f * acc[i][j];
    __syncthreads();
    if (tid < 64) {
        float s = 0.f, sq = 0.f;
        for (int c = 0; c < 64; c++) { float v = s_y[tid][c]; s += v; sq += v*v; }
        float mu = s * (1.f/64.f);
        float var = sq * (1.f/64.f) - mu*mu;
        mu_s[tid] = mu; rs_s[tid] = rsqrtf(var + 1e-5f);
    }
    __syncthreads();
    for (int idx = tid; idx < 64*64; idx += 256) {
        int c = idx >> 6, ll = idx & 63;
        float v = (s_y[ll][c] - mu_s[ll]) * rs_s[ll] * lng[c] + lnb[c];
        g_vol2[(size_t)(b*64 + c)*LL + l0 + ll] = v;
    }
}

// ------------------------------- launcher ------------------------------------
// conv1+stats are independent of the Mamba branch until conv2. Run them on a
// capture-forked side stream (event fork/join pattern — graph-capture legal)
// so conv1 hides entirely behind inproj→prep→scanA→scanC→outln.
// Stream/event objects are created fresh each call (no caching) and NOT
// destroyed here: destroying a capture-participating stream before capture
// ends invalidates the capture. No device memory is allocated by these calls.
extern "C" void kernel_launch(void* const* d_in, const int* in_sizes, int n_in,
                              void* d_out, int out_size)
{
    (void)in_sizes; (void)n_in; (void)out_size;
    const float* input     = (const float*)d_in[0];
    const float* conv_w    = (const float*)d_in[1];
    const float* conv_b    = (const float*)d_in[2];
    const float* in_proj_w = (const float*)d_in[3];
    const float* conv1d_w  = (const float*)d_in[4];
    const float* conv1d_b  = (const float*)d_in[5];
    const float* x_proj_w  = (const float*)d_in[6];
    const float* dt_proj_w = (const float*)d_in[7];
    const float* dt_proj_b = (const float*)d_in[8];
    const float* A_log     = (const float*)d_in[9];
    const float* A_b_log   = (const float*)d_in[10];
    const float* D_skip    = (const float*)d_in[11];
    const float* out_proj_w= (const float*)d_in[12];
    const float* ln_g      = (const float*)d_in[13];
    const float* ln_b      = (const float*)d_in[14];
    float* out = (float*)d_out;

    cudaStream_t s2;
    cudaStreamCreateWithFlags(&s2, cudaStreamNonBlocking);
    cudaEvent_t evFork, evJoin;
    cudaEventCreateWithFlags(&evFork, cudaEventDisableTiming);
    cudaEventCreateWithFlags(&evJoin, cudaEventDisableTiming);

    // one-time weight tf32 prep into fragment-ready layout (needed by conv1)
    wsplit_k<<<512, 256>>>(conv_w);

    // fork: conv1 + stats on side stream
    cudaEventRecord(evFork, 0);
    cudaStreamWaitEvent(s2, evFork, 0);
    conv3d_m<true><<<512, 256, 0, s2>>>(input, conv_b, nullptr);
    stats_k<<<128, 256, 0, s2>>>();

    // main stream: the Mamba branch
    inproj_k<<<dim3(512, 2), 256>>>(input, in_proj_w);
    prep_k<<<dim3(512, 2, 2), 256>>>(conv1d_w, conv1d_b, x_proj_w, dt_proj_w, dt_proj_b);
    scanA_k<<<dim3(NCK, 2, 2), 512>>>(A_log, A_b_log);
    scanC_k<<<dim3(NCK, 2, 2), 512>>>(A_log, A_b_log, D_skip);
    outln_k<<<dim3(512, 2), 256>>>(out_proj_w, ln_g, ln_b);

    // join, then conv #2 + residual skip (reads g_vol2, g_tmp1, g_mr)
    cudaEventRecord(evJoin, s2);
    cudaStreamWaitEvent(0, evJoin, 0);
    conv3d_m<false><<<512, 256>>>(nullptr, conv_b, out);
}

// round 16
// speedup vs baseline: 4.2114x; 1.0200x over previous
#include <cuda_runtime.h>
#include <math.h>
#include <stdint.h>

#define BB 2
#define CC 64
#define LL 32768      // 32*32*32 spatial = token count
#define DI 64
#define DS 8
#define CS 256        // scan chunk length
#define NCK 128       // number of chunks = LL/CS

// per-direction buffer strides
#define XZSTR ((size_t)BB*LL*128)
#define XCSTR ((size_t)BB*LL*DI)      // g_xc/g_dt/g_y per-dir stride
#define BMSTR ((size_t)BB*LL*DS)
#define PQSTR ((size_t)BB*NCK*DI*DS)  // = BB*NCK*512

// ---------------- scratch (static device globals; no allocation) -------------
__device__ float g_tmp1[BB*CC*LL];     // conv1 output
__device__ float g_mr[BB*CC*2];        // per (b,c) mean / rstd
__device__ float g_xz[XZSTR];          // in_proj output, [b][l][128]
__device__ float g_xc[2*XCSTR];        // [dir][b][l][d]
__device__ float g_dt[2*XCSTR];
__device__ float g_Bm[2*BMSTR];
__device__ float g_Cm[2*BMSTR];
__device__ float g_P[2*PQSTR];
__device__ float g_Q[2*PQSTR];
__device__ float g_y[2*XCSTR];         // [dir][b][l][d] at ORIGINAL l
__device__ float g_vol2[BB*CC*LL];     // LN output in volume layout (input of conv2)
__device__ float g_wB[64*2048];        // tf32 weights, FRAGMENT-READY layout (see wsplit)

// ---------------- one-time weight prep -> fragment-ready permuted layout -----
__global__ __launch_bounds__(256) void wsplit_k(const float* __restrict__ cw)
{
    int idx = blockIdx.x*256 + threadIdx.x;   // 64ci * 32k * 64co = 131072
    if (idx >= 64*32*64) return;
    int ci = idx >> 11;
    int k  = (idx >> 6) & 31;
    int co = idx & 63;
    float w = (k < 27) ? cw[(co*64 + ci)*27 + k] : 0.f;
    uint32_t hb; asm("cvt.rna.tf32.f32 %0, %1;" : "=r"(hb) : "f"(w));
    int ks = k >> 3, rr = k & 7, hf = rr >> 2, r = rr & 3;
    int wn = co >> 5, rem = co & 31, nt = rem >> 3, q = rem & 7;
    int lane = q*4 + r;
    int vecidx = nt*2 + hf;
    g_wB[ci*2048 + wn*1024 + ks*256 + (vecidx>>2)*128 + lane*4 + (vecidx&3)]
        = __uint_as_float(hb);
}

// ---------------- mma.sync m16n8k8 tf32 helper (sm_80+ baseline PTX) ---------
__device__ __forceinline__ void mma8(float* c, const uint32_t* a, const uint32_t* b)
{
    asm volatile("mma.sync.aligned.m16n8k8.row.col.f32.tf32.tf32.f32 "
        "{%0,%1,%2,%3}, {%4,%5,%6,%7}, {%8,%9}, {%0,%1,%2,%3};"
        : "+f"(c[0]), "+f"(c[1]), "+f"(c[2]), "+f"(c[3])
        : "r"(a[0]), "r"(a[1]), "r"(a[2]), "r"(a[3]), "r"(b[0]), "r"(b[1]));
}

// ---------------- cp.async helpers (sm_80+ baseline PTX) ---------------------
__device__ __forceinline__ uint32_t s2u32(const void* p) {
    uint32_t a;
    asm("{ .reg .u64 t; cvta.to.shared.u64 t, %1; cvt.u32.u64 %0, t; }" : "=r"(a) : "l"(p));
    return a;
}
__device__ __forceinline__ void cpa4(uint32_t dst, const float* src, int srcsz) {
    asm volatile("cp.async.ca.shared.global [%0], [%1], 4, %2;"
        :: "r"(dst), "l"(src), "r"(srcsz) : "memory");
}
__device__ __forceinline__ void cpa16(uint32_t dst, const float4* src) {
    asm volatile("cp.async.cg.shared.global [%0], [%1], 16;"
        :: "r"(dst), "l"(src) : "memory");
}
#define CP_COMMIT() asm volatile("cp.async.commit_group;" ::: "memory")
#define CP_WAIT1()  asm volatile("cp.async.wait_group 1;" ::: "memory")
#define CP_WAIT0()  asm volatile("cp.async.wait_group 0;" ::: "memory")

// ---------------- conv3d (3x3x3, pad 1, 64->64) via tf32 mma.sync ------------
template<bool FIRST>
__global__ __launch_bounds__(256, 3) void conv3d_m(
    const float* __restrict__ in, const float* __restrict__ cb,
    float* __restrict__ outp)
{
    __shared__ __align__(16) float sP[2][2*648];     // 2 ci patches [18 rows][36]
    __shared__ __align__(16) float sB[2][2*2048];    // 2 ci fragment-ready B

    int tid  = threadIdx.x;
    int lane = tid & 31;
    int warp = tid >> 5;
    int wm = warp & 3;               // pos group (also wl, since pos = wl*32+d)
    int wn = warp >> 2;              // co group
    int bid = blockIdx.x;            // 512 = b(2) × h(32) × j(8)
    int b = bid >> 8;
    int h = (bid >> 3) & 31;
    int j = bid & 7;

    const float* src  = FIRST ? in : (const float*)g_vol2;
    const float* srcb = src + (size_t)b * 64 * LL;

    int r = lane & 3;                // threadID_in_group
    int q = lane >> 2;               // groupID

    // ---- per-thread staging descriptors (patch: 612 logical elems/ci) ----
    int   pOff[3]; int pSz[3]; uint32_t pDst[2][3];
    int nP = (tid < 100) ? 3 : 2;
#pragma unroll
    for (int e = 0; e < 3; e++) {
        int idx = tid + e*256;
        if (idx < 612) {
            int row = idx / 34, col = idx - row*34;
            int kh = row / 6, iww = row - kh*6;
            int ih = h + kh - 1;
            int iw = j*4 + iww - 1;
            int id = col - 1;
            bool ok = (unsigned)ih < 32u && (unsigned)iw < 32u && (unsigned)id < 32u;
            pOff[e] = ok ? (ih*1024 + iw*32 + id) : 0;
            pSz[e]  = ok ? 4 : 0;
            pDst[0][e] = s2u32(&sP[0][row*36 + col]);   // 36-stride (matches koff)
            pDst[1][e] = s2u32(&sP[1][row*36 + col]);
        }
    }
    uint32_t bDst[2] = { s2u32(&sB[0][0]) + (uint32_t)tid*16,
                         s2u32(&sB[1][0]) + (uint32_t)tid*16 };

    // Per-thread patch offsets for the 8 k columns this lane touches
    int koff[4][2];
#pragma unroll
    for (int ks = 0; ks < 4; ks++)
#pragma unroll
        for (int hf = 0; hf < 2; hf++) {
            int k = ks*8 + r + hf*4;
            if (k < 27) {
                int kh = k/9, kw = (k%9)/3, kd = k%3;
                koff[ks][hf] = (kh*6 + kw + wm)*36 + kd;
            } else koff[ks][hf] = -1;
        }

    float acc[2][4][4];
#pragma unroll
    for (int mt = 0; mt < 2; mt++)
#pragma unroll
        for (int nt = 0; nt < 4; nt++)
#pragma unroll
            for (int e = 0; e < 4; e++) acc[mt][nt][e] = 0.f;

    // ---- stage loader (2 ci) ----
    auto stage_load = [&](int st, int ci0) {
        const float* sc0 = srcb + (size_t)ci0 * LL;
        for (int e = 0; e < nP; e++) {
            cpa4(pDst[st][e],        sc0 + pOff[e],      pSz[e]);
            cpa4(pDst[st][e] + 2592, sc0 + LL + pOff[e], pSz[e]);   // ci0+1, +648 floats
        }
        const float4* bs = (const float4*)(g_wB + ci0*2048);
#pragma unroll
        for (int t = 0; t < 4; t++)
            cpa16(bDst[st] + (uint32_t)(t*256*16), bs + tid + t*256);
    };

    stage_load(0, 0);
    CP_COMMIT();

    for (int s = 0; s < 32; s++) {
        int cur = s & 1;
        if (s < 31) {
            stage_load(cur ^ 1, (s+1)*2);
            CP_COMMIT();
            CP_WAIT1();
        } else {
            CP_WAIT0();
        }
        __syncthreads();

        // pre-convert this stage's A patches to tf32 in place
        {
            float* p = sP[cur];
            for (int idx = tid; idx < 2*648; idx += 256) {
                float v = p[idx];
                uint32_t hb; asm("cvt.rna.tf32.f32 %0, %1;" : "=r"(hb) : "f"(v));
                p[idx] = __uint_as_float(hb);
            }
        }
        __syncthreads();

#pragma unroll
        for (int cii = 0; cii < 2; cii++) {
            const float* sPc = sP[cur] + cii*648;
            const float* sBc = sB[cur] + cii*2048 + wn*1024;
#pragma unroll
            for (int ks = 0; ks < 4; ks++) {
                uint32_t ah[2][4];
#pragma unroll
                for (int mt = 0; mt < 2; mt++) {
                    int dA = mt*16 + q;
#pragma unroll
                    for (int e = 0; e < 4; e++) {
                        int hf = e >> 1;
                        int dd = dA + ((e & 1) ? 8 : 0);
                        int off = koff[ks][hf];
                        ah[mt][e] = (off >= 0) ? __float_as_uint(sPc[off + dd]) : 0u;
                    }
                }
                const float* bb = sBc + ks*256 + lane*4;
                float4 v0 = *(const float4*)&bb[0];
                float4 v1 = *(const float4*)&bb[128];
                uint32_t bhf[4][2];
                bhf[0][0] = __float_as_uint(v0.x); bhf[0][1] = __float_as_uint(v0.y);
                bhf[1][0] = __float_as_uint(v0.z); bhf[1][1] = __float_as_uint(v0.w);
                bhf[2][0] = __float_as_uint(v1.x); bhf[2][1] = __float_as_uint(v1.y);
                bhf[3][0] = __float_as_uint(v1.z); bhf[3][1] = __float_as_uint(v1.w);
#pragma unroll
                for (int mt = 0; mt < 2; mt++)
#pragma unroll
                    for (int nt = 0; nt < 4; nt++)
                        mma8(acc[mt][nt], ah[mt], bhf[nt]);
            }
        }
        __syncthreads();
    }

    // epilogue
    int w = j*4 + wm;
#pragma unroll
    for (int mt = 0; mt < 2; mt++)
#pragma unroll
        for (int nt = 0; nt < 4; nt++)
#pragma unroll
            for (int e = 0; e < 4; e++) {
                int dd = mt*16 + q + ((e >= 2) ? 8 : 0);
                int co = wn*32 + nt*8 + 2*r + (e & 1);
                size_t gidx = (size_t)(b*64 + co)*LL + h*1024 + w*32 + dd;
                float v = acc[mt][nt][e] + cb[co];
                if (FIRST) {
                    g_tmp1[gidx] = v;
                } else {
                    float mean = g_mr[(b*64 + co)*2];
                    float rstd = g_mr[(b*64 + co)*2 + 1];
                    float s = (g_tmp1[gidx] - mean) * rstd;
                    outp[gidx] = v + (s > 0.f ? s : 0.f);
                }
            }
}

// ---------------- instance-norm stats (deterministic) ------------------------
__global__ __launch_bounds__(256) void stats_k()
{
    int bc = blockIdx.x;  // 0..127
    const float* p = g_tmp1 + (size_t)bc * LL;
    float s = 0.f, sq = 0.f;
    for (int i = threadIdx.x; i < LL; i += 256) { float v = p[i]; s += v; sq += v*v; }
    __shared__ float sh0[256], sh1[256];
    sh0[threadIdx.x] = s; sh1[threadIdx.x] = sq;
    __syncthreads();
    for (int o = 128; o > 0; o >>= 1) {
        if (threadIdx.x < o) { sh0[threadIdx.x] += sh0[threadIdx.x+o]; sh1[threadIdx.x] += sh1[threadIdx.x+o]; }
        __syncthreads();
    }
    if (threadIdx.x == 0) {
        float mean = sh0[0] * (1.f/LL);
        float var  = sh1[0] * (1.f/LL) - mean*mean;
        g_mr[bc*2]   = mean;
        g_mr[bc*2+1] = rsqrtf(var + 1e-5f);
    }
}

// ---------------- in_proj: xz[b][l][j] = sum_c in[b][c][l] * W[j][c] ----------
__global__ __launch_bounds__(256) void inproj_k(const float* __restrict__ in,
                                                const float* __restrict__ ipw)
{
    __shared__ float s_w[128][66];
    __shared__ float s_x[32][64];
    int b = blockIdx.y;
    int l0 = blockIdx.x * 64;
    int tid = threadIdx.x;
    for (int idx = tid; idx < 128*64; idx += 256) s_w[idx >> 6][idx & 63] = ipw[idx];

    int lq = tid & 15;
    int jq = tid >> 4;
    float acc[4][8];
#pragma unroll
    for (int i = 0; i < 4; i++)
#pragma unroll
        for (int j = 0; j < 8; j++) acc[i][j] = 0.f;

    for (int ch = 0; ch < 2; ch++) {
        __syncthreads();
        for (int idx = tid; idx < 32*64; idx += 256) {
            int c = idx >> 6, ll = idx & 63;
            s_x[c][ll] = in[(size_t)(b*64 + ch*32 + c)*LL + l0 + ll];
        }
        __syncthreads();
        for (int c = 0; c < 32; c++) {
            float4 xv4 = *(const float4*)&s_x[c][lq*4];   // 1 LDS.128, conflict-free
            float xv[4] = {xv4.x, xv4.y, xv4.z, xv4.w};
            float wv[8];
#pragma unroll
            for (int j = 0; j < 8; j++) wv[j] = s_w[jq*8 + j][ch*32 + c];
#pragma unroll
            for (int i = 0; i < 4; i++)
#pragma unroll
                for (int j = 0; j < 8; j++) acc[i][j] += xv[i] * wv[j];
        }
    }
#pragma unroll
    for (int i = 0; i < 4; i++) {
        int l = l0 + lq*4 + i;
        float4 v0 = make_float4(acc[i][0], acc[i][1], acc[i][2], acc[i][3]);
        float4 v1 = make_float4(acc[i][4], acc[i][5], acc[i][6], acc[i][7]);
        float4* dst = (float4*)&g_xz[((size_t)b*LL + l)*128 + jq*8];
        dst[0] = v0; dst[1] = v1;
    }
}

// ---------------- prep (both dirs): conv1d+silu, x_proj, dt_proj -------------
__global__ __launch_bounds__(256) void prep_k(
    const float* __restrict__ w1d_g, const float* __restrict__ b1d_g,
    const float* __restrict__ xpw_g, const float* __restrict__ dtw_g,
    const float* __restrict__ dtb_g)
{
    __shared__ float xs[67][64];
    __shared__ float xc_s[64][65];
    __shared__ float dbl_s[64][20];
    __shared__ float xpw[20][65];
    __shared__ float w1d[64][4];
    __shared__ float dtw[64][5];
    __shared__ float b1d[64], dtb[64];

    int b = blockIdx.y;
    int dir = blockIdx.z;
    int s0 = blockIdx.x * 64;
    int tid = threadIdx.x;
    size_t xcb = (size_t)dir*XCSTR;
    size_t bmb = (size_t)dir*BMSTR;

    for (int idx = tid; idx < 20*64; idx += 256) xpw[idx/64][idx%64] = xpw_g[idx];
    if (tid < 64) {
#pragma unroll
        for (int k = 0; k < 4; k++) { w1d[tid][k] = w1d_g[tid*4 + k]; dtw[tid][k] = dtw_g[tid*4 + k]; }
        b1d[tid] = b1d_g[tid];
        dtb[tid] = dtb_g[tid];
    }
    for (int idx = tid; idx < 67*64; idx += 256) {
        int sr = idx / 64, d = idx % 64;
        int s = s0 + sr - 3;
        float v = 0.f;
        if (s >= 0) {
            int l = (dir == 0) ? s : (LL - 1 - s);
            v = g_xz[((size_t)b*LL + l)*128 + d];
        }
        xs[sr][d] = v;
    }
    __syncthreads();

    // causal depthwise conv1d (k=4) + silu
    for (int idx = tid; idx < 64*64; idx += 256) {
        int sl = idx >> 6, d = idx & 63;
        float v = b1d[d];
#pragma unroll
        for (int k = 0; k < 4; k++) v += w1d[d][k] * xs[sl + k][d];
        v = v / (1.f + __expf(-v));
        xc_s[sl][d] = v;
        g_xc[xcb + ((size_t)b*LL + s0 + sl)*64 + d] = v;
    }
    __syncthreads();

    // dbl = xc @ x_proj_w.T — register-tiled: 64 sl × 4 jg, 5 j per thread.
    // Per d: 1 broadcast xv LDS + 5 broadcast wv LDS + 5 FMA (warp-uniform jg).
    {
        int sl = tid & 63;
        int jg = tid >> 6;          // 0..3 (warp-uniform: warps 0-1 jg0... pairs)
        float accp[5] = {0.f, 0.f, 0.f, 0.f, 0.f};
        for (int d = 0; d < 64; d++) {
            float xv = xc_s[sl][d];
#pragma unroll
            for (int jj = 0; jj < 5; jj++)
                accp[jj] += xv * xpw[jg*5 + jj][d];
        }
#pragma unroll
        for (int jj = 0; jj < 5; jj++) {
            int jdx = jg*5 + jj;
            dbl_s[sl][jdx] = accp[jj];
            int s = s0 + sl;
            if (jdx >= 4 && jdx < 12)  g_Bm[bmb + ((size_t)b*LL + s)*8 + (jdx-4)]  = accp[jj];
            else if (jdx >= 12)        g_Cm[bmb + ((size_t)b*LL + s)*8 + (jdx-12)] = accp[jj];
        }
    }
    __syncthreads();

    // dt = softplus(dt_r @ dt_proj_w.T + b)
    for (int idx = tid; idx < 64*64; idx += 256) {
        int sl = idx >> 6, dd = idx & 63;
        float t = dtb[dd];
#pragma unroll
        for (int r = 0; r < 4; r++) t += dbl_s[sl][r] * dtw[dd][r];
        float sp = (t > 20.f) ? t : log1pf(__expf(t));
        g_dt[xcb + ((size_t)b*LL + s0 + sl)*64 + dd] = sp;
    }
}

// ---------------- scan pass A (both dirs): per-chunk (P, Q) reduction --------
__global__ __launch_bounds__(512) void scanA_k(const float* __restrict__ alog_f,
                                               const float* __restrict__ alog_b)
{
    __shared__ float s_dt[32][64];
    __shared__ float s_xc[32][64];
    __shared__ float s_B[32][8];
    int b = blockIdx.y;
    int dir = blockIdx.z;
    int chunk = blockIdx.x;
    int tid = threadIdx.x;
    int d = tid >> 3, n = tid & 7;
    const float* alog = dir ? alog_b : alog_f;
    float a = -__expf(alog[d*8 + n]);
    size_t xcb = (size_t)dir*XCSTR;
    size_t bmb = (size_t)dir*BMSTR;
    float P = 1.f, Q = 0.f;
    int sbase = chunk * CS;
    for (int sub = 0; sub < CS/32; sub++) {
        __syncthreads();
        int st = sbase + sub*32;
        for (int idx = tid; idx < 32*64; idx += 512) {
            int sl = idx >> 6, dd = idx & 63;
            size_t g = xcb + ((size_t)b*LL + st + sl)*64 + dd;
            s_dt[sl][dd] = g_dt[g];
            s_xc[sl][dd] = g_xc[g];
        }
        if (tid < 256) {
            int sl = tid >> 3, nn = tid & 7;
            s_B[sl][nn] = g_Bm[bmb + ((size_t)b*LL + st + sl)*8 + nn];
        }
        __syncthreads();
#pragma unroll 8
        for (int sl = 0; sl < 32; sl++) {
            float dtv = s_dt[sl][d];
            float ex = __expf(dtv * a);
            float u = dtv * s_xc[sl][d] * s_B[sl][n];
            P *= ex;
            Q = ex*Q + u;
        }
    }
    size_t o = (size_t)dir*PQSTR + ((size_t)(b*NCK + chunk))*512 + tid;
    g_P[o] = P; g_Q[o] = Q;
}

// ---------------- scan pass C (both dirs): inline carry + replay + epilogue --
__global__ __launch_bounds__(512) void scanC_k(const float* __restrict__ alog_f,
                                               const float* __restrict__ alog_b,
                                               const float* __restrict__ Dsk)
{
    __shared__ float s_dt[32][64];
    __shared__ float s_xc[32][64];
    __shared__ float s_B[32][8];
    __shared__ float s_C[32][8];
    __shared__ float s_y[32][64];
    int b = blockIdx.y;
    int dir = blockIdx.z;
    int chunk = blockIdx.x;
    int tid = threadIdx.x;
    int d = tid >> 3, n = tid & 7;
    const float* alog = dir ? alog_b : alog_f;
    float a = -__expf(alog[d*8 + n]);
    float Dv = Dsk[d];
    size_t xcb = (size_t)dir*XCSTR;
    size_t bmb = (size_t)dir*BMSTR;

    // inline carry: prefix chain over preceding chunks' (P, Q).
    // Batched unroll-by-8: loads are independent (MLP 16), FMAs chain.
    float h = 0.f;
    {
        size_t pqb = (size_t)dir*PQSTR + (size_t)b*NCK*512 + tid;
        int jj = 0;
        for (; jj + 8 <= chunk; jj += 8) {
            float p[8], qq[8];
#pragma unroll
            for (int t = 0; t < 8; t++) {
                size_t o = pqb + (size_t)(jj + t)*512;
                p[t]  = g_P[o];
                qq[t] = g_Q[o];
            }
#pragma unroll
            for (int t = 0; t < 8; t++) h = p[t]*h + qq[t];
        }
        for (; jj < chunk; jj++) {
            size_t o = pqb + (size_t)jj*512;
            h = g_P[o]*h + g_Q[o];
        }
    }
    int sbase = chunk * CS;

    for (int sub = 0; sub < CS/32; sub++) {
        int st = sbase + sub*32;
        __syncthreads();
        for (int idx = tid; idx < 32*64; idx += 512) {
            int sl = idx >> 6, dd = idx & 63;
            size_t g = xcb + ((size_t)b*LL + st + sl)*64 + dd;
            s_dt[sl][dd] = g_dt[g];
            s_xc[sl][dd] = g_xc[g];
        }
        if (tid < 256) {
            int sl = tid >> 3, nn = tid & 7;
            size_t g = bmb + ((size_t)b*LL + st + sl)*8 + nn;
            s_B[sl][nn] = g_Bm[g];
            s_C[sl][nn] = g_Cm[g];
        }
        __syncthreads();
        for (int sl = 0; sl < 32; sl++) {
            float dtv = s_dt[sl][d];
            float xcv = s_xc[sl][d];
            float ex = __expf(dtv * a);
            h = ex*h + dtv * xcv * s_B[sl][n];
            float part = h * s_C[sl][n];
            part += __shfl_xor_sync(0xffffffffu, part, 1);
            part += __shfl_xor_sync(0xffffffffu, part, 2);
            part += __shfl_xor_sync(0xffffffffu, part, 4);
            if (n == 0) s_y[sl][d] = part + xcv * Dv;
        }
        __syncthreads();
        // multiply silu(z) and store at ORIGINAL l (per-dir buffer; outln sums)
        for (int idx = tid; idx < 32*64; idx += 512) {
            int sl = idx >> 6, dd = idx & 63;
            int s = st + sl;
            int l = (dir == 0) ? s : (LL - 1 - s);
            float z = g_xz[((size_t)b*LL + l)*128 + 64 + dd];
            float sil = z / (1.f + __expf(-z));
            g_y[xcb + ((size_t)b*LL + l)*64 + dd] = s_y[sl][dd] * sil;
        }
    }
}

// ---------------- out_proj (×0.5) + LayerNorm, write volume layout -----------
__global__ __launch_bounds__(256) void outln_k(const float* __restrict__ opw,
                                               const float* __restrict__ lng,
                                               const float* __restrict__ lnb)
{
    __shared__ float s_y[64][65];   // reused as r_s after GEMM
    __shared__ float s_w[64][65];
    __shared__ float mu_s[64], rs_s[64];
    int b = blockIdx.y;
    int l0 = blockIdx.x * 64;
    int tid = threadIdx.x;
    for (int idx = tid; idx < 64*64; idx += 256) s_w[idx >> 6][idx & 63] = opw[idx];
    for (int idx = tid; idx < 64*64; idx += 256) {
        int ll = idx >> 6, dd = idx & 63;
        size_t o = ((size_t)b*LL + l0 + ll)*64 + dd;
        s_y[ll][dd] = g_y[o] + g_y[XCSTR + o];   // y_f + y_b
    }
    __syncthreads();

    int lq = tid & 15, cq = tid >> 4;
    float acc[4][4];
#pragma unroll
    for (int i = 0; i < 4; i++)
#pragma unroll
        for (int j = 0; j < 4; j++) acc[i][j] = 0.f;
    for (int dd = 0; dd < 64; dd++) {
        float yv[4], wv[4];
#pragma unroll
        for (int i = 0; i < 4; i++) yv[i] = s_y[lq*4 + i][dd];
#pragma unroll
        for (int j = 0; j < 4; j++) wv[j] = s_w[cq*4 + j][dd];
#pragma unroll
        for (int i = 0; i < 4; i++)
#pragma unroll
            for (int j = 0; j < 4; j++) acc[i][j] += yv[i] * wv[j];
    }
    __syncthreads();
#pragma unroll
    for (int i = 0; i < 4; i++)
#pragma unroll
        for (int j = 0; j < 4; j++)
            s_y[lq*4 + i][cq*4 + j] = 0.5f * acc[i][j];
    __syncthreads();
    if (tid < 64) {
        float s = 0.f, sq = 0.f;
        for (int c = 0; c < 64; c++) { float v = s_y[tid][c]; s += v; sq += v*v; }
        float mu = s * (1.f/64.f);
        float var = sq * (1.f/64.f) - mu*mu;
        mu_s[tid] = mu; rs_s[tid] = rsqrtf(var + 1e-5f);
    }
    __syncthreads();
    for (int idx = tid; idx < 64*64; idx += 256) {
        int c = idx >> 6, ll = idx & 63;
        float v = (s_y[ll][c] - mu_s[ll]) * rs_s[ll] * lng[c] + lnb[c];
        g_vol2[(size_t)(b*64 + c)*LL + l0 + ll] = v;
    }
}

// ------------------------------- launcher ------------------------------------
// conv1+stats run on a capture-forked side stream (fork/join via events) so
// they overlap the Mamba branch. Stream/event objects created fresh per call;
// not destroyed mid-capture. No device memory allocated.
extern "C" void kernel_launch(void* const* d_in, const int* in_sizes, int n_in,
                              void* d_out, int out_size)
{
    (void)in_sizes; (void)n_in; (void)out_size;
    const float* input     = (const float*)d_in[0];
    const float* conv_w    = (const float*)d_in[1];
    const float* conv_b    = (const float*)d_in[2];
    const float* in_proj_w = (const float*)d_in[3];
    const float* conv1d_w  = (const float*)d_in[4];
    const float* conv1d_b  = (const float*)d_in[5];
    const float* x_proj_w  = (const float*)d_in[6];
    const float* dt_proj_w = (const float*)d_in[7];
    const float* dt_proj_b = (const float*)d_in[8];
    const float* A_log     = (const float*)d_in[9];
    const float* A_b_log   = (const float*)d_in[10];
    const float* D_skip    = (const float*)d_in[11];
    const float* out_proj_w= (const float*)d_in[12];
    const float* ln_g      = (const float*)d_in[13];
    const float* ln_b      = (const float*)d_in[14];
    float* out = (float*)d_out;

    cudaStream_t s2;
    cudaStreamCreateWithFlags(&s2, cudaStreamNonBlocking);
    cudaEvent_t evFork, evJoin;
    cudaEventCreateWithFlags(&evFork, cudaEventDisableTiming);
    cudaEventCreateWithFlags(&evJoin, cudaEventDisableTiming);

    // one-time weight tf32 prep into fragment-ready layout (needed by conv1)
    wsplit_k<<<512, 256>>>(conv_w);

    // fork: conv1 + stats on side stream
    cudaEventRecord(evFork, 0);
    cudaStreamWaitEvent(s2, evFork, 0);
    conv3d_m<true><<<512, 256, 0, s2>>>(input, conv_b, nullptr);
    stats_k<<<128, 256, 0, s2>>>();

    // main stream: the Mamba branch
    inproj_k<<<dim3(512, 2), 256>>>(input, in_proj_w);
    prep_k<<<dim3(512, 2, 2), 256>>>(conv1d_w, conv1d_b, x_proj_w, dt_proj_w, dt_proj_b);
    scanA_k<<<dim3(NCK, 2, 2), 512>>>(A_log, A_b_log);
    scanC_k<<<dim3(NCK, 2, 2), 512>>>(A_log, A_b_log, D_skip);
    outln_k<<<dim3(512, 2), 256>>>(out_proj_w, ln_g, ln_b);

    // join, then conv #2 + residual skip (reads g_vol2, g_tmp1, g_mr)
    cudaEventRecord(evJoin, s2);
    cudaStreamWaitEvent(0, evJoin, 0);
    conv3d_m<false><<<512, 256>>>(nullptr, conv_b, out);
}

// round 17
// speedup vs baseline: 4.2303x; 1.0045x over previous
#include <cuda_runtime.h>
#include <math.h>
#include <stdint.h>

#define BB 2
#define CC 64
#define LL 32768      // 32*32*32 spatial = token count
#define DI 64
#define DS 8
#define CS 256        // scan chunk length
#define NCK 128       // number of chunks = LL/CS

// per-direction buffer strides
#define XZSTR ((size_t)BB*LL*128)
#define XCSTR ((size_t)BB*LL*DI)      // g_xc/g_dt/g_y per-dir stride
#define BMSTR ((size_t)BB*LL*DS)
#define PQSTR ((size_t)BB*NCK*DI*DS)  // = BB*NCK*512

// ---------------- scratch (static device globals; no allocation) -------------
__device__ float g_tmp1[BB*CC*LL];     // conv1 output
__device__ float g_mr[BB*CC*2];        // per (b,c) mean / rstd
__device__ float g_xz[XZSTR];          // in_proj output, [b][l][128]
__device__ float g_xc[2*XCSTR];        // [dir][b][l][d]
__device__ float g_dt[2*XCSTR];
__device__ float g_Bm[2*BMSTR];
__device__ float g_Cm[2*BMSTR];
__device__ float g_P[2*PQSTR];
__device__ float g_Q[2*PQSTR];
__device__ float g_y[2*XCSTR];         // [dir][b][l][d] at ORIGINAL l
__device__ float g_vol2[BB*CC*LL];     // LN output in volume layout (input of conv2)
__device__ float g_wB[64*2048];        // tf32 weights, FRAGMENT-READY layout (see wsplit)

// ---------------- one-time weight prep -> fragment-ready permuted layout -----
__global__ __launch_bounds__(256) void wsplit_k(const float* __restrict__ cw)
{
    int idx = blockIdx.x*256 + threadIdx.x;   // 64ci * 32k * 64co = 131072
    if (idx >= 64*32*64) return;
    int ci = idx >> 11;
    int k  = (idx >> 6) & 31;
    int co = idx & 63;
    float w = (k < 27) ? cw[(co*64 + ci)*27 + k] : 0.f;
    uint32_t hb; asm("cvt.rna.tf32.f32 %0, %1;" : "=r"(hb) : "f"(w));
    int ks = k >> 3, rr = k & 7, hf = rr >> 2, r = rr & 3;
    int wn = co >> 5, rem = co & 31, nt = rem >> 3, q = rem & 7;
    int lane = q*4 + r;
    int vecidx = nt*2 + hf;
    g_wB[ci*2048 + wn*1024 + ks*256 + (vecidx>>2)*128 + lane*4 + (vecidx&3)]
        = __uint_as_float(hb);
}

// ---------------- mma.sync m16n8k8 tf32 helper (sm_80+ baseline PTX) ---------
__device__ __forceinline__ void mma8(float* c, const uint32_t* a, const uint32_t* b)
{
    asm volatile("mma.sync.aligned.m16n8k8.row.col.f32.tf32.tf32.f32 "
        "{%0,%1,%2,%3}, {%4,%5,%6,%7}, {%8,%9}, {%0,%1,%2,%3};"
        : "+f"(c[0]), "+f"(c[1]), "+f"(c[2]), "+f"(c[3])
        : "r"(a[0]), "r"(a[1]), "r"(a[2]), "r"(a[3]), "r"(b[0]), "r"(b[1]));
}

// ---------------- cp.async helpers (sm_80+ baseline PTX) ---------------------
__device__ __forceinline__ uint32_t s2u32(const void* p) {
    uint32_t a;
    asm("{ .reg .u64 t; cvta.to.shared.u64 t, %1; cvt.u32.u64 %0, t; }" : "=r"(a) : "l"(p));
    return a;
}
__device__ __forceinline__ void cpa4(uint32_t dst, const float* src, int srcsz) {
    asm volatile("cp.async.ca.shared.global [%0], [%1], 4, %2;"
        :: "r"(dst), "l"(src), "r"(srcsz) : "memory");
}
__device__ __forceinline__ void cpa16(uint32_t dst, const float4* src) {
    asm volatile("cp.async.cg.shared.global [%0], [%1], 16;"
        :: "r"(dst), "l"(src) : "memory");
}
#define CP_COMMIT() asm volatile("cp.async.commit_group;" ::: "memory")
#define CP_WAIT1()  asm volatile("cp.async.wait_group 1;" ::: "memory")
#define CP_WAIT0()  asm volatile("cp.async.wait_group 0;" ::: "memory")

// ---------------- conv3d (3x3x3, pad 1, 64->64) via tf32 mma.sync ------------
// CO-SPLIT blocks: 1024 = b(2)×h(32)×j(8)×half(2); 128 threads = 4 warps.
// Block tile: 128 pos (4 w × 32 d) × 32 co (co-half = wn from blockIdx).
// Warp wm owns pos [wm*32,+32) × all 32 co as 2 m-tiles × 4 n-tiles m16n8k8.
// 2 ci per cp.async double-buffered stage; A patch pre-converted to tf32.
// 4-warp barriers + 6 CTAs/SM → latency hiding across independent pipelines.
template<bool FIRST>
__global__ __launch_bounds__(128, 6) void conv3d_m(
    const float* __restrict__ in, const float* __restrict__ cb,
    float* __restrict__ outp)
{
    __shared__ __align__(16) float sP[2][2*648];     // 2 ci patches [18 rows][36]
    __shared__ __align__(16) float sB[2][2*1024];    // 2 ci, this co-half only

    int tid  = threadIdx.x;
    int lane = tid & 31;
    int wm   = tid >> 5;             // 4 warps = pos groups (also wl)
    int bid  = blockIdx.x;
    int wn = bid & 1;                // co half
    int j  = (bid >> 1) & 7;
    int h  = (bid >> 4) & 31;
    int b  = bid >> 9;

    const float* src  = FIRST ? in : (const float*)g_vol2;
    const float* srcb = src + (size_t)b * 64 * LL;

    int r = lane & 3;                // threadID_in_group
    int q = lane >> 2;               // groupID

    // ---- per-thread staging descriptors (patch: 612 logical elems/ci) ----
    int   pOff[5]; int pSz[5]; uint32_t pDst[2][5];
    int nP = (tid < 100) ? 5 : 4;
#pragma unroll
    for (int e = 0; e < 5; e++) {
        int idx = tid + e*128;
        if (idx < 612) {
            int row = idx / 34, col = idx - row*34;
            int kh = row / 6, iww = row - kh*6;
            int ih = h + kh - 1;
            int iw = j*4 + iww - 1;
            int id = col - 1;
            bool ok = (unsigned)ih < 32u && (unsigned)iw < 32u && (unsigned)id < 32u;
            pOff[e] = ok ? (ih*1024 + iw*32 + id) : 0;
            pSz[e]  = ok ? 4 : 0;
            pDst[0][e] = s2u32(&sP[0][row*36 + col]);   // 36-stride (matches koff)
            pDst[1][e] = s2u32(&sP[1][row*36 + col]);
        }
    }
    uint32_t bDst[2] = { s2u32(&sB[0][0]) + (uint32_t)tid*16,
                         s2u32(&sB[1][0]) + (uint32_t)tid*16 };

    // Per-thread patch offsets for the 8 k columns this lane touches
    int koff[4][2];
#pragma unroll
    for (int ks = 0; ks < 4; ks++)
#pragma unroll
        for (int hf = 0; hf < 2; hf++) {
            int k = ks*8 + r + hf*4;
            if (k < 27) {
                int kh = k/9, kw = (k%9)/3, kd = k%3;
                koff[ks][hf] = (kh*6 + kw + wm)*36 + kd;
            } else koff[ks][hf] = -1;
        }

    float acc[2][4][4];
#pragma unroll
    for (int mt = 0; mt < 2; mt++)
#pragma unroll
        for (int nt = 0; nt < 4; nt++)
#pragma unroll
            for (int e = 0; e < 4; e++) acc[mt][nt][e] = 0.f;

    // ---- stage loader (2 ci; B = this co-half only) ----
    auto stage_load = [&](int st, int ci0) {
        const float* sc0 = srcb + (size_t)ci0 * LL;
        for (int e = 0; e < nP; e++) {
            cpa4(pDst[st][e],        sc0 + pOff[e],      pSz[e]);
            cpa4(pDst[st][e] + 2592, sc0 + LL + pOff[e], pSz[e]);   // ci0+1, +648 floats
        }
        const float4* bs = (const float4*)(g_wB + ci0*2048 + wn*1024);
        cpa16(bDst[st],                       bs + tid);           // ci0 lo
        cpa16(bDst[st] + (uint32_t)(128*16),  bs + tid + 128);     // ci0 hi
        cpa16(bDst[st] + (uint32_t)(256*16),  bs + tid + 512);     // ci0+1 lo
        cpa16(bDst[st] + (uint32_t)(384*16),  bs + tid + 640);     // ci0+1 hi
    };

    stage_load(0, 0);
    CP_COMMIT();

    for (int s = 0; s < 32; s++) {
        int cur = s & 1;
        if (s < 31) {
            stage_load(cur ^ 1, (s+1)*2);
            CP_COMMIT();
            CP_WAIT1();
        } else {
            CP_WAIT0();
        }
        __syncthreads();

        // pre-convert this stage's A patches to tf32 in place
        {
            float* p = sP[cur];
            for (int idx = tid; idx < 2*648; idx += 128) {
                float v = p[idx];
                uint32_t hb; asm("cvt.rna.tf32.f32 %0, %1;" : "=r"(hb) : "f"(v));
                p[idx] = __uint_as_float(hb);
            }
        }
        __syncthreads();

#pragma unroll
        for (int cii = 0; cii < 2; cii++) {
            const float* sPc = sP[cur] + cii*648;
            const float* sBc = sB[cur] + cii*1024;
#pragma unroll
            for (int ks = 0; ks < 4; ks++) {
                uint32_t ah[2][4];
#pragma unroll
                for (int mt = 0; mt < 2; mt++) {
                    int dA = mt*16 + q;
#pragma unroll
                    for (int e = 0; e < 4; e++) {
                        int hf = e >> 1;
                        int dd = dA + ((e & 1) ? 8 : 0);
                        int off = koff[ks][hf];
                        ah[mt][e] = (off >= 0) ? __float_as_uint(sPc[off + dd]) : 0u;
                    }
                }
                const float* bb = sBc + ks*256 + lane*4;
                float4 v0 = *(const float4*)&bb[0];
                float4 v1 = *(const float4*)&bb[128];
                uint32_t bhf[4][2];
                bhf[0][0] = __float_as_uint(v0.x); bhf[0][1] = __float_as_uint(v0.y);
                bhf[1][0] = __float_as_uint(v0.z); bhf[1][1] = __float_as_uint(v0.w);
                bhf[2][0] = __float_as_uint(v1.x); bhf[2][1] = __float_as_uint(v1.y);
                bhf[3][0] = __float_as_uint(v1.z); bhf[3][1] = __float_as_uint(v1.w);
#pragma unroll
                for (int mt = 0; mt < 2; mt++)
#pragma unroll
                    for (int nt = 0; nt < 4; nt++)
                        mma8(acc[mt][nt], ah[mt], bhf[nt]);
            }
        }
        __syncthreads();
    }

    // epilogue
    int w = j*4 + wm;
#pragma unroll
    for (int mt = 0; mt < 2; mt++)
#pragma unroll
        for (int nt = 0; nt < 4; nt++)
#pragma unroll
            for (int e = 0; e < 4; e++) {
                int dd = mt*16 + q + ((e >= 2) ? 8 : 0);
                int co = wn*32 + nt*8 + 2*r + (e & 1);
                size_t gidx = (size_t)(b*64 + co)*LL + h*1024 + w*32 + dd;
                float v = acc[mt][nt][e] + cb[co];
                if (FIRST) {
                    g_tmp1[gidx] = v;
                } else {
                    float mean = g_mr[(b*64 + co)*2];
                    float rstd = g_mr[(b*64 + co)*2 + 1];
                    float s = (g_tmp1[gidx] - mean) * rstd;
                    outp[gidx] = v + (s > 0.f ? s : 0.f);
                }
            }
}

// ---------------- instance-norm stats (deterministic) ------------------------
__global__ __launch_bounds__(256) void stats_k()
{
    int bc = blockIdx.x;  // 0..127
    const float* p = g_tmp1 + (size_t)bc * LL;
    float s = 0.f, sq = 0.f;
    for (int i = threadIdx.x; i < LL; i += 256) { float v = p[i]; s += v; sq += v*v; }
    __shared__ float sh0[256], sh1[256];
    sh0[threadIdx.x] = s; sh1[threadIdx.x] = sq;
    __syncthreads();
    for (int o = 128; o > 0; o >>= 1) {
        if (threadIdx.x < o) { sh0[threadIdx.x] += sh0[threadIdx.x+o]; sh1[threadIdx.x] += sh1[threadIdx.x+o]; }
        __syncthreads();
    }
    if (threadIdx.x == 0) {
        float mean = sh0[0] * (1.f/LL);
        float var  = sh1[0] * (1.f/LL) - mean*mean;
        g_mr[bc*2]   = mean;
        g_mr[bc*2+1] = rsqrtf(var + 1e-5f);
    }
}

// ---------------- in_proj: xz[b][l][j] = sum_c in[b][c][l] * W[j][c] ----------
// Weights staged TRANSPOSED (s_wT[c][j], 132-stride = 16B-aligned rows) so the
// inner loop is 3× LDS.128 + 32 FMA per c.
__global__ __launch_bounds__(256) void inproj_k(const float* __restrict__ in,
                                                const float* __restrict__ ipw)
{
    __shared__ float s_wT[64][132];
    __shared__ float s_x[32][64];
    int b = blockIdx.y;
    int l0 = blockIdx.x * 64;
    int tid = threadIdx.x;
    for (int idx = tid; idx < 128*64; idx += 256) {
        int jrow = idx >> 6, c = idx & 63;
        s_wT[c][jrow] = ipw[idx];
    }

    int lq = tid & 15;
    int jq = tid >> 4;
    float acc[4][8];
#pragma unroll
    for (int i = 0; i < 4; i++)
#pragma unroll
        for (int j = 0; j < 8; j++) acc[i][j] = 0.f;

    for (int ch = 0; ch < 2; ch++) {
        __syncthreads();
        for (int idx = tid; idx < 32*64; idx += 256) {
            int c = idx >> 6, ll = idx & 63;
            s_x[c][ll] = in[(size_t)(b*64 + ch*32 + c)*LL + l0 + ll];
        }
        __syncthreads();
        for (int c = 0; c < 32; c++) {
            float4 xv4 = *(const float4*)&s_x[c][lq*4];
            float xv[4] = {xv4.x, xv4.y, xv4.z, xv4.w};
            const float* wr = &s_wT[ch*32 + c][jq*8];
            float4 w0 = *(const float4*)wr;
            float4 w1 = *(const float4*)(wr + 4);
            float wv[8] = {w0.x, w0.y, w0.z, w0.w, w1.x, w1.y, w1.z, w1.w};
#pragma unroll
            for (int i = 0; i < 4; i++)
#pragma unroll
                for (int j = 0; j < 8; j++) acc[i][j] += xv[i] * wv[j];
        }
    }
#pragma unroll
    for (int i = 0; i < 4; i++) {
        int l = l0 + lq*4 + i;
        float4 v0 = make_float4(acc[i][0], acc[i][1], acc[i][2], acc[i][3]);
        float4 v1 = make_float4(acc[i][4], acc[i][5], acc[i][6], acc[i][7]);
        float4* dst = (float4*)&g_xz[((size_t)b*LL + l)*128 + jq*8];
        dst[0] = v0; dst[1] = v1;
    }
}

// ---------------- prep (both dirs): conv1d+silu, x_proj, dt_proj -------------
__global__ __launch_bounds__(256) void prep_k(
    const float* __restrict__ w1d_g, const float* __restrict__ b1d_g,
    const float* __restrict__ xpw_g, const float* __restrict__ dtw_g,
    const float* __restrict__ dtb_g)
{
    __shared__ float xs[67][64];
    __shared__ float xc_s[64][65];
    __shared__ float dbl_s[64][20];
    __shared__ float xpw[20][65];
    __shared__ float w1d[64][4];
    __shared__ float dtw[64][5];
    __shared__ float b1d[64], dtb[64];

    int b = blockIdx.y;
    int dir = blockIdx.z;
    int s0 = blockIdx.x * 64;
    int tid = threadIdx.x;
    size_t xcb = (size_t)dir*XCSTR;
    size_t bmb = (size_t)dir*BMSTR;

    for (int idx = tid; idx < 20*64; idx += 256) xpw[idx/64][idx%64] = xpw_g[idx];
    if (tid < 64) {
#pragma unroll
        for (int k = 0; k < 4; k++) { w1d[tid][k] = w1d_g[tid*4 + k]; dtw[tid][k] = dtw_g[tid*4 + k]; }
        b1d[tid] = b1d_g[tid];
        dtb[tid] = dtb_g[tid];
    }
    for (int idx = tid; idx < 67*64; idx += 256) {
        int sr = idx / 64, d = idx % 64;
        int s = s0 + sr - 3;
        float v = 0.f;
        if (s >= 0) {
            int l = (dir == 0) ? s : (LL - 1 - s);
            v = g_xz[((size_t)b*LL + l)*128 + d];
        }
        xs[sr][d] = v;
    }
    __syncthreads();

    // causal depthwise conv1d (k=4) + silu
    for (int idx = tid; idx < 64*64; idx += 256) {
        int sl = idx >> 6, d = idx & 63;
        float v = b1d[d];
#pragma unroll
        for (int k = 0; k < 4; k++) v += w1d[d][k] * xs[sl + k][d];
        v = v / (1.f + __expf(-v));
        xc_s[sl][d] = v;
        g_xc[xcb + ((size_t)b*LL + s0 + sl)*64 + d] = v;
    }
    __syncthreads();

    // dbl = xc @ x_proj_w.T — register-tiled: 64 sl × 4 jg, 5 j per thread.
    {
        int sl = tid & 63;
        int jg = tid >> 6;
        float accp[5] = {0.f, 0.f, 0.f, 0.f, 0.f};
        for (int d = 0; d < 64; d++) {
            float xv = xc_s[sl][d];
#pragma unroll
            for (int jj = 0; jj < 5; jj++)
                accp[jj] += xv * xpw[jg*5 + jj][d];
        }
#pragma unroll
        for (int jj = 0; jj < 5; jj++) {
            int jdx = jg*5 + jj;
            dbl_s[sl][jdx] = accp[jj];
            int s = s0 + sl;
            if (jdx >= 4 && jdx < 12)  g_Bm[bmb + ((size_t)b*LL + s)*8 + (jdx-4)]  = accp[jj];
            else if (jdx >= 12)        g_Cm[bmb + ((size_t)b*LL + s)*8 + (jdx-12)] = accp[jj];
        }
    }
    __syncthreads();

    // dt = softplus(dt_r @ dt_proj_w.T + b)
    for (int idx = tid; idx < 64*64; idx += 256) {
        int sl = idx >> 6, dd = idx & 63;
        float t = dtb[dd];
#pragma unroll
        for (int r = 0; r < 4; r++) t += dbl_s[sl][r] * dtw[dd][r];
        float sp = (t > 20.f) ? t : log1pf(__expf(t));
        g_dt[xcb + ((size_t)b*LL + s0 + sl)*64 + dd] = sp;
    }
}

// ---------------- scan pass A (both dirs): per-chunk (P, Q) reduction --------
__global__ __launch_bounds__(512) void scanA_k(const float* __restrict__ alog_f,
                                               const float* __restrict__ alog_b)
{
    __shared__ float s_dt[32][64];
    __shared__ float s_xc[32][64];
    __shared__ float s_B[32][8];
    int b = blockIdx.y;
    int dir = blockIdx.z;
    int chunk = blockIdx.x;
    int tid = threadIdx.x;
    int d = tid >> 3, n = tid & 7;
    const float* alog = dir ? alog_b : alog_f;
    float a = -__expf(alog[d*8 + n]);
    size_t xcb = (size_t)dir*XCSTR;
    size_t bmb = (size_t)dir*BMSTR;
    float P = 1.f, Q = 0.f;
    int sbase = chunk * CS;
    for (int sub = 0; sub < CS/32; sub++) {
        __syncthreads();
        int st = sbase + sub*32;
        for (int idx = tid; idx < 32*64; idx += 512) {
            int sl = idx >> 6, dd = idx & 63;
            size_t g = xcb + ((size_t)b*LL + st + sl)*64 + dd;
            s_dt[sl][dd] = g_dt[g];
            s_xc[sl][dd] = g_xc[g];
        }
        if (tid < 256) {
            int sl = tid >> 3, nn = tid & 7;
            s_B[sl][nn] = g_Bm[bmb + ((size_t)b*LL + st + sl)*8 + nn];
        }
        __syncthreads();
#pragma unroll 8
        for (int sl = 0; sl < 32; sl++) {
            float dtv = s_dt[sl][d];
            float ex = __expf(dtv * a);
            float u = dtv * s_xc[sl][d] * s_B[sl][n];
            P *= ex;
            Q = ex*Q + u;
        }
    }
    size_t o = (size_t)dir*PQSTR + ((size_t)(b*NCK + chunk))*512 + tid;
    g_P[o] = P; g_Q[o] = Q;
}

// ---------------- scan pass C (both dirs): inline carry + replay + epilogue --
__global__ __launch_bounds__(512) void scanC_k(const float* __restrict__ alog_f,
                                               const float* __restrict__ alog_b,
                                               const float* __restrict__ Dsk)
{
    __shared__ float s_dt[32][64];
    __shared__ float s_xc[32][64];
    __shared__ float s_B[32][8];
    __shared__ float s_C[32][8];
    __shared__ float s_y[32][64];
    int b = blockIdx.y;
    int dir = blockIdx.z;
    int chunk = blockIdx.x;
    int tid = threadIdx.x;
    int d = tid >> 3, n = tid & 7;
    const float* alog = dir ? alog_b : alog_f;
    float a = -__expf(alog[d*8 + n]);
    float Dv = Dsk[d];
    size_t xcb = (size_t)dir*XCSTR;
    size_t bmb = (size_t)dir*BMSTR;

    // inline carry: batched unroll-by-8 prefix over preceding chunks' (P, Q)
    float h = 0.f;
    {
        size_t pqb = (size_t)dir*PQSTR + (size_t)b*NCK*512 + tid;
        int jj = 0;
        for (; jj + 8 <= chunk; jj += 8) {
            float p[8], qq[8];
#pragma unroll
            for (int t = 0; t < 8; t++) {
                size_t o = pqb + (size_t)(jj + t)*512;
                p[t]  = g_P[o];
                qq[t] = g_Q[o];
            }
#pragma unroll
            for (int t = 0; t < 8; t++) h = p[t]*h + qq[t];
        }
        for (; jj < chunk; jj++) {
            size_t o = pqb + (size_t)jj*512;
            h = g_P[o]*h + g_Q[o];
        }
    }
    int sbase = chunk * CS;

    for (int sub = 0; sub < CS/32; sub++) {
        int st = sbase + sub*32;
        __syncthreads();
        for (int idx = tid; idx < 32*64; idx += 512) {
            int sl = idx >> 6, dd = idx & 63;
            size_t g = xcb + ((size_t)b*LL + st + sl)*64 + dd;
            s_dt[sl][dd] = g_dt[g];
            s_xc[sl][dd] = g_xc[g];
        }
        if (tid < 256) {
            int sl = tid >> 3, nn = tid & 7;
            size_t g = bmb + ((size_t)b*LL + st + sl)*8 + nn;
            s_B[sl][nn] = g_Bm[g];
            s_C[sl][nn] = g_Cm[g];
        }
        __syncthreads();
        for (int sl = 0; sl < 32; sl++) {
            float dtv = s_dt[sl][d];
            float xcv = s_xc[sl][d];
            float ex = __expf(dtv * a);
            h = ex*h + dtv * xcv * s_B[sl][n];
            float part = h * s_C[sl][n];
            part += __shfl_xor_sync(0xffffffffu, part, 1);
            part += __shfl_xor_sync(0xffffffffu, part, 2);
            part += __shfl_xor_sync(0xffffffffu, part, 4);
            if (n == 0) s_y[sl][d] = part + xcv * Dv;
        }
        __syncthreads();
        // multiply silu(z) and store at ORIGINAL l (per-dir buffer; outln sums)
        for (int idx = tid; idx < 32*64; idx += 512) {
            int sl = idx >> 6, dd = idx & 63;
            int s = st + sl;
            int l = (dir == 0) ? s : (LL - 1 - s);
            float z = g_xz[((size_t)b*LL + l)*128 + 64 + dd];
            float sil = z / (1.f + __expf(-z));
            g_y[xcb + ((size_t)b*LL + l)*64 + dd] = s_y[sl][dd] * sil;
        }
    }
}

// ---------------- out_proj (×0.5) + LayerNorm, write volume layout -----------
__global__ __launch_bounds__(256) void outln_k(const float* __restrict__ opw,
                                               const float* __restrict__ lng,
                                               const float* __restrict__ lnb)
{
    __shared__ float s_y[64][65];   // reused as r_s after GEMM
    __shared__ float s_w[64][65];
    __shared__ float mu_s[64], rs_s[64];
    int b = blockIdx.y;
    int l0 = blockIdx.x * 64;
    int tid = threadIdx.x;
    for (int idx = tid; idx < 64*64; idx += 256) s_w[idx >> 6][idx & 63] = opw[idx];
    for (int idx = tid; idx < 64*64; idx += 256) {
        int ll = idx >> 6, dd = idx & 63;
        size_t o = ((size_t)b*LL + l0 + ll)*64 + dd;
        s_y[ll][dd] = g_y[o] + g_y[XCSTR + o];   // y_f + y_b
    }
    __syncthreads();

    int lq = tid & 15, cq = tid >> 4;
    float acc[4][4];
#pragma unroll
    for (int i = 0; i < 4; i++)
#pragma unroll
        for (int j = 0; j < 4; j++) acc[i][j] = 0.f;
    for (int dd = 0; dd < 64; dd++) {
        float yv[4], wv[4];
#pragma unroll
        for (int i = 0; i < 4; i++) yv[i] = s_y[lq*4 + i][dd];
#pragma unroll
        for (int j = 0; j < 4; j++) wv[j] = s_w[cq*4 + j][dd];
#pragma unroll
        for (int i = 0; i < 4; i++)
#pragma unroll
            for (int j = 0; j < 4; j++) acc[i][j] += yv[i] * wv[j];
    }
    __syncthreads();
#pragma unroll
    for (int i = 0; i < 4; i++)
#pragma unroll
        for (int j = 0; j < 4; j++)
            s_y[lq*4 + i][cq*4 + j] = 0.5f * acc[i][j];
    __syncthreads();
    if (tid < 64) {
        float s = 0.f, sq = 0.f;
        for (int c = 0; c < 64; c++) { float v = s_y[tid][c]; s += v; sq += v*v; }
        float mu = s * (1.f/64.f);
        float var = sq * (1.f/64.f) - mu*mu;
        mu_s[tid] = mu; rs_s[tid] = rsqrtf(var + 1e-5f);
    }
    __syncthreads();
    for (int idx = tid; idx < 64*64; idx += 256) {
        int c = idx >> 6, ll = idx & 63;
        float v = (s_y[ll][c] - mu_s[ll]) * rs_s[ll] * lng[c] + lnb[c];
        g_vol2[(size_t)(b*64 + c)*LL + l0 + ll] = v;
    }
}

// ------------------------------- launcher ------------------------------------
// conv1+stats run on a capture-forked side stream (fork/join via events).
// Stream/event objects created fresh per call; not destroyed mid-capture.
extern "C" void kernel_launch(void* const* d_in, const int* in_sizes, int n_in,
                              void* d_out, int out_size)
{
    (void)in_sizes; (void)n_in; (void)out_size;
    const float* input     = (const float*)d_in[0];
    const float* conv_w    = (const float*)d_in[1];
    const float* conv_b    = (const float*)d_in[2];
    const float* in_proj_w = (const float*)d_in[3];
    const float* conv1d_w  = (const float*)d_in[4];
    const float* conv1d_b  = (const float*)d_in[5];
    const float* x_proj_w  = (const float*)d_in[6];
    const float* dt_proj_w = (const float*)d_in[7];
    const float* dt_proj_b = (const float*)d_in[8];
    const float* A_log     = (const float*)d_in[9];
    const float* A_b_log   = (const float*)d_in[10];
    const float* D_skip    = (const float*)d_in[11];
    const float* out_proj_w= (const float*)d_in[12];
    const float* ln_g      = (const float*)d_in[13];
    const float* ln_b      = (const float*)d_in[14];
    float* out = (float*)d_out;

    cudaStream_t s2;
    cudaStreamCreateWithFlags(&s2, cudaStreamNonBlocking);
    cudaEvent_t evFork, evJoin;
    cudaEventCreateWithFlags(&evFork, cudaEventDisableTiming);
    cudaEventCreateWithFlags(&evJoin, cudaEventDisableTiming);

    // one-time weight tf32 prep into fragment-ready layout (needed by conv1)
    wsplit_k<<<512, 256>>>(conv_w);

    // fork: conv1 + stats on side stream
    cudaEventRecord(evFork, 0);
    cudaStreamWaitEvent(s2, evFork, 0);
    conv3d_m<true><<<1024, 128, 0, s2>>>(input, conv_b, nullptr);
    stats_k<<<128, 256, 0, s2>>>();

    // main stream: the Mamba branch
    inproj_k<<<dim3(512, 2), 256>>>(input, in_proj_w);
    prep_k<<<dim3(512, 2, 2), 256>>>(conv1d_w, conv1d_b, x_proj_w, dt_proj_w, dt_proj_b);
    scanA_k<<<dim3(NCK, 2, 2), 512>>>(A_log, A_b_log);
    scanC_k<<<dim3(NCK, 2, 2), 512>>>(A_log, A_b_log, D_skip);
    outln_k<<<dim3(512, 2), 256>>>(out_proj_w, ln_g, ln_b);

    // join, then conv #2 + residual skip (reads g_vol2, g_tmp1, g_mr)
    cudaEventRecord(evJoin, s2);
    cudaStreamWaitEvent(0, evJoin, 0);
    conv3d_m<false><<<1024, 128>>>(nullptr, conv_b, out);
}